// round 9
// baseline (speedup 1.0000x reference)
#include <cuda_runtime.h>
#include <cuda_fp16.h>
#include <cstdint>

#define B_  4
#define T_  2048
#define D_  1024
#define H_  16
#define DK_ 64
#define M_  (B_*T_)
#define BH_ (B_*H_)

// Scratch (allocation-free rule: module-scope device globals)
__device__ float g_x_t32[(size_t)M_ * D_];       // x pre-rounded to tf32
__device__ float g_qkv[(size_t)M_ * 3 * D_];     // [B,T,3D] (only V region written)
__device__ float g_att[(size_t)M_ * D_];         // [B,T,D] (tf32-rounded values)
__device__ float g_wqkv_t[(size_t)3 * D_ * D_];  // W_qkv^T [3D, D] tf32-rounded
__device__ float g_wout_t[(size_t)D_ * D_];      // W_out^T [D, D] tf32-rounded
// half hi/lo splits for attention
__device__ __half g_q_hi[(size_t)BH_ * T_ * DK_];
__device__ __half g_q_lo[(size_t)BH_ * T_ * DK_];
__device__ __half g_k_hi[(size_t)BH_ * T_ * DK_];
__device__ __half g_k_lo[(size_t)BH_ * T_ * DK_];
__device__ __half g_vt_hi[(size_t)BH_ * DK_ * T_];  // [bh][d][t]
__device__ __half g_vt_lo[(size_t)BH_ * DK_ * T_];

// ---------------------------------------------------------------------------
// PTX helpers
// ---------------------------------------------------------------------------
__device__ __forceinline__ uint32_t smem_u32(const void* p) {
    uint32_t a;
    asm("{ .reg .u64 t; cvta.to.shared.u64 t, %1; cvt.u32.u64 %0, t; }"
        : "=r"(a) : "l"(p));
    return a;
}
__device__ __forceinline__ void cp_async16(uint32_t dst, const void* src) {
    asm volatile("cp.async.ca.shared.global [%0], [%1], 16;"
                 :: "r"(dst), "l"(src) : "memory");
}
__device__ __forceinline__ void cp_commit() {
    asm volatile("cp.async.commit_group;" ::: "memory");
}
__device__ __forceinline__ void cp_wait0() {
    asm volatile("cp.async.wait_group 0;" ::: "memory");
}
__device__ __forceinline__ void cp_wait1() {
    asm volatile("cp.async.wait_group 1;" ::: "memory");
}
__device__ __forceinline__ void cp_wait3() {
    asm volatile("cp.async.wait_group 3;" ::: "memory");
}
__device__ __forceinline__ float ex2f(float x) {
    float y;
    asm("ex2.approx.f32 %0, %1;" : "=f"(y) : "f"(x));
    return y;
}
__device__ __forceinline__ float rna_tf32(float x) {
    uint32_t r;
    asm("cvt.rna.tf32.f32 %0, %1;" : "=r"(r) : "f"(x));
    return __uint_as_float(r);
}
__device__ __forceinline__ void cvt4_rna(uint32_t (&o)[4], float4 v) {
    asm("cvt.rna.tf32.f32 %0, %1;" : "=r"(o[0]) : "f"(v.x));
    asm("cvt.rna.tf32.f32 %0, %1;" : "=r"(o[1]) : "f"(v.y));
    asm("cvt.rna.tf32.f32 %0, %1;" : "=r"(o[2]) : "f"(v.z));
    asm("cvt.rna.tf32.f32 %0, %1;" : "=r"(o[3]) : "f"(v.w));
}
__device__ __forceinline__ void mma16816(float (&c)[4], uint32_t a0, uint32_t a1,
                                         uint32_t a2, uint32_t a3,
                                         uint32_t b0, uint32_t b1) {
    asm volatile(
        "mma.sync.aligned.m16n8k16.row.col.f32.f16.f16.f32 "
        "{%0,%1,%2,%3}, {%4,%5,%6,%7}, {%8,%9}, {%0,%1,%2,%3};"
        : "+f"(c[0]), "+f"(c[1]), "+f"(c[2]), "+f"(c[3])
        : "r"(a0), "r"(a1), "r"(a2), "r"(a3), "r"(b0), "r"(b1));
}
__device__ __forceinline__ void mma_tf32(float (&c)[4], const uint32_t (&a)[4],
                                         const uint32_t (&b)[2]) {
    asm volatile(
        "mma.sync.aligned.m16n8k8.row.col.f32.tf32.tf32.f32 "
        "{%0,%1,%2,%3}, {%4,%5,%6,%7}, {%8,%9}, {%0,%1,%2,%3};"
        : "+f"(c[0]), "+f"(c[1]), "+f"(c[2]), "+f"(c[3])
        : "r"(a[0]), "r"(a[1]), "r"(a[2]), "r"(a[3]), "r"(b[0]), "r"(b[1]));
}

// split one float pair into half2 hi/lo and store
__device__ __forceinline__ void split_store2(float x, float y,
                                             __half* hi, __half* lo, size_t o) {
    __half2 h = __floats2half2_rn(x, y);
    float2 f = __half22float2(h);
    __half2 l = __floats2half2_rn(x - f.x, y - f.y);
    *(__half2*)(hi + o) = h;
    *(__half2*)(lo + o) = l;
}

// ---------------------------------------------------------------------------
// Elementwise tf32 rounding
// ---------------------------------------------------------------------------
__global__ __launch_bounds__(256)
void cvt_tf32_kernel(const float4* __restrict__ in, float4* __restrict__ out)
{
    int i = blockIdx.x * 256 + threadIdx.x;
    uint32_t c4[4];
    cvt4_rna(c4, in[i]);
    out[i] = *(float4*)c4;
}

// ---------------------------------------------------------------------------
// Transpose + tf32 round: out[c][r] = rna_tf32(in[r][c])   (in: [R,C])
// ---------------------------------------------------------------------------
__global__ __launch_bounds__(256)
void transpose_kernel(const float* __restrict__ in, float* __restrict__ out,
                      int R, int C)
{
    __shared__ float t[32][33];
    int bx = blockIdx.x * 32;
    int by = blockIdx.y * 32;
    int tx = threadIdx.x & 31, ty = threadIdx.x >> 5;
#pragma unroll
    for (int j = 0; j < 32; j += 8)
        t[ty + j][tx] = in[(size_t)(by + ty + j) * C + bx + tx];
    __syncthreads();
#pragma unroll
    for (int j = 0; j < 32; j += 8)
        out[(size_t)(bx + ty + j) * R + by + tx] = rna_tf32(t[tx][ty + j]);
}

// ---------------------------------------------------------------------------
// tf32 GEMM v5: C[M,N] = A[M,K] @ Bt[N,K]^T + bias[N]
// Round-6 schedule (wait -> sync -> issue -> compute), NSTAGE=5, wait3
// (prefetch distance 4 chunks). Optional fused epilogue: Q/K regions of the
// QKV projection are split to half hi/lo directly (bit-identical to the old
// convert_qk pass, which read the same fp32 acc+bias values).
// ---------------------------------------------------------------------------
#define APAD   20
#define ATILE  (128 * APAD)             // words per operand per stage
#define STW    (2 * ATILE)              // words per stage
#define NSTAGE 5
#define GEMM_SMEM (NSTAGE * STW * 4)    // 102400 B

__global__ __launch_bounds__(128, 2)
void gemm_tf32_kernel(const float* __restrict__ A,
                      const float* __restrict__ Bt,
                      const float* __restrict__ bias,
                      float* __restrict__ C,
                      int M, int N, int K,
                      int fuse_qk,
                      __half* __restrict__ qh, __half* __restrict__ ql,
                      __half* __restrict__ kh, __half* __restrict__ kl)
{
    extern __shared__ uint32_t smw[];
    const uint32_t sbase = smem_u32(smw);
    const int tid  = threadIdx.x;
    const int wid  = tid >> 5;
    const int lane = tid & 31;
    const int grp  = lane >> 2;
    const int tg   = lane & 3;
    const int warp_m = (wid & 1) * 64;
    const int warp_n = (wid >> 1) * 64;
    const int m0 = blockIdx.y * 128;
    const int n0 = blockIdx.x * 128;
    const int nk = K >> 4;

    const float* Abase = A + (size_t)m0 * K;
    const float* Bbase = Bt + (size_t)n0 * K;

    auto issue = [&](int i) {
        if (i < nk) {
            const int k0 = i << 4;
            const uint32_t st = sbase + ((i % NSTAGE) * STW) * 4;
#pragma unroll
            for (int j = 0; j < 4; j++) {
                const int idx = tid + j * 128;          // 0..511
                const int r = idx >> 2, kc = (idx & 3) << 2;
                cp_async16(st + (r * APAD + kc) * 4,
                           Abase + (size_t)r * K + k0 + kc);
                cp_async16(st + (ATILE + r * APAD + kc) * 4,
                           Bbase + (size_t)r * K + k0 + kc);
            }
        }
        cp_commit();
    };

    float acc[4][8][4];
#pragma unroll
    for (int i = 0; i < 4; i++)
#pragma unroll
        for (int j = 0; j < 8; j++)
#pragma unroll
            for (int r = 0; r < 4; r++) acc[i][j][r] = 0.f;

    issue(0); issue(1); issue(2); issue(3);

    uint32_t a[2][4][4], b[2][8][2];

    for (int i = 0; i < nk; i++) {
        cp_wait3();                      // chunk i resident (own copies)
        __syncthreads();                 // publish copies; chunk i-1 compute done
        issue(i + 4);                    // overwrites slot of i-1 (safe)

        const uint32_t* Au = smw + (i % NSTAGE) * STW;
        const uint32_t* Bu = Au + ATILE;

        // load ks=0 fragments
        {
            const int k0 = tg;
#pragma unroll
            for (int ii = 0; ii < 4; ii++) {
                const uint32_t* p0 = Au + (warp_m + 16 * ii + grp) * APAD;
                a[0][ii][0] = p0[k0];
                a[0][ii][2] = p0[k0 + 4];
                const uint32_t* p1 = p0 + 8 * APAD;
                a[0][ii][1] = p1[k0];
                a[0][ii][3] = p1[k0 + 4];
            }
#pragma unroll
            for (int jj = 0; jj < 8; jj++) {
                const uint32_t* pn = Bu + (warp_n + 8 * jj + grp) * APAD;
                b[0][jj][0] = pn[k0];
                b[0][jj][1] = pn[k0 + 4];
            }
        }
#pragma unroll
        for (int ks = 0; ks < 2; ks++) {
            if (ks == 0) {      // prefetch ks=1 fragments under ks=0 mma
                const int k0 = 8 + tg;
#pragma unroll
                for (int ii = 0; ii < 4; ii++) {
                    const uint32_t* p0 = Au + (warp_m + 16 * ii + grp) * APAD;
                    a[1][ii][0] = p0[k0];
                    a[1][ii][2] = p0[k0 + 4];
                    const uint32_t* p1 = p0 + 8 * APAD;
                    a[1][ii][1] = p1[k0];
                    a[1][ii][3] = p1[k0 + 4];
                }
#pragma unroll
                for (int jj = 0; jj < 8; jj++) {
                    const uint32_t* pn = Bu + (warp_n + 8 * jj + grp) * APAD;
                    b[1][jj][0] = pn[k0];
                    b[1][jj][1] = pn[k0 + 4];
                }
            }
#pragma unroll
            for (int ii = 0; ii < 4; ii++)
#pragma unroll
                for (int jj = 0; jj < 8; jj++)
                    mma_tf32(acc[ii][jj], a[ks][ii], b[ks][jj]);
        }
    }

    // ---- epilogue
    const int region = fuse_qk ? (n0 >> 10) : 3;   // 0=Q, 1=K, 2=V/plain, 3=plain
#pragma unroll
    for (int ii = 0; ii < 4; ii++) {
        const int m = m0 + warp_m + 16 * ii + grp;
#pragma unroll
        for (int jj = 0; jj < 8; jj++) {
            const int n = n0 + warp_n + 8 * jj + 2 * tg;
            const float bv0 = __ldg(&bias[n]);
            const float bv1 = __ldg(&bias[n + 1]);
            const float v00 = acc[ii][jj][0] + bv0, v01 = acc[ii][jj][1] + bv1;
            const float v10 = acc[ii][jj][2] + bv0, v11 = acc[ii][jj][3] + bv1;
            if (region <= 1) {
                // Q or K: split-store half hi/lo at [bh][t][d]
                const int nr = n - (region << 10);     // 0..1023 within region
                const int hh = nr >> 6, d = nr & 63;
                const int b0i = m >> 11, t0i = m & 2047;
                const size_t o0 = ((size_t)(b0i * 16 + hh) * T_ + t0i) * 64 + d;
                const int b1i = (m + 8) >> 11, t1i = (m + 8) & 2047;
                const size_t o1 = ((size_t)(b1i * 16 + hh) * T_ + t1i) * 64 + d;
                if (region == 0) {
                    split_store2(v00, v01, qh, ql, o0);
                    split_store2(v10, v11, qh, ql, o1);
                } else {
                    split_store2(v00, v01, kh, kl, o0);
                    split_store2(v10, v11, kh, kl, o1);
                }
            } else {
                float2 v0 = {v00, v01};
                float2 v1 = {v10, v11};
                *(float2*)(C + (size_t)m * N + n)       = v0;
                *(float2*)(C + (size_t)(m + 8) * N + n) = v1;
            }
        }
    }
}

// ---------------------------------------------------------------------------
// V transpose + split: g_qkv V part -> [bh][d][t] hi/lo halfs
// ---------------------------------------------------------------------------
__global__ __launch_bounds__(256)
void convert_vt_kernel(const float* __restrict__ qkv,
                       __half* __restrict__ vh, __half* __restrict__ vl)
{
    __shared__ float tile[32][33];
    int t0 = blockIdx.x * 32;
    int d0 = blockIdx.y * 32;
    int bh = blockIdx.z;
    int b = bh >> 4, h = bh & 15;
    int tx = threadIdx.x & 31, ty = threadIdx.x >> 5;
#pragma unroll
    for (int j = 0; j < 32; j += 8)
        tile[ty + j][tx] = qkv[((size_t)(b * T_ + t0 + ty + j)) * 3 * D_
                               + 2 * D_ + h * 64 + d0 + tx];
    __syncthreads();
#pragma unroll
    for (int j = 0; j < 32; j += 8) {
        int d = d0 + ty + j;
        float v = tile[tx][ty + j];
        __half hv = __float2half_rn(v);
        __half lv = __float2half_rn(v - __half2float(hv));
        size_t o = ((size_t)bh * DK_ + d) * T_ + t0 + tx;
        vh[o] = hv;
        vl[o] = lv;
    }
}

// ---------------------------------------------------------------------------
// Flash attention on fp16 tensor cores with hi/lo split (round-6 proven).
// ---------------------------------------------------------------------------
#define AW   36
#define KVW  (64 * AW)
#define BUFW (4 * KVW)
#define ATT_SMEM (2 * BUFW * 4)

__global__ __launch_bounds__(256, 2)
void flash_mma_kernel(const __half* __restrict__ qh_g, const __half* __restrict__ ql_g,
                      const __half* __restrict__ kh_g, const __half* __restrict__ kl_g,
                      const __half* __restrict__ vh_g, const __half* __restrict__ vl_g,
                      float* __restrict__ out)
{
    extern __shared__ uint32_t smw[];
    const uint32_t sbase = smem_u32(smw);
    const int tid = threadIdx.x, wid = tid >> 5, lane = tid & 31;
    const int grp = lane >> 2, tg = lane & 3;
    const int bh = blockIdx.y, b = bh >> 4, h = bh & 15;
    const int qt = gridDim.x - 1 - blockIdx.x;
    const int q0 = qt * 128;
    const int wm = wid * 16;
    const int row0 = q0 + wm + grp;
    const int row1 = row0 + 8;

    {
        const uint4* qh4 = (const uint4*)(qh_g + (size_t)bh * T_ * DK_) + q0 * 8;
        const uint4* ql4 = (const uint4*)(ql_g + (size_t)bh * T_ * DK_) + q0 * 8;
#pragma unroll
        for (int j = 0; j < 4; j++) {
            int idx = tid + j * 256;
            int r = idx >> 3, c = idx & 7;
            uint32_t dst = sbase + (r * AW + c * 4) * 4;
            cp_async16(dst, qh4 + r * 8 + c);
            cp_async16(dst + 4608 * 4, ql4 + r * 8 + c);
        }
        cp_commit(); cp_wait0();
        __syncthreads();
    }
    uint32_t qfh[4][4], qfl[4][4];
    {
        const uint32_t* Q = smw;
        const int base = (wm + grp) * AW + tg;
#pragma unroll
        for (int kc = 0; kc < 4; kc++) {
            qfh[kc][0] = Q[base + 8 * kc];
            qfh[kc][1] = Q[base + 8 * AW + 8 * kc];
            qfh[kc][2] = Q[base + 8 * kc + 4];
            qfh[kc][3] = Q[base + 8 * AW + 8 * kc + 4];
            qfl[kc][0] = Q[4608 + base + 8 * kc];
            qfl[kc][1] = Q[4608 + base + 8 * AW + 8 * kc];
            qfl[kc][2] = Q[4608 + base + 8 * kc + 4];
            qfl[kc][3] = Q[4608 + base + 8 * AW + 8 * kc + 4];
        }
    }
    __syncthreads();

    const uint4* kh4 = (const uint4*)(kh_g + (size_t)bh * T_ * DK_);
    const uint4* kl4 = (const uint4*)(kl_g + (size_t)bh * T_ * DK_);
    const uint4* vh4 = (const uint4*)(vh_g + (size_t)bh * DK_ * T_);
    const uint4* vl4 = (const uint4*)(vl_g + (size_t)bh * DK_ * T_);

    auto kv_load = [&](int t, int buf) {
        const int kv0 = t * 64;
#pragma unroll
        for (int j = 0; j < 2; j++) {
            int idx = tid + j * 256;
            int r = idx >> 3, c = idx & 7;
            uint32_t dst = sbase + (buf * BUFW + r * AW + c * 4) * 4;
            cp_async16(dst,               kh4 + (kv0 + r) * 8 + c);
            cp_async16(dst + KVW * 4,     kl4 + (kv0 + r) * 8 + c);
            cp_async16(dst + 2 * KVW * 4, vh4 + (size_t)r * (T_ / 8) + kv0 / 8 + c);
            cp_async16(dst + 3 * KVW * 4, vl4 + (size_t)r * (T_ / 8) + kv0 / 8 + c);
        }
    };

    float o[8][4];
#pragma unroll
    for (int j = 0; j < 8; j++)
#pragma unroll
        for (int e = 0; e < 4; e++) o[j][e] = 0.f;
    float m0 = -1e30f, m1 = -1e30f, l0 = 0.f, l1 = 0.f;

    const int nt = 2 * (qt + 1);
    kv_load(0, 0); cp_commit();

    for (int t = 0; t < nt; t++) {
        if (t + 1 < nt) { kv_load(t + 1, (t + 1) & 1); cp_commit(); cp_wait1(); }
        else           { cp_wait0(); }
        __syncthreads();

        const uint32_t* Kh = smw + (t & 1) * BUFW;
        const uint32_t* Kl = Kh + KVW;
        const uint32_t* Vh = Kh + 2 * KVW;
        const uint32_t* Vl = Kh + 3 * KVW;

        float s[8][4];
#pragma unroll
        for (int j = 0; j < 8; j++)
#pragma unroll
            for (int e = 0; e < 4; e++) s[j][e] = 0.f;
#pragma unroll
        for (int kc = 0; kc < 4; kc++) {
            const int bo = 8 * kc + tg;
#pragma unroll
            for (int j = 0; j < 8; j++) {
                const int nb = (8 * j + grp) * AW + bo;
                uint32_t b0h = Kh[nb], b1h = Kh[nb + 4];
                uint32_t b0l = Kl[nb], b1l = Kl[nb + 4];
                mma16816(s[j], qfh[kc][0], qfh[kc][1], qfh[kc][2], qfh[kc][3], b0h, b1h);
                mma16816(s[j], qfl[kc][0], qfl[kc][1], qfl[kc][2], qfl[kc][3], b0h, b1h);
                mma16816(s[j], qfh[kc][0], qfh[kc][1], qfh[kc][2], qfh[kc][3], b0l, b1l);
            }
        }

        const int kv0 = t * 64;
        const float cs = 0.125f * 1.4426950408889634f;
        const bool maskw = (kv0 + 63 > q0 + wm);
        float mx0 = -1e30f, mx1 = -1e30f;
#pragma unroll
        for (int j = 0; j < 8; j++) {
            const int c0 = kv0 + 8 * j + 2 * tg;
            float x0 = s[j][0] * cs, x1 = s[j][1] * cs;
            float x2 = s[j][2] * cs, x3 = s[j][3] * cs;
            if (maskw) {
                if (c0 > row0)     x0 = -1e30f;
                if (c0 + 1 > row0) x1 = -1e30f;
                if (c0 > row1)     x2 = -1e30f;
                if (c0 + 1 > row1) x3 = -1e30f;
            }
            s[j][0] = x0; s[j][1] = x1; s[j][2] = x2; s[j][3] = x3;
            mx0 = fmaxf(mx0, fmaxf(x0, x1));
            mx1 = fmaxf(mx1, fmaxf(x2, x3));
        }
        mx0 = fmaxf(mx0, __shfl_xor_sync(0xffffffffu, mx0, 1));
        mx0 = fmaxf(mx0, __shfl_xor_sync(0xffffffffu, mx0, 2));
        mx1 = fmaxf(mx1, __shfl_xor_sync(0xffffffffu, mx1, 1));
        mx1 = fmaxf(mx1, __shfl_xor_sync(0xffffffffu, mx1, 2));
        const float mn0 = fmaxf(m0, mx0), mn1 = fmaxf(m1, mx1);
        const float a0 = ex2f(m0 - mn0),  a1 = ex2f(m1 - mn1);
        m0 = mn0; m1 = mn1;

        float sum0 = 0.f, sum1 = 0.f;
#pragma unroll
        for (int j = 0; j < 8; j++) {
            float p0 = ex2f(s[j][0] - m0), p1 = ex2f(s[j][1] - m0);
            float p2 = ex2f(s[j][2] - m1), p3 = ex2f(s[j][3] - m1);
            s[j][0] = p0; s[j][1] = p1; s[j][2] = p2; s[j][3] = p3;
            sum0 += p0 + p1; sum1 += p2 + p3;
        }
        sum0 += __shfl_xor_sync(0xffffffffu, sum0, 1);
        sum0 += __shfl_xor_sync(0xffffffffu, sum0, 2);
        sum1 += __shfl_xor_sync(0xffffffffu, sum1, 1);
        sum1 += __shfl_xor_sync(0xffffffffu, sum1, 2);
        l0 = l0 * a0 + sum0;
        l1 = l1 * a1 + sum1;
#pragma unroll
        for (int j = 0; j < 8; j++) {
            o[j][0] *= a0; o[j][1] *= a0; o[j][2] *= a1; o[j][3] *= a1;
        }

#pragma unroll
        for (int kc = 0; kc < 4; kc++) {
            const int j0 = 2 * kc, j1 = 2 * kc + 1;
            __half2 A0 = __floats2half2_rn(s[j0][0], s[j0][1]);
            __half2 A1 = __floats2half2_rn(s[j0][2], s[j0][3]);
            __half2 A2 = __floats2half2_rn(s[j1][0], s[j1][1]);
            __half2 A3 = __floats2half2_rn(s[j1][2], s[j1][3]);
            float2 f0 = __half22float2(A0), f1 = __half22float2(A1);
            float2 f2 = __half22float2(A2), f3 = __half22float2(A3);
            __half2 L0 = __floats2half2_rn(s[j0][0] - f0.x, s[j0][1] - f0.y);
            __half2 L1 = __floats2half2_rn(s[j0][2] - f1.x, s[j0][3] - f1.y);
            __half2 L2 = __floats2half2_rn(s[j1][0] - f2.x, s[j1][1] - f2.y);
            __half2 L3 = __floats2half2_rn(s[j1][2] - f3.x, s[j1][3] - f3.y);
            const uint32_t ph0 = *(uint32_t*)&A0, ph1 = *(uint32_t*)&A1;
            const uint32_t ph2 = *(uint32_t*)&A2, ph3 = *(uint32_t*)&A3;
            const uint32_t pl0 = *(uint32_t*)&L0, pl1 = *(uint32_t*)&L1;
            const uint32_t pl2 = *(uint32_t*)&L2, pl3 = *(uint32_t*)&L3;
            const int bo = 8 * kc + tg;
#pragma unroll
            for (int jj = 0; jj < 8; jj++) {
                const int nb = (8 * jj + grp) * AW + bo;
                uint32_t v0h = Vh[nb], v1h = Vh[nb + 4];
                uint32_t v0l = Vl[nb], v1l = Vl[nb + 4];
                mma16816(o[jj], ph0, ph1, ph2, ph3, v0h, v1h);
                mma16816(o[jj], pl0, pl1, pl2, pl3, v0h, v1h);
                mma16816(o[jj], ph0, ph1, ph2, ph3, v0l, v1l);
            }
        }
        __syncthreads();
    }

    const float i0 = 1.0f / l0, i1 = 1.0f / l1;
    float* out0 = out + ((size_t)(b * T_ + row0)) * D_ + h * 64 + 2 * tg;
    float* out1 = out + ((size_t)(b * T_ + row1)) * D_ + h * 64 + 2 * tg;
#pragma unroll
    for (int jj = 0; jj < 8; jj++) {
        float2 v0 = {rna_tf32(o[jj][0] * i0), rna_tf32(o[jj][1] * i0)};
        float2 v1 = {rna_tf32(o[jj][2] * i1), rna_tf32(o[jj][3] * i1)};
        *(float2*)(out0 + 8 * jj) = v0;
        *(float2*)(out1 + 8 * jj) = v1;
    }
}

// ---------------------------------------------------------------------------
extern "C" void kernel_launch(void* const* d_in, const int* in_sizes, int n_in,
                              void* d_out, int out_size)
{
    (void)in_sizes; (void)n_in; (void)out_size;
    const float* x     = (const float*)d_in[0];
    const float* W_qkv = (const float*)d_in[1];
    const float* b_qkv = (const float*)d_in[2];
    const float* W_out = (const float*)d_in[3];
    const float* b_out = (const float*)d_in[4];
    float* out = (float*)d_out;

    float *xt_ptr, *qkv_ptr, *att_ptr, *wqkvt_ptr, *woutt_ptr;
    cudaGetSymbolAddress((void**)&xt_ptr,    g_x_t32);
    cudaGetSymbolAddress((void**)&qkv_ptr,   g_qkv);
    cudaGetSymbolAddress((void**)&att_ptr,   g_att);
    cudaGetSymbolAddress((void**)&wqkvt_ptr, g_wqkv_t);
    cudaGetSymbolAddress((void**)&woutt_ptr, g_wout_t);
    __half *qh, *ql, *kh, *kl, *vh, *vl;
    cudaGetSymbolAddress((void**)&qh, g_q_hi);
    cudaGetSymbolAddress((void**)&ql, g_q_lo);
    cudaGetSymbolAddress((void**)&kh, g_k_hi);
    cudaGetSymbolAddress((void**)&kl, g_k_lo);
    cudaGetSymbolAddress((void**)&vh, g_vt_hi);
    cudaGetSymbolAddress((void**)&vl, g_vt_lo);

    cudaFuncSetAttribute(gemm_tf32_kernel,
                         cudaFuncAttributeMaxDynamicSharedMemorySize, GEMM_SMEM);
    cudaFuncSetAttribute(flash_mma_kernel,
                         cudaFuncAttributeMaxDynamicSharedMemorySize, ATT_SMEM);

    // 0) Pre-round operands to tf32: weights (during transpose) + x
    transpose_kernel<<<dim3(3 * D_ / 32, D_ / 32), 256>>>(W_qkv, wqkvt_ptr, D_, 3 * D_);
    transpose_kernel<<<dim3(D_ / 32, D_ / 32), 256>>>(W_out, woutt_ptr, D_, D_);
    cvt_tf32_kernel<<<(M_ * D_ / 4) / 256, 256>>>((const float4*)x, (float4*)xt_ptr);

    // 1) QKV projection with fused Q/K half-split epilogue
    gemm_tf32_kernel<<<dim3(3 * D_ / 128, M_ / 128), 128, GEMM_SMEM>>>(
        xt_ptr, wqkvt_ptr, b_qkv, qkv_ptr, M_, 3 * D_, D_,
        1, qh, ql, kh, kl);

    // 2) V transpose + split (reads V region of g_qkv)
    convert_vt_kernel<<<dim3(T_ / 32, DK_ / 32, BH_), 256>>>(qkv_ptr, vh, vl);

    // 3) Causal attention (fp16 mma, split-3x accuracy)
    flash_mma_kernel<<<dim3(T_ / 128, BH_), 256, ATT_SMEM>>>(
        qh, ql, kh, kl, vh, vl, att_ptr);

    // 4) Output projection (plain epilogue)
    gemm_tf32_kernel<<<dim3(D_ / 128, M_ / 128), 128, GEMM_SMEM>>>(
        att_ptr, woutt_ptr, b_out, out, M_, D_, D_,
        0, nullptr, nullptr, nullptr, nullptr);
}

// round 10
// speedup vs baseline: 1.1122x; 1.1122x over previous
#include <cuda_runtime.h>
#include <cuda_fp16.h>
#include <cstdint>

#define B_  4
#define T_  2048
#define D_  1024
#define H_  16
#define DK_ 64
#define M_  (B_*T_)
#define BH_ (B_*H_)

// Scratch (allocation-free rule: module-scope device globals)
__device__ float g_x_t32[(size_t)M_ * D_];       // x pre-rounded to tf32
__device__ float g_qkv[(size_t)M_ * 3 * D_];     // [B,T,3D] (only V region written)
__device__ float g_att[(size_t)M_ * D_];         // [B,T,D] (tf32-rounded values)
__device__ float g_wqkv_t[(size_t)3 * D_ * D_];  // W_qkv^T [3D, D] tf32-rounded
__device__ float g_wout_t[(size_t)D_ * D_];      // W_out^T [D, D] tf32-rounded
// half hi/lo splits for attention
__device__ __half g_q_hi[(size_t)BH_ * T_ * DK_];
__device__ __half g_q_lo[(size_t)BH_ * T_ * DK_];
__device__ __half g_k_hi[(size_t)BH_ * T_ * DK_];
__device__ __half g_k_lo[(size_t)BH_ * T_ * DK_];
__device__ __half g_vt_hi[(size_t)BH_ * DK_ * T_];  // [bh][d][t]
__device__ __half g_vt_lo[(size_t)BH_ * DK_ * T_];

// ---------------------------------------------------------------------------
// PTX helpers
// ---------------------------------------------------------------------------
__device__ __forceinline__ uint32_t smem_u32(const void* p) {
    uint32_t a;
    asm("{ .reg .u64 t; cvta.to.shared.u64 t, %1; cvt.u32.u64 %0, t; }"
        : "=r"(a) : "l"(p));
    return a;
}
__device__ __forceinline__ void cp_async16(uint32_t dst, const void* src) {
    asm volatile("cp.async.ca.shared.global [%0], [%1], 16;"
                 :: "r"(dst), "l"(src) : "memory");
}
__device__ __forceinline__ void cp_commit() {
    asm volatile("cp.async.commit_group;" ::: "memory");
}
__device__ __forceinline__ void cp_wait0() {
    asm volatile("cp.async.wait_group 0;" ::: "memory");
}
__device__ __forceinline__ void cp_wait1() {
    asm volatile("cp.async.wait_group 1;" ::: "memory");
}
__device__ __forceinline__ void cp_wait2() {
    asm volatile("cp.async.wait_group 2;" ::: "memory");
}
__device__ __forceinline__ float ex2f(float x) {
    float y;
    asm("ex2.approx.f32 %0, %1;" : "=f"(y) : "f"(x));
    return y;
}
__device__ __forceinline__ float rna_tf32(float x) {
    uint32_t r;
    asm("cvt.rna.tf32.f32 %0, %1;" : "=r"(r) : "f"(x));
    return __uint_as_float(r);
}
__device__ __forceinline__ void cvt4_rna(uint32_t (&o)[4], float4 v) {
    asm("cvt.rna.tf32.f32 %0, %1;" : "=r"(o[0]) : "f"(v.x));
    asm("cvt.rna.tf32.f32 %0, %1;" : "=r"(o[1]) : "f"(v.y));
    asm("cvt.rna.tf32.f32 %0, %1;" : "=r"(o[2]) : "f"(v.z));
    asm("cvt.rna.tf32.f32 %0, %1;" : "=r"(o[3]) : "f"(v.w));
}
__device__ __forceinline__ void mma16816(float (&c)[4], uint32_t a0, uint32_t a1,
                                         uint32_t a2, uint32_t a3,
                                         uint32_t b0, uint32_t b1) {
    asm volatile(
        "mma.sync.aligned.m16n8k16.row.col.f32.f16.f16.f32 "
        "{%0,%1,%2,%3}, {%4,%5,%6,%7}, {%8,%9}, {%0,%1,%2,%3};"
        : "+f"(c[0]), "+f"(c[1]), "+f"(c[2]), "+f"(c[3])
        : "r"(a0), "r"(a1), "r"(a2), "r"(a3), "r"(b0), "r"(b1));
}
__device__ __forceinline__ void mma_tf32(float (&c)[4], const uint32_t (&a)[4],
                                         const uint32_t (&b)[2]) {
    asm volatile(
        "mma.sync.aligned.m16n8k8.row.col.f32.tf32.tf32.f32 "
        "{%0,%1,%2,%3}, {%4,%5,%6,%7}, {%8,%9}, {%0,%1,%2,%3};"
        : "+f"(c[0]), "+f"(c[1]), "+f"(c[2]), "+f"(c[3])
        : "r"(a[0]), "r"(a[1]), "r"(a[2]), "r"(a[3]), "r"(b[0]), "r"(b[1]));
}

// split one float pair into half2 hi/lo and store
__device__ __forceinline__ void split_store2(float x, float y,
                                             __half* hi, __half* lo, size_t o) {
    __half2 h = __floats2half2_rn(x, y);
    float2 f = __half22float2(h);
    __half2 l = __floats2half2_rn(x - f.x, y - f.y);
    *(__half2*)(hi + o) = h;
    *(__half2*)(lo + o) = l;
}

// ---------------------------------------------------------------------------
// Elementwise tf32 rounding
// ---------------------------------------------------------------------------
__global__ __launch_bounds__(256)
void cvt_tf32_kernel(const float4* __restrict__ in, float4* __restrict__ out)
{
    int i = blockIdx.x * 256 + threadIdx.x;
    uint32_t c4[4];
    cvt4_rna(c4, in[i]);
    out[i] = *(float4*)c4;
}

// ---------------------------------------------------------------------------
// Transpose + tf32 round: out[c][r] = rna_tf32(in[r][c])   (in: [R,C])
// ---------------------------------------------------------------------------
__global__ __launch_bounds__(256)
void transpose_kernel(const float* __restrict__ in, float* __restrict__ out,
                      int R, int C)
{
    __shared__ float t[32][33];
    int bx = blockIdx.x * 32;
    int by = blockIdx.y * 32;
    int tx = threadIdx.x & 31, ty = threadIdx.x >> 5;
#pragma unroll
    for (int j = 0; j < 32; j += 8)
        t[ty + j][tx] = in[(size_t)(by + ty + j) * C + bx + tx];
    __syncthreads();
#pragma unroll
    for (int j = 0; j < 32; j += 8)
        out[(size_t)(bx + ty + j) * R + by + tx] = rna_tf32(t[tx][ty + j]);
}

// ---------------------------------------------------------------------------
// tf32 GEMM (round-6 mainloop, exact): C[M,N] = A[M,K] @ Bt[N,K]^T + bias[N]
// CTA 128x128, 128 threads = 4 warps (2Mx2N), warp tile 64x64. BK=16.
// NSTAGE=4 (& 3 slot math), per-chunk issue, cp_wait2, ONE barrier per chunk.
// Fused epilogue option: Q/K regions of the QKV projection are split to
// half hi/lo directly (bit-identical to the old convert_qk pass).
// ---------------------------------------------------------------------------
#define APAD   20
#define ATILE  (128 * APAD)             // words per operand per stage
#define STW    (2 * ATILE)              // words per stage
#define NSTAGE 4
#define GEMM_SMEM (NSTAGE * STW * 4)    // 81920 B

__global__ __launch_bounds__(128, 2)
void gemm_tf32_kernel(const float* __restrict__ A,
                      const float* __restrict__ Bt,
                      const float* __restrict__ bias,
                      float* __restrict__ C,
                      int M, int N, int K,
                      int fuse_qk,
                      __half* __restrict__ qh, __half* __restrict__ ql,
                      __half* __restrict__ kh, __half* __restrict__ kl)
{
    extern __shared__ uint32_t smw[];
    const uint32_t sbase = smem_u32(smw);
    const int tid  = threadIdx.x;
    const int wid  = tid >> 5;
    const int lane = tid & 31;
    const int grp  = lane >> 2;
    const int tg   = lane & 3;
    const int warp_m = (wid & 1) * 64;
    const int warp_n = (wid >> 1) * 64;
    const int m0 = blockIdx.y * 128;
    const int n0 = blockIdx.x * 128;
    const int nk = K >> 4;

    const float* Abase = A + (size_t)m0 * K;
    const float* Bbase = Bt + (size_t)n0 * K;

    auto issue = [&](int i) {
        if (i < nk) {
            const int k0 = i << 4;
            const uint32_t st = sbase + ((i & (NSTAGE - 1)) * STW) * 4;
#pragma unroll
            for (int j = 0; j < 4; j++) {
                const int idx = tid + j * 128;          // 0..511
                const int r = idx >> 2, kc = (idx & 3) << 2;
                cp_async16(st + (r * APAD + kc) * 4,
                           Abase + (size_t)r * K + k0 + kc);
                cp_async16(st + (ATILE + r * APAD + kc) * 4,
                           Bbase + (size_t)r * K + k0 + kc);
            }
        }
        cp_commit();
    };

    float acc[4][8][4];
#pragma unroll
    for (int i = 0; i < 4; i++)
#pragma unroll
        for (int j = 0; j < 8; j++)
#pragma unroll
            for (int r = 0; r < 4; r++) acc[i][j][r] = 0.f;

    issue(0); issue(1); issue(2);

    uint32_t a[2][4][4], b[2][8][2];

    for (int i = 0; i < nk; i++) {
        cp_wait2();
        __syncthreads();
        issue(i + 3);

        const uint32_t* Au = smw + (i & (NSTAGE - 1)) * STW;
        const uint32_t* Bu = Au + ATILE;

        // load ks=0 fragments
        {
            const int k0 = tg;
#pragma unroll
            for (int ii = 0; ii < 4; ii++) {
                const uint32_t* p0 = Au + (warp_m + 16 * ii + grp) * APAD;
                a[0][ii][0] = p0[k0];
                a[0][ii][2] = p0[k0 + 4];
                const uint32_t* p1 = p0 + 8 * APAD;
                a[0][ii][1] = p1[k0];
                a[0][ii][3] = p1[k0 + 4];
            }
#pragma unroll
            for (int jj = 0; jj < 8; jj++) {
                const uint32_t* pn = Bu + (warp_n + 8 * jj + grp) * APAD;
                b[0][jj][0] = pn[k0];
                b[0][jj][1] = pn[k0 + 4];
            }
        }
#pragma unroll
        for (int ks = 0; ks < 2; ks++) {
            if (ks == 0) {      // prefetch ks=1 fragments under ks=0 mma
                const int k0 = 8 + tg;
#pragma unroll
                for (int ii = 0; ii < 4; ii++) {
                    const uint32_t* p0 = Au + (warp_m + 16 * ii + grp) * APAD;
                    a[1][ii][0] = p0[k0];
                    a[1][ii][2] = p0[k0 + 4];
                    const uint32_t* p1 = p0 + 8 * APAD;
                    a[1][ii][1] = p1[k0];
                    a[1][ii][3] = p1[k0 + 4];
                }
#pragma unroll
                for (int jj = 0; jj < 8; jj++) {
                    const uint32_t* pn = Bu + (warp_n + 8 * jj + grp) * APAD;
                    b[1][jj][0] = pn[k0];
                    b[1][jj][1] = pn[k0 + 4];
                }
            }
#pragma unroll
            for (int ii = 0; ii < 4; ii++)
#pragma unroll
                for (int jj = 0; jj < 8; jj++)
                    mma_tf32(acc[ii][jj], a[ks][ii], b[ks][jj]);
        }
    }

    // ---- epilogue
    const int region = fuse_qk ? (n0 >> 10) : 3;   // 0=Q, 1=K, 2=V/plain, 3=plain
#pragma unroll
    for (int ii = 0; ii < 4; ii++) {
        const int m = m0 + warp_m + 16 * ii + grp;
#pragma unroll
        for (int jj = 0; jj < 8; jj++) {
            const int n = n0 + warp_n + 8 * jj + 2 * tg;
            const float bv0 = __ldg(&bias[n]);
            const float bv1 = __ldg(&bias[n + 1]);
            const float v00 = acc[ii][jj][0] + bv0, v01 = acc[ii][jj][1] + bv1;
            const float v10 = acc[ii][jj][2] + bv0, v11 = acc[ii][jj][3] + bv1;
            if (region <= 1) {
                // Q or K: split-store half hi/lo at [bh][t][d]
                const int nr = n - (region << 10);     // 0..1023 within region
                const int hh = nr >> 6, d = nr & 63;
                const int b0i = m >> 11, t0i = m & 2047;
                const size_t o0 = ((size_t)(b0i * 16 + hh) * T_ + t0i) * 64 + d;
                const int b1i = (m + 8) >> 11, t1i = (m + 8) & 2047;
                const size_t o1 = ((size_t)(b1i * 16 + hh) * T_ + t1i) * 64 + d;
                if (region == 0) {
                    split_store2(v00, v01, qh, ql, o0);
                    split_store2(v10, v11, qh, ql, o1);
                } else {
                    split_store2(v00, v01, kh, kl, o0);
                    split_store2(v10, v11, kh, kl, o1);
                }
            } else {
                float2 v0 = {v00, v01};
                float2 v1 = {v10, v11};
                *(float2*)(C + (size_t)m * N + n)       = v0;
                *(float2*)(C + (size_t)(m + 8) * N + n) = v1;
            }
        }
    }
}

// ---------------------------------------------------------------------------
// V transpose + split: g_qkv V part -> [bh][d][t] hi/lo halfs
// ---------------------------------------------------------------------------
__global__ __launch_bounds__(256)
void convert_vt_kernel(const float* __restrict__ qkv,
                       __half* __restrict__ vh, __half* __restrict__ vl)
{
    __shared__ float tile[32][33];
    int t0 = blockIdx.x * 32;
    int d0 = blockIdx.y * 32;
    int bh = blockIdx.z;
    int b = bh >> 4, h = bh & 15;
    int tx = threadIdx.x & 31, ty = threadIdx.x >> 5;
#pragma unroll
    for (int j = 0; j < 32; j += 8)
        tile[ty + j][tx] = qkv[((size_t)(b * T_ + t0 + ty + j)) * 3 * D_
                               + 2 * D_ + h * 64 + d0 + tx];
    __syncthreads();
#pragma unroll
    for (int j = 0; j < 32; j += 8) {
        int d = d0 + ty + j;
        float v = tile[tx][ty + j];
        __half hv = __float2half_rn(v);
        __half lv = __float2half_rn(v - __half2float(hv));
        size_t o = ((size_t)bh * DK_ + d) * T_ + t0 + tx;
        vh[o] = hv;
        vl[o] = lv;
    }
}

// ---------------------------------------------------------------------------
// Flash attention on fp16 tensor cores with hi/lo split (round-6 proven).
// ---------------------------------------------------------------------------
#define AW   36
#define KVW  (64 * AW)
#define BUFW (4 * KVW)
#define ATT_SMEM (2 * BUFW * 4)

__global__ __launch_bounds__(256, 2)
void flash_mma_kernel(const __half* __restrict__ qh_g, const __half* __restrict__ ql_g,
                      const __half* __restrict__ kh_g, const __half* __restrict__ kl_g,
                      const __half* __restrict__ vh_g, const __half* __restrict__ vl_g,
                      float* __restrict__ out)
{
    extern __shared__ uint32_t smw[];
    const uint32_t sbase = smem_u32(smw);
    const int tid = threadIdx.x, wid = tid >> 5, lane = tid & 31;
    const int grp = lane >> 2, tg = lane & 3;
    const int bh = blockIdx.y, b = bh >> 4, h = bh & 15;
    const int qt = gridDim.x - 1 - blockIdx.x;
    const int q0 = qt * 128;
    const int wm = wid * 16;
    const int row0 = q0 + wm + grp;
    const int row1 = row0 + 8;

    {
        const uint4* qh4 = (const uint4*)(qh_g + (size_t)bh * T_ * DK_) + q0 * 8;
        const uint4* ql4 = (const uint4*)(ql_g + (size_t)bh * T_ * DK_) + q0 * 8;
#pragma unroll
        for (int j = 0; j < 4; j++) {
            int idx = tid + j * 256;
            int r = idx >> 3, c = idx & 7;
            uint32_t dst = sbase + (r * AW + c * 4) * 4;
            cp_async16(dst, qh4 + r * 8 + c);
            cp_async16(dst + 4608 * 4, ql4 + r * 8 + c);
        }
        cp_commit(); cp_wait0();
        __syncthreads();
    }
    uint32_t qfh[4][4], qfl[4][4];
    {
        const uint32_t* Q = smw;
        const int base = (wm + grp) * AW + tg;
#pragma unroll
        for (int kc = 0; kc < 4; kc++) {
            qfh[kc][0] = Q[base + 8 * kc];
            qfh[kc][1] = Q[base + 8 * AW + 8 * kc];
            qfh[kc][2] = Q[base + 8 * kc + 4];
            qfh[kc][3] = Q[base + 8 * AW + 8 * kc + 4];
            qfl[kc][0] = Q[4608 + base + 8 * kc];
            qfl[kc][1] = Q[4608 + base + 8 * AW + 8 * kc];
            qfl[kc][2] = Q[4608 + base + 8 * kc + 4];
            qfl[kc][3] = Q[4608 + base + 8 * AW + 8 * kc + 4];
        }
    }
    __syncthreads();

    const uint4* kh4 = (const uint4*)(kh_g + (size_t)bh * T_ * DK_);
    const uint4* kl4 = (const uint4*)(kl_g + (size_t)bh * T_ * DK_);
    const uint4* vh4 = (const uint4*)(vh_g + (size_t)bh * DK_ * T_);
    const uint4* vl4 = (const uint4*)(vl_g + (size_t)bh * DK_ * T_);

    auto kv_load = [&](int t, int buf) {
        const int kv0 = t * 64;
#pragma unroll
        for (int j = 0; j < 2; j++) {
            int idx = tid + j * 256;
            int r = idx >> 3, c = idx & 7;
            uint32_t dst = sbase + (buf * BUFW + r * AW + c * 4) * 4;
            cp_async16(dst,               kh4 + (kv0 + r) * 8 + c);
            cp_async16(dst + KVW * 4,     kl4 + (kv0 + r) * 8 + c);
            cp_async16(dst + 2 * KVW * 4, vh4 + (size_t)r * (T_ / 8) + kv0 / 8 + c);
            cp_async16(dst + 3 * KVW * 4, vl4 + (size_t)r * (T_ / 8) + kv0 / 8 + c);
        }
    };

    float o[8][4];
#pragma unroll
    for (int j = 0; j < 8; j++)
#pragma unroll
        for (int e = 0; e < 4; e++) o[j][e] = 0.f;
    float m0 = -1e30f, m1 = -1e30f, l0 = 0.f, l1 = 0.f;

    const int nt = 2 * (qt + 1);
    kv_load(0, 0); cp_commit();

    for (int t = 0; t < nt; t++) {
        if (t + 1 < nt) { kv_load(t + 1, (t + 1) & 1); cp_commit(); cp_wait1(); }
        else           { cp_wait0(); }
        __syncthreads();

        const uint32_t* Kh = smw + (t & 1) * BUFW;
        const uint32_t* Kl = Kh + KVW;
        const uint32_t* Vh = Kh + 2 * KVW;
        const uint32_t* Vl = Kh + 3 * KVW;

        float s[8][4];
#pragma unroll
        for (int j = 0; j < 8; j++)
#pragma unroll
            for (int e = 0; e < 4; e++) s[j][e] = 0.f;
#pragma unroll
        for (int kc = 0; kc < 4; kc++) {
            const int bo = 8 * kc + tg;
#pragma unroll
            for (int j = 0; j < 8; j++) {
                const int nb = (8 * j + grp) * AW + bo;
                uint32_t b0h = Kh[nb], b1h = Kh[nb + 4];
                uint32_t b0l = Kl[nb], b1l = Kl[nb + 4];
                mma16816(s[j], qfh[kc][0], qfh[kc][1], qfh[kc][2], qfh[kc][3], b0h, b1h);
                mma16816(s[j], qfl[kc][0], qfl[kc][1], qfl[kc][2], qfl[kc][3], b0h, b1h);
                mma16816(s[j], qfh[kc][0], qfh[kc][1], qfh[kc][2], qfh[kc][3], b0l, b1l);
            }
        }

        const int kv0 = t * 64;
        const float cs = 0.125f * 1.4426950408889634f;
        const bool maskw = (kv0 + 63 > q0 + wm);
        float mx0 = -1e30f, mx1 = -1e30f;
#pragma unroll
        for (int j = 0; j < 8; j++) {
            const int c0 = kv0 + 8 * j + 2 * tg;
            float x0 = s[j][0] * cs, x1 = s[j][1] * cs;
            float x2 = s[j][2] * cs, x3 = s[j][3] * cs;
            if (maskw) {
                if (c0 > row0)     x0 = -1e30f;
                if (c0 + 1 > row0) x1 = -1e30f;
                if (c0 > row1)     x2 = -1e30f;
                if (c0 + 1 > row1) x3 = -1e30f;
            }
            s[j][0] = x0; s[j][1] = x1; s[j][2] = x2; s[j][3] = x3;
            mx0 = fmaxf(mx0, fmaxf(x0, x1));
            mx1 = fmaxf(mx1, fmaxf(x2, x3));
        }
        mx0 = fmaxf(mx0, __shfl_xor_sync(0xffffffffu, mx0, 1));
        mx0 = fmaxf(mx0, __shfl_xor_sync(0xffffffffu, mx0, 2));
        mx1 = fmaxf(mx1, __shfl_xor_sync(0xffffffffu, mx1, 1));
        mx1 = fmaxf(mx1, __shfl_xor_sync(0xffffffffu, mx1, 2));
        const float mn0 = fmaxf(m0, mx0), mn1 = fmaxf(m1, mx1);
        const float a0 = ex2f(m0 - mn0),  a1 = ex2f(m1 - mn1);
        m0 = mn0; m1 = mn1;

        float sum0 = 0.f, sum1 = 0.f;
#pragma unroll
        for (int j = 0; j < 8; j++) {
            float p0 = ex2f(s[j][0] - m0), p1 = ex2f(s[j][1] - m0);
            float p2 = ex2f(s[j][2] - m1), p3 = ex2f(s[j][3] - m1);
            s[j][0] = p0; s[j][1] = p1; s[j][2] = p2; s[j][3] = p3;
            sum0 += p0 + p1; sum1 += p2 + p3;
        }
        sum0 += __shfl_xor_sync(0xffffffffu, sum0, 1);
        sum0 += __shfl_xor_sync(0xffffffffu, sum0, 2);
        sum1 += __shfl_xor_sync(0xffffffffu, sum1, 1);
        sum1 += __shfl_xor_sync(0xffffffffu, sum1, 2);
        l0 = l0 * a0 + sum0;
        l1 = l1 * a1 + sum1;
#pragma unroll
        for (int j = 0; j < 8; j++) {
            o[j][0] *= a0; o[j][1] *= a0; o[j][2] *= a1; o[j][3] *= a1;
        }

#pragma unroll
        for (int kc = 0; kc < 4; kc++) {
            const int j0 = 2 * kc, j1 = 2 * kc + 1;
            __half2 A0 = __floats2half2_rn(s[j0][0], s[j0][1]);
            __half2 A1 = __floats2half2_rn(s[j0][2], s[j0][3]);
            __half2 A2 = __floats2half2_rn(s[j1][0], s[j1][1]);
            __half2 A3 = __floats2half2_rn(s[j1][2], s[j1][3]);
            float2 f0 = __half22float2(A0), f1 = __half22float2(A1);
            float2 f2 = __half22float2(A2), f3 = __half22float2(A3);
            __half2 L0 = __floats2half2_rn(s[j0][0] - f0.x, s[j0][1] - f0.y);
            __half2 L1 = __floats2half2_rn(s[j0][2] - f1.x, s[j0][3] - f1.y);
            __half2 L2 = __floats2half2_rn(s[j1][0] - f2.x, s[j1][1] - f2.y);
            __half2 L3 = __floats2half2_rn(s[j1][2] - f3.x, s[j1][3] - f3.y);
            const uint32_t ph0 = *(uint32_t*)&A0, ph1 = *(uint32_t*)&A1;
            const uint32_t ph2 = *(uint32_t*)&A2, ph3 = *(uint32_t*)&A3;
            const uint32_t pl0 = *(uint32_t*)&L0, pl1 = *(uint32_t*)&L1;
            const uint32_t pl2 = *(uint32_t*)&L2, pl3 = *(uint32_t*)&L3;
            const int bo = 8 * kc + tg;
#pragma unroll
            for (int jj = 0; jj < 8; jj++) {
                const int nb = (8 * jj + grp) * AW + bo;
                uint32_t v0h = Vh[nb], v1h = Vh[nb + 4];
                uint32_t v0l = Vl[nb], v1l = Vl[nb + 4];
                mma16816(o[jj], ph0, ph1, ph2, ph3, v0h, v1h);
                mma16816(o[jj], pl0, pl1, pl2, pl3, v0h, v1h);
                mma16816(o[jj], ph0, ph1, ph2, ph3, v0l, v1l);
            }
        }
        __syncthreads();
    }

    const float i0 = 1.0f / l0, i1 = 1.0f / l1;
    float* out0 = out + ((size_t)(b * T_ + row0)) * D_ + h * 64 + 2 * tg;
    float* out1 = out + ((size_t)(b * T_ + row1)) * D_ + h * 64 + 2 * tg;
#pragma unroll
    for (int jj = 0; jj < 8; jj++) {
        float2 v0 = {rna_tf32(o[jj][0] * i0), rna_tf32(o[jj][1] * i0)};
        float2 v1 = {rna_tf32(o[jj][2] * i1), rna_tf32(o[jj][3] * i1)};
        *(float2*)(out0 + 8 * jj) = v0;
        *(float2*)(out1 + 8 * jj) = v1;
    }
}

// ---------------------------------------------------------------------------
extern "C" void kernel_launch(void* const* d_in, const int* in_sizes, int n_in,
                              void* d_out, int out_size)
{
    (void)in_sizes; (void)n_in; (void)out_size;
    const float* x     = (const float*)d_in[0];
    const float* W_qkv = (const float*)d_in[1];
    const float* b_qkv = (const float*)d_in[2];
    const float* W_out = (const float*)d_in[3];
    const float* b_out = (const float*)d_in[4];
    float* out = (float*)d_out;

    float *xt_ptr, *qkv_ptr, *att_ptr, *wqkvt_ptr, *woutt_ptr;
    cudaGetSymbolAddress((void**)&xt_ptr,    g_x_t32);
    cudaGetSymbolAddress((void**)&qkv_ptr,   g_qkv);
    cudaGetSymbolAddress((void**)&att_ptr,   g_att);
    cudaGetSymbolAddress((void**)&wqkvt_ptr, g_wqkv_t);
    cudaGetSymbolAddress((void**)&woutt_ptr, g_wout_t);
    __half *qh, *ql, *kh, *kl, *vh, *vl;
    cudaGetSymbolAddress((void**)&qh, g_q_hi);
    cudaGetSymbolAddress((void**)&ql, g_q_lo);
    cudaGetSymbolAddress((void**)&kh, g_k_hi);
    cudaGetSymbolAddress((void**)&kl, g_k_lo);
    cudaGetSymbolAddress((void**)&vh, g_vt_hi);
    cudaGetSymbolAddress((void**)&vl, g_vt_lo);

    cudaFuncSetAttribute(gemm_tf32_kernel,
                         cudaFuncAttributeMaxDynamicSharedMemorySize, GEMM_SMEM);
    cudaFuncSetAttribute(flash_mma_kernel,
                         cudaFuncAttributeMaxDynamicSharedMemorySize, ATT_SMEM);

    // 0) Pre-round operands to tf32: weights (during transpose) + x
    transpose_kernel<<<dim3(3 * D_ / 32, D_ / 32), 256>>>(W_qkv, wqkvt_ptr, D_, 3 * D_);
    transpose_kernel<<<dim3(D_ / 32, D_ / 32), 256>>>(W_out, woutt_ptr, D_, D_);
    cvt_tf32_kernel<<<(M_ * D_ / 4) / 256, 256>>>((const float4*)x, (float4*)xt_ptr);

    // 1) QKV projection (round-6 mainloop) with fused Q/K half-split epilogue
    gemm_tf32_kernel<<<dim3(3 * D_ / 128, M_ / 128), 128, GEMM_SMEM>>>(
        xt_ptr, wqkvt_ptr, b_qkv, qkv_ptr, M_, 3 * D_, D_,
        1, qh, ql, kh, kl);

    // 2) V transpose + split (reads V region of g_qkv)
    convert_vt_kernel<<<dim3(T_ / 32, DK_ / 32, BH_), 256>>>(qkv_ptr, vh, vl);

    // 3) Causal attention (fp16 mma, split-3x accuracy)
    flash_mma_kernel<<<dim3(T_ / 128, BH_), 256, ATT_SMEM>>>(
        qh, ql, kh, kl, vh, vl, att_ptr);

    // 4) Output projection (plain epilogue)
    gemm_tf32_kernel<<<dim3(D_ / 128, M_ / 128), 128, GEMM_SMEM>>>(
        att_ptr, woutt_ptr, b_out, out, M_, D_, D_,
        0, nullptr, nullptr, nullptr, nullptr);
}

// round 11
// speedup vs baseline: 1.1343x; 1.0199x over previous
#include <cuda_runtime.h>
#include <cuda_fp16.h>
#include <cstdint>

#define B_  4
#define T_  2048
#define D_  1024
#define H_  16
#define DK_ 64
#define M_  (B_*T_)
#define BH_ (B_*H_)

// Scratch (allocation-free rule: module-scope device globals)
__device__ float g_x_t32[(size_t)M_ * D_];       // x pre-rounded to tf32
__device__ float g_qkv[(size_t)M_ * 3 * D_];     // [B,T,3D] (only V region written)
__device__ float g_att[(size_t)M_ * D_];         // [B,T,D] (tf32-rounded values)
__device__ float g_wqkv_t[(size_t)3 * D_ * D_];  // W_qkv^T [3D, D] tf32-rounded
__device__ float g_wout_t[(size_t)D_ * D_];      // W_out^T [D, D] tf32-rounded
// half hi/lo splits for attention
__device__ __half g_q_hi[(size_t)BH_ * T_ * DK_];
__device__ __half g_q_lo[(size_t)BH_ * T_ * DK_];
__device__ __half g_k_hi[(size_t)BH_ * T_ * DK_];
__device__ __half g_k_lo[(size_t)BH_ * T_ * DK_];
__device__ __half g_vt_hi[(size_t)BH_ * DK_ * T_];  // [bh][d][t]
__device__ __half g_vt_lo[(size_t)BH_ * DK_ * T_];

// ---------------------------------------------------------------------------
// PTX helpers
// ---------------------------------------------------------------------------
__device__ __forceinline__ uint32_t smem_u32(const void* p) {
    uint32_t a;
    asm("{ .reg .u64 t; cvta.to.shared.u64 t, %1; cvt.u32.u64 %0, t; }"
        : "=r"(a) : "l"(p));
    return a;
}
__device__ __forceinline__ void cp_async16(uint32_t dst, const void* src) {
    asm volatile("cp.async.ca.shared.global [%0], [%1], 16;"
                 :: "r"(dst), "l"(src) : "memory");
}
__device__ __forceinline__ void cp_commit() {
    asm volatile("cp.async.commit_group;" ::: "memory");
}
__device__ __forceinline__ void cp_wait0() {
    asm volatile("cp.async.wait_group 0;" ::: "memory");
}
__device__ __forceinline__ void cp_wait1() {
    asm volatile("cp.async.wait_group 1;" ::: "memory");
}
__device__ __forceinline__ void cp_wait2() {
    asm volatile("cp.async.wait_group 2;" ::: "memory");
}
__device__ __forceinline__ float ex2f(float x) {
    float y;
    asm("ex2.approx.f32 %0, %1;" : "=f"(y) : "f"(x));
    return y;
}
__device__ __forceinline__ float rna_tf32(float x) {
    uint32_t r;
    asm("cvt.rna.tf32.f32 %0, %1;" : "=r"(r) : "f"(x));
    return __uint_as_float(r);
}
__device__ __forceinline__ void cvt4_rna(uint32_t (&o)[4], float4 v) {
    asm("cvt.rna.tf32.f32 %0, %1;" : "=r"(o[0]) : "f"(v.x));
    asm("cvt.rna.tf32.f32 %0, %1;" : "=r"(o[1]) : "f"(v.y));
    asm("cvt.rna.tf32.f32 %0, %1;" : "=r"(o[2]) : "f"(v.z));
    asm("cvt.rna.tf32.f32 %0, %1;" : "=r"(o[3]) : "f"(v.w));
}
__device__ __forceinline__ void mma16816(float (&c)[4], uint32_t a0, uint32_t a1,
                                         uint32_t a2, uint32_t a3,
                                         uint32_t b0, uint32_t b1) {
    asm volatile(
        "mma.sync.aligned.m16n8k16.row.col.f32.f16.f16.f32 "
        "{%0,%1,%2,%3}, {%4,%5,%6,%7}, {%8,%9}, {%0,%1,%2,%3};"
        : "+f"(c[0]), "+f"(c[1]), "+f"(c[2]), "+f"(c[3])
        : "r"(a0), "r"(a1), "r"(a2), "r"(a3), "r"(b0), "r"(b1));
}
__device__ __forceinline__ void mma_tf32(float (&c)[4], const uint32_t (&a)[4],
                                         const uint32_t (&b)[2]) {
    asm volatile(
        "mma.sync.aligned.m16n8k8.row.col.f32.tf32.tf32.f32 "
        "{%0,%1,%2,%3}, {%4,%5,%6,%7}, {%8,%9}, {%0,%1,%2,%3};"
        : "+f"(c[0]), "+f"(c[1]), "+f"(c[2]), "+f"(c[3])
        : "r"(a[0]), "r"(a[1]), "r"(a[2]), "r"(a[3]), "r"(b[0]), "r"(b[1]));
}

// split one float pair into half2 hi/lo and store
__device__ __forceinline__ void split_store2(float x, float y,
                                             __half* hi, __half* lo, size_t o) {
    __half2 h = __floats2half2_rn(x, y);
    float2 f = __half22float2(h);
    __half2 l = __floats2half2_rn(x - f.x, y - f.y);
    *(__half2*)(hi + o) = h;
    *(__half2*)(lo + o) = l;
}

// ---------------------------------------------------------------------------
// Elementwise tf32 rounding
// ---------------------------------------------------------------------------
__global__ __launch_bounds__(256)
void cvt_tf32_kernel(const float4* __restrict__ in, float4* __restrict__ out)
{
    int i = blockIdx.x * 256 + threadIdx.x;
    uint32_t c4[4];
    cvt4_rna(c4, in[i]);
    out[i] = *(float4*)c4;
}

// ---------------------------------------------------------------------------
// Transpose + tf32 round: out[c][r] = rna_tf32(in[r][c])   (in: [R,C])
// ---------------------------------------------------------------------------
__global__ __launch_bounds__(256)
void transpose_kernel(const float* __restrict__ in, float* __restrict__ out,
                      int R, int C)
{
    __shared__ float t[32][33];
    int bx = blockIdx.x * 32;
    int by = blockIdx.y * 32;
    int tx = threadIdx.x & 31, ty = threadIdx.x >> 5;
#pragma unroll
    for (int j = 0; j < 32; j += 8)
        t[ty + j][tx] = in[(size_t)(by + ty + j) * C + bx + tx];
    __syncthreads();
#pragma unroll
    for (int j = 0; j < 32; j += 8)
        out[(size_t)(bx + ty + j) * R + by + tx] = rna_tf32(t[tx][ty + j]);
}

// ---------------------------------------------------------------------------
// tf32 GEMM (round-6 mainloop, exact): C[M,N] = A[M,K] @ Bt[N,K]^T + bias[N]
// CTA 128x128, 128 threads = 4 warps (2Mx2N), warp tile 64x64. BK=16.
// NSTAGE=4 (& 3 slot math), per-chunk issue, cp_wait2, ONE barrier per chunk.
// Fused Q/K epilogue v2: stage acc+bias in smem (pipeline buffers are dead),
// then COALESCED half2 hi/lo stores (one 64-half contiguous run per warp-op).
// Values bit-identical to the plain-store + convert_qk path.
// ---------------------------------------------------------------------------
#define APAD   20
#define ATILE  (128 * APAD)             // words per operand per stage
#define STW    (2 * ATILE)              // words per stage
#define NSTAGE 4
#define GEMM_SMEM (NSTAGE * STW * 4)    // 81920 B
#define SPAD   130                      // staging row stride (floats)

__global__ __launch_bounds__(128, 2)
void gemm_tf32_kernel(const float* __restrict__ A,
                      const float* __restrict__ Bt,
                      const float* __restrict__ bias,
                      float* __restrict__ C,
                      int M, int N, int K,
                      int fuse_qk,
                      __half* __restrict__ qh, __half* __restrict__ ql,
                      __half* __restrict__ kh, __half* __restrict__ kl)
{
    extern __shared__ uint32_t smw[];
    const uint32_t sbase = smem_u32(smw);
    const int tid  = threadIdx.x;
    const int wid  = tid >> 5;
    const int lane = tid & 31;
    const int grp  = lane >> 2;
    const int tg   = lane & 3;
    const int warp_m = (wid & 1) * 64;
    const int warp_n = (wid >> 1) * 64;
    const int m0 = blockIdx.y * 128;
    const int n0 = blockIdx.x * 128;
    const int nk = K >> 4;

    const float* Abase = A + (size_t)m0 * K;
    const float* Bbase = Bt + (size_t)n0 * K;

    auto issue = [&](int i) {
        if (i < nk) {
            const int k0 = i << 4;
            const uint32_t st = sbase + ((i & (NSTAGE - 1)) * STW) * 4;
#pragma unroll
            for (int j = 0; j < 4; j++) {
                const int idx = tid + j * 128;          // 0..511
                const int r = idx >> 2, kc = (idx & 3) << 2;
                cp_async16(st + (r * APAD + kc) * 4,
                           Abase + (size_t)r * K + k0 + kc);
                cp_async16(st + (ATILE + r * APAD + kc) * 4,
                           Bbase + (size_t)r * K + k0 + kc);
            }
        }
        cp_commit();
    };

    float acc[4][8][4];
#pragma unroll
    for (int i = 0; i < 4; i++)
#pragma unroll
        for (int j = 0; j < 8; j++)
#pragma unroll
            for (int r = 0; r < 4; r++) acc[i][j][r] = 0.f;

    issue(0); issue(1); issue(2);

    uint32_t a[2][4][4], b[2][8][2];

    for (int i = 0; i < nk; i++) {
        cp_wait2();
        __syncthreads();
        issue(i + 3);

        const uint32_t* Au = smw + (i & (NSTAGE - 1)) * STW;
        const uint32_t* Bu = Au + ATILE;

        // load ks=0 fragments
        {
            const int k0 = tg;
#pragma unroll
            for (int ii = 0; ii < 4; ii++) {
                const uint32_t* p0 = Au + (warp_m + 16 * ii + grp) * APAD;
                a[0][ii][0] = p0[k0];
                a[0][ii][2] = p0[k0 + 4];
                const uint32_t* p1 = p0 + 8 * APAD;
                a[0][ii][1] = p1[k0];
                a[0][ii][3] = p1[k0 + 4];
            }
#pragma unroll
            for (int jj = 0; jj < 8; jj++) {
                const uint32_t* pn = Bu + (warp_n + 8 * jj + grp) * APAD;
                b[0][jj][0] = pn[k0];
                b[0][jj][1] = pn[k0 + 4];
            }
        }
#pragma unroll
        for (int ks = 0; ks < 2; ks++) {
            if (ks == 0) {      // prefetch ks=1 fragments under ks=0 mma
                const int k0 = 8 + tg;
#pragma unroll
                for (int ii = 0; ii < 4; ii++) {
                    const uint32_t* p0 = Au + (warp_m + 16 * ii + grp) * APAD;
                    a[1][ii][0] = p0[k0];
                    a[1][ii][2] = p0[k0 + 4];
                    const uint32_t* p1 = p0 + 8 * APAD;
                    a[1][ii][1] = p1[k0];
                    a[1][ii][3] = p1[k0 + 4];
                }
#pragma unroll
                for (int jj = 0; jj < 8; jj++) {
                    const uint32_t* pn = Bu + (warp_n + 8 * jj + grp) * APAD;
                    b[1][jj][0] = pn[k0];
                    b[1][jj][1] = pn[k0 + 4];
                }
            }
#pragma unroll
            for (int ii = 0; ii < 4; ii++)
#pragma unroll
                for (int jj = 0; jj < 8; jj++)
                    mma_tf32(acc[ii][jj], a[ks][ii], b[ks][jj]);
        }
    }

    // ---- epilogue
    const int region = fuse_qk ? (n0 >> 10) : 2;   // 0=Q, 1=K, else plain
    if (region <= 1) {
        // stage acc+bias to smem (pipeline buffers dead after this barrier)
        __syncthreads();
        float* S = (float*)smw;
#pragma unroll
        for (int ii = 0; ii < 4; ii++) {
            const int mm = warp_m + 16 * ii + grp;
#pragma unroll
            for (int jj = 0; jj < 8; jj++) {
                const int nn = warp_n + 8 * jj + 2 * tg;
                const float bv0 = __ldg(&bias[n0 + nn]);
                const float bv1 = __ldg(&bias[n0 + nn + 1]);
                S[mm * SPAD + nn]           = acc[ii][jj][0] + bv0;
                S[mm * SPAD + nn + 1]       = acc[ii][jj][1] + bv1;
                S[(mm + 8) * SPAD + nn]     = acc[ii][jj][2] + bv0;
                S[(mm + 8) * SPAD + nn + 1] = acc[ii][jj][3] + bv1;
            }
        }
        __syncthreads();
        // coalesced write: one (row, head-half) per warp-iteration;
        // 32 lanes cover 64 contiguous halves (4B/lane -> 128B/warp/store)
        const int hh0 = (n0 & 1023) >> 6;        // first head in this tile
        __half* hi = (region == 0) ? qh : kh;
        __half* lo = (region == 0) ? ql : kl;
        for (int it = wid; it < 256; it += 4) {
            const int mm = it >> 1, hf = it & 1;
            const int m = m0 + mm;
            const int bi = m >> 11, ti = m & (T_ - 1);
            const size_t o = ((size_t)(bi * 16 + hh0 + hf) * T_ + ti) * 64 + 2 * lane;
            const float x = S[mm * SPAD + hf * 64 + 2 * lane];
            const float y = S[mm * SPAD + hf * 64 + 2 * lane + 1];
            split_store2(x, y, hi, lo, o);
        }
    } else {
#pragma unroll
        for (int ii = 0; ii < 4; ii++) {
            const int m = m0 + warp_m + 16 * ii + grp;
#pragma unroll
            for (int jj = 0; jj < 8; jj++) {
                const int n = n0 + warp_n + 8 * jj + 2 * tg;
                const float bv0 = __ldg(&bias[n]);
                const float bv1 = __ldg(&bias[n + 1]);
                float2 v0 = {acc[ii][jj][0] + bv0, acc[ii][jj][1] + bv1};
                float2 v1 = {acc[ii][jj][2] + bv0, acc[ii][jj][3] + bv1};
                *(float2*)(C + (size_t)m * N + n)       = v0;
                *(float2*)(C + (size_t)(m + 8) * N + n) = v1;
            }
        }
    }
}

// ---------------------------------------------------------------------------
// V transpose + split: g_qkv V part -> [bh][d][t] hi/lo halfs
// ---------------------------------------------------------------------------
__global__ __launch_bounds__(256)
void convert_vt_kernel(const float* __restrict__ qkv,
                       __half* __restrict__ vh, __half* __restrict__ vl)
{
    __shared__ float tile[32][33];
    int t0 = blockIdx.x * 32;
    int d0 = blockIdx.y * 32;
    int bh = blockIdx.z;
    int b = bh >> 4, h = bh & 15;
    int tx = threadIdx.x & 31, ty = threadIdx.x >> 5;
#pragma unroll
    for (int j = 0; j < 32; j += 8)
        tile[ty + j][tx] = qkv[((size_t)(b * T_ + t0 + ty + j)) * 3 * D_
                               + 2 * D_ + h * 64 + d0 + tx];
    __syncthreads();
#pragma unroll
    for (int j = 0; j < 32; j += 8) {
        int d = d0 + ty + j;
        float v = tile[tx][ty + j];
        __half hv = __float2half_rn(v);
        __half lv = __float2half_rn(v - __half2float(hv));
        size_t o = ((size_t)bh * DK_ + d) * T_ + t0 + tx;
        vh[o] = hv;
        vl[o] = lv;
    }
}

// ---------------------------------------------------------------------------
// Flash attention on fp16 tensor cores with hi/lo split (round-6 proven).
// ---------------------------------------------------------------------------
#define AW   36
#define KVW  (64 * AW)
#define BUFW (4 * KVW)
#define ATT_SMEM (2 * BUFW * 4)

__global__ __launch_bounds__(256, 2)
void flash_mma_kernel(const __half* __restrict__ qh_g, const __half* __restrict__ ql_g,
                      const __half* __restrict__ kh_g, const __half* __restrict__ kl_g,
                      const __half* __restrict__ vh_g, const __half* __restrict__ vl_g,
                      float* __restrict__ out)
{
    extern __shared__ uint32_t smw[];
    const uint32_t sbase = smem_u32(smw);
    const int tid = threadIdx.x, wid = tid >> 5, lane = tid & 31;
    const int grp = lane >> 2, tg = lane & 3;
    const int bh = blockIdx.y, b = bh >> 4, h = bh & 15;
    const int qt = gridDim.x - 1 - blockIdx.x;
    const int q0 = qt * 128;
    const int wm = wid * 16;
    const int row0 = q0 + wm + grp;
    const int row1 = row0 + 8;

    {
        const uint4* qh4 = (const uint4*)(qh_g + (size_t)bh * T_ * DK_) + q0 * 8;
        const uint4* ql4 = (const uint4*)(ql_g + (size_t)bh * T_ * DK_) + q0 * 8;
#pragma unroll
        for (int j = 0; j < 4; j++) {
            int idx = tid + j * 256;
            int r = idx >> 3, c = idx & 7;
            uint32_t dst = sbase + (r * AW + c * 4) * 4;
            cp_async16(dst, qh4 + r * 8 + c);
            cp_async16(dst + 4608 * 4, ql4 + r * 8 + c);
        }
        cp_commit(); cp_wait0();
        __syncthreads();
    }
    uint32_t qfh[4][4], qfl[4][4];
    {
        const uint32_t* Q = smw;
        const int base = (wm + grp) * AW + tg;
#pragma unroll
        for (int kc = 0; kc < 4; kc++) {
            qfh[kc][0] = Q[base + 8 * kc];
            qfh[kc][1] = Q[base + 8 * AW + 8 * kc];
            qfh[kc][2] = Q[base + 8 * kc + 4];
            qfh[kc][3] = Q[base + 8 * AW + 8 * kc + 4];
            qfl[kc][0] = Q[4608 + base + 8 * kc];
            qfl[kc][1] = Q[4608 + base + 8 * AW + 8 * kc];
            qfl[kc][2] = Q[4608 + base + 8 * kc + 4];
            qfl[kc][3] = Q[4608 + base + 8 * AW + 8 * kc + 4];
        }
    }
    __syncthreads();

    const uint4* kh4 = (const uint4*)(kh_g + (size_t)bh * T_ * DK_);
    const uint4* kl4 = (const uint4*)(kl_g + (size_t)bh * T_ * DK_);
    const uint4* vh4 = (const uint4*)(vh_g + (size_t)bh * DK_ * T_);
    const uint4* vl4 = (const uint4*)(vl_g + (size_t)bh * DK_ * T_);

    auto kv_load = [&](int t, int buf) {
        const int kv0 = t * 64;
#pragma unroll
        for (int j = 0; j < 2; j++) {
            int idx = tid + j * 256;
            int r = idx >> 3, c = idx & 7;
            uint32_t dst = sbase + (buf * BUFW + r * AW + c * 4) * 4;
            cp_async16(dst,               kh4 + (kv0 + r) * 8 + c);
            cp_async16(dst + KVW * 4,     kl4 + (kv0 + r) * 8 + c);
            cp_async16(dst + 2 * KVW * 4, vh4 + (size_t)r * (T_ / 8) + kv0 / 8 + c);
            cp_async16(dst + 3 * KVW * 4, vl4 + (size_t)r * (T_ / 8) + kv0 / 8 + c);
        }
    };

    float o[8][4];
#pragma unroll
    for (int j = 0; j < 8; j++)
#pragma unroll
        for (int e = 0; e < 4; e++) o[j][e] = 0.f;
    float m0 = -1e30f, m1 = -1e30f, l0 = 0.f, l1 = 0.f;

    const int nt = 2 * (qt + 1);
    kv_load(0, 0); cp_commit();

    for (int t = 0; t < nt; t++) {
        if (t + 1 < nt) { kv_load(t + 1, (t + 1) & 1); cp_commit(); cp_wait1(); }
        else           { cp_wait0(); }
        __syncthreads();

        const uint32_t* Kh = smw + (t & 1) * BUFW;
        const uint32_t* Kl = Kh + KVW;
        const uint32_t* Vh = Kh + 2 * KVW;
        const uint32_t* Vl = Kh + 3 * KVW;

        float s[8][4];
#pragma unroll
        for (int j = 0; j < 8; j++)
#pragma unroll
            for (int e = 0; e < 4; e++) s[j][e] = 0.f;
#pragma unroll
        for (int kc = 0; kc < 4; kc++) {
            const int bo = 8 * kc + tg;
#pragma unroll
            for (int j = 0; j < 8; j++) {
                const int nb = (8 * j + grp) * AW + bo;
                uint32_t b0h = Kh[nb], b1h = Kh[nb + 4];
                uint32_t b0l = Kl[nb], b1l = Kl[nb + 4];
                mma16816(s[j], qfh[kc][0], qfh[kc][1], qfh[kc][2], qfh[kc][3], b0h, b1h);
                mma16816(s[j], qfl[kc][0], qfl[kc][1], qfl[kc][2], qfl[kc][3], b0h, b1h);
                mma16816(s[j], qfh[kc][0], qfh[kc][1], qfh[kc][2], qfh[kc][3], b0l, b1l);
            }
        }

        const int kv0 = t * 64;
        const float cs = 0.125f * 1.4426950408889634f;
        const bool maskw = (kv0 + 63 > q0 + wm);
        float mx0 = -1e30f, mx1 = -1e30f;
#pragma unroll
        for (int j = 0; j < 8; j++) {
            const int c0 = kv0 + 8 * j + 2 * tg;
            float x0 = s[j][0] * cs, x1 = s[j][1] * cs;
            float x2 = s[j][2] * cs, x3 = s[j][3] * cs;
            if (maskw) {
                if (c0 > row0)     x0 = -1e30f;
                if (c0 + 1 > row0) x1 = -1e30f;
                if (c0 > row1)     x2 = -1e30f;
                if (c0 + 1 > row1) x3 = -1e30f;
            }
            s[j][0] = x0; s[j][1] = x1; s[j][2] = x2; s[j][3] = x3;
            mx0 = fmaxf(mx0, fmaxf(x0, x1));
            mx1 = fmaxf(mx1, fmaxf(x2, x3));
        }
        mx0 = fmaxf(mx0, __shfl_xor_sync(0xffffffffu, mx0, 1));
        mx0 = fmaxf(mx0, __shfl_xor_sync(0xffffffffu, mx0, 2));
        mx1 = fmaxf(mx1, __shfl_xor_sync(0xffffffffu, mx1, 1));
        mx1 = fmaxf(mx1, __shfl_xor_sync(0xffffffffu, mx1, 2));
        const float mn0 = fmaxf(m0, mx0), mn1 = fmaxf(m1, mx1);
        const float a0 = ex2f(m0 - mn0),  a1 = ex2f(m1 - mn1);
        m0 = mn0; m1 = mn1;

        float sum0 = 0.f, sum1 = 0.f;
#pragma unroll
        for (int j = 0; j < 8; j++) {
            float p0 = ex2f(s[j][0] - m0), p1 = ex2f(s[j][1] - m0);
            float p2 = ex2f(s[j][2] - m1), p3 = ex2f(s[j][3] - m1);
            s[j][0] = p0; s[j][1] = p1; s[j][2] = p2; s[j][3] = p3;
            sum0 += p0 + p1; sum1 += p2 + p3;
        }
        sum0 += __shfl_xor_sync(0xffffffffu, sum0, 1);
        sum0 += __shfl_xor_sync(0xffffffffu, sum0, 2);
        sum1 += __shfl_xor_sync(0xffffffffu, sum1, 1);
        sum1 += __shfl_xor_sync(0xffffffffu, sum1, 2);
        l0 = l0 * a0 + sum0;
        l1 = l1 * a1 + sum1;
#pragma unroll
        for (int j = 0; j < 8; j++) {
            o[j][0] *= a0; o[j][1] *= a0; o[j][2] *= a1; o[j][3] *= a1;
        }

#pragma unroll
        for (int kc = 0; kc < 4; kc++) {
            const int j0 = 2 * kc, j1 = 2 * kc + 1;
            __half2 A0 = __floats2half2_rn(s[j0][0], s[j0][1]);
            __half2 A1 = __floats2half2_rn(s[j0][2], s[j0][3]);
            __half2 A2 = __floats2half2_rn(s[j1][0], s[j1][1]);
            __half2 A3 = __floats2half2_rn(s[j1][2], s[j1][3]);
            float2 f0 = __half22float2(A0), f1 = __half22float2(A1);
            float2 f2 = __half22float2(A2), f3 = __half22float2(A3);
            __half2 L0 = __floats2half2_rn(s[j0][0] - f0.x, s[j0][1] - f0.y);
            __half2 L1 = __floats2half2_rn(s[j0][2] - f1.x, s[j0][3] - f1.y);
            __half2 L2 = __floats2half2_rn(s[j1][0] - f2.x, s[j1][1] - f2.y);
            __half2 L3 = __floats2half2_rn(s[j1][2] - f3.x, s[j1][3] - f3.y);
            const uint32_t ph0 = *(uint32_t*)&A0, ph1 = *(uint32_t*)&A1;
            const uint32_t ph2 = *(uint32_t*)&A2, ph3 = *(uint32_t*)&A3;
            const uint32_t pl0 = *(uint32_t*)&L0, pl1 = *(uint32_t*)&L1;
            const uint32_t pl2 = *(uint32_t*)&L2, pl3 = *(uint32_t*)&L3;
            const int bo = 8 * kc + tg;
#pragma unroll
            for (int jj = 0; jj < 8; jj++) {
                const int nb = (8 * jj + grp) * AW + bo;
                uint32_t v0h = Vh[nb], v1h = Vh[nb + 4];
                uint32_t v0l = Vl[nb], v1l = Vl[nb + 4];
                mma16816(o[jj], ph0, ph1, ph2, ph3, v0h, v1h);
                mma16816(o[jj], pl0, pl1, pl2, pl3, v0h, v1h);
                mma16816(o[jj], ph0, ph1, ph2, ph3, v0l, v1l);
            }
        }
        __syncthreads();
    }

    const float i0 = 1.0f / l0, i1 = 1.0f / l1;
    float* out0 = out + ((size_t)(b * T_ + row0)) * D_ + h * 64 + 2 * tg;
    float* out1 = out + ((size_t)(b * T_ + row1)) * D_ + h * 64 + 2 * tg;
#pragma unroll
    for (int jj = 0; jj < 8; jj++) {
        float2 v0 = {rna_tf32(o[jj][0] * i0), rna_tf32(o[jj][1] * i0)};
        float2 v1 = {rna_tf32(o[jj][2] * i1), rna_tf32(o[jj][3] * i1)};
        *(float2*)(out0 + 8 * jj) = v0;
        *(float2*)(out1 + 8 * jj) = v1;
    }
}

// ---------------------------------------------------------------------------
extern "C" void kernel_launch(void* const* d_in, const int* in_sizes, int n_in,
                              void* d_out, int out_size)
{
    (void)in_sizes; (void)n_in; (void)out_size;
    const float* x     = (const float*)d_in[0];
    const float* W_qkv = (const float*)d_in[1];
    const float* b_qkv = (const float*)d_in[2];
    const float* W_out = (const float*)d_in[3];
    const float* b_out = (const float*)d_in[4];
    float* out = (float*)d_out;

    float *xt_ptr, *qkv_ptr, *att_ptr, *wqkvt_ptr, *woutt_ptr;
    cudaGetSymbolAddress((void**)&xt_ptr,    g_x_t32);
    cudaGetSymbolAddress((void**)&qkv_ptr,   g_qkv);
    cudaGetSymbolAddress((void**)&att_ptr,   g_att);
    cudaGetSymbolAddress((void**)&wqkvt_ptr, g_wqkv_t);
    cudaGetSymbolAddress((void**)&woutt_ptr, g_wout_t);
    __half *qh, *ql, *kh, *kl, *vh, *vl;
    cudaGetSymbolAddress((void**)&qh, g_q_hi);
    cudaGetSymbolAddress((void**)&ql, g_q_lo);
    cudaGetSymbolAddress((void**)&kh, g_k_hi);
    cudaGetSymbolAddress((void**)&kl, g_k_lo);
    cudaGetSymbolAddress((void**)&vh, g_vt_hi);
    cudaGetSymbolAddress((void**)&vl, g_vt_lo);

    cudaFuncSetAttribute(gemm_tf32_kernel,
                         cudaFuncAttributeMaxDynamicSharedMemorySize, GEMM_SMEM);
    cudaFuncSetAttribute(flash_mma_kernel,
                         cudaFuncAttributeMaxDynamicSharedMemorySize, ATT_SMEM);

    // 0) Pre-round operands to tf32: weights (during transpose) + x
    transpose_kernel<<<dim3(3 * D_ / 32, D_ / 32), 256>>>(W_qkv, wqkvt_ptr, D_, 3 * D_);
    transpose_kernel<<<dim3(D_ / 32, D_ / 32), 256>>>(W_out, woutt_ptr, D_, D_);
    cvt_tf32_kernel<<<(M_ * D_ / 4) / 256, 256>>>((const float4*)x, (float4*)xt_ptr);

    // 1) QKV projection (round-6 mainloop) + coalesced fused Q/K epilogue
    gemm_tf32_kernel<<<dim3(3 * D_ / 128, M_ / 128), 128, GEMM_SMEM>>>(
        xt_ptr, wqkvt_ptr, b_qkv, qkv_ptr, M_, 3 * D_, D_,
        1, qh, ql, kh, kl);

    // 2) V transpose + split (reads V region of g_qkv)
    convert_vt_kernel<<<dim3(T_ / 32, DK_ / 32, BH_), 256>>>(qkv_ptr, vh, vl);

    // 3) Causal attention (fp16 mma, split-3x accuracy)
    flash_mma_kernel<<<dim3(T_ / 128, BH_), 256, ATT_SMEM>>>(
        qh, ql, kh, kl, vh, vl, att_ptr);

    // 4) Output projection (plain epilogue)
    gemm_tf32_kernel<<<dim3(D_ / 128, M_ / 128), 128, GEMM_SMEM>>>(
        att_ptr, woutt_ptr, b_out, out, M_, D_, D_,
        0, nullptr, nullptr, nullptr, nullptr);
}

// round 12
// speedup vs baseline: 1.1573x; 1.0203x over previous
#include <cuda_runtime.h>
#include <cuda_fp16.h>
#include <cstdint>

#define B_  4
#define T_  2048
#define D_  1024
#define H_  16
#define DK_ 64
#define M_  (B_*T_)
#define BH_ (B_*H_)

// Scratch (allocation-free rule: module-scope device globals)
__device__ float g_x_t32[(size_t)M_ * D_];       // x pre-rounded to tf32
__device__ float g_qkv[(size_t)M_ * 3 * D_];     // [B,T,3D]
__device__ float g_att[(size_t)M_ * D_];         // [B,T,D] (tf32-rounded values)
__device__ float g_wqkv_t[(size_t)3 * D_ * D_];  // W_qkv^T [3D, D] tf32-rounded
__device__ float g_wout_t[(size_t)D_ * D_];      // W_out^T [D, D] tf32-rounded
// half hi/lo splits for attention
__device__ __half g_q_hi[(size_t)BH_ * T_ * DK_];
__device__ __half g_q_lo[(size_t)BH_ * T_ * DK_];
__device__ __half g_k_hi[(size_t)BH_ * T_ * DK_];
__device__ __half g_k_lo[(size_t)BH_ * T_ * DK_];
__device__ __half g_vt_hi[(size_t)BH_ * DK_ * T_];  // [bh][d][t]
__device__ __half g_vt_lo[(size_t)BH_ * DK_ * T_];

// ---------------------------------------------------------------------------
// PTX helpers
// ---------------------------------------------------------------------------
__device__ __forceinline__ uint32_t smem_u32(const void* p) {
    uint32_t a;
    asm("{ .reg .u64 t; cvta.to.shared.u64 t, %1; cvt.u32.u64 %0, t; }"
        : "=r"(a) : "l"(p));
    return a;
}
__device__ __forceinline__ void cp_async16(uint32_t dst, const void* src) {
    asm volatile("cp.async.ca.shared.global [%0], [%1], 16;"
                 :: "r"(dst), "l"(src) : "memory");
}
__device__ __forceinline__ void cp_commit() {
    asm volatile("cp.async.commit_group;" ::: "memory");
}
__device__ __forceinline__ void cp_wait0() {
    asm volatile("cp.async.wait_group 0;" ::: "memory");
}
__device__ __forceinline__ void cp_wait1() {
    asm volatile("cp.async.wait_group 1;" ::: "memory");
}
__device__ __forceinline__ void cp_wait2() {
    asm volatile("cp.async.wait_group 2;" ::: "memory");
}
__device__ __forceinline__ float ex2f(float x) {
    float y;
    asm("ex2.approx.f32 %0, %1;" : "=f"(y) : "f"(x));
    return y;
}
__device__ __forceinline__ float rna_tf32(float x) {
    uint32_t r;
    asm("cvt.rna.tf32.f32 %0, %1;" : "=r"(r) : "f"(x));
    return __uint_as_float(r);
}
__device__ __forceinline__ void cvt4_rna(uint32_t (&o)[4], float4 v) {
    asm("cvt.rna.tf32.f32 %0, %1;" : "=r"(o[0]) : "f"(v.x));
    asm("cvt.rna.tf32.f32 %0, %1;" : "=r"(o[1]) : "f"(v.y));
    asm("cvt.rna.tf32.f32 %0, %1;" : "=r"(o[2]) : "f"(v.z));
    asm("cvt.rna.tf32.f32 %0, %1;" : "=r"(o[3]) : "f"(v.w));
}
__device__ __forceinline__ void mma16816(float (&c)[4], uint32_t a0, uint32_t a1,
                                         uint32_t a2, uint32_t a3,
                                         uint32_t b0, uint32_t b1) {
    asm volatile(
        "mma.sync.aligned.m16n8k16.row.col.f32.f16.f16.f32 "
        "{%0,%1,%2,%3}, {%4,%5,%6,%7}, {%8,%9}, {%0,%1,%2,%3};"
        : "+f"(c[0]), "+f"(c[1]), "+f"(c[2]), "+f"(c[3])
        : "r"(a0), "r"(a1), "r"(a2), "r"(a3), "r"(b0), "r"(b1));
}
__device__ __forceinline__ void mma_tf32(float (&c)[4], const uint32_t (&a)[4],
                                         const uint32_t (&b)[2]) {
    asm volatile(
        "mma.sync.aligned.m16n8k8.row.col.f32.tf32.tf32.f32 "
        "{%0,%1,%2,%3}, {%4,%5,%6,%7}, {%8,%9}, {%0,%1,%2,%3};"
        : "+f"(c[0]), "+f"(c[1]), "+f"(c[2]), "+f"(c[3])
        : "r"(a[0]), "r"(a[1]), "r"(a[2]), "r"(a[3]), "r"(b[0]), "r"(b[1]));
}

// split one float4 into half hi/lo pairs and store
__device__ __forceinline__ void split_store4(float4 v, __half* hi, __half* lo,
                                             size_t o) {
    __half2 h0 = __floats2half2_rn(v.x, v.y);
    __half2 h1 = __floats2half2_rn(v.z, v.w);
    float2 f0 = __half22float2(h0), f1 = __half22float2(h1);
    __half2 l0 = __floats2half2_rn(v.x - f0.x, v.y - f0.y);
    __half2 l1 = __floats2half2_rn(v.z - f1.x, v.w - f1.y);
    *(__half2*)(hi + o)     = h0;
    *(__half2*)(hi + o + 2) = h1;
    *(__half2*)(lo + o)     = l0;
    *(__half2*)(lo + o + 2) = l1;
}

// ---------------------------------------------------------------------------
// Merged prologue: W_qkv transpose+round | W_out transpose+round | x round.
// Dispatch by blockIdx.x range. 256 threads everywhere.
//   [0, 3072)        : W_qkv^T tile (96 x 32 tiles of 32x32)
//   [3072, 4096)     : W_out^T tile (32 x 32 tiles)
//   [4096, 12288)    : x cvt (8192 blocks x 256 float4)
// ---------------------------------------------------------------------------
__global__ __launch_bounds__(256)
void prologue_kernel(const float* __restrict__ Wqkv, float* __restrict__ WqkvT,
                     const float* __restrict__ Wout, float* __restrict__ WoutT,
                     const float4* __restrict__ x, float4* __restrict__ xT)
{
    const int bid = blockIdx.x;
    const int tid = threadIdx.x;
    if (bid >= 4096) {
        const int i = (bid - 4096) * 256 + tid;
        uint32_t c4[4];
        cvt4_rna(c4, x[i]);
        xT[i] = *(float4*)c4;
        return;
    }
    __shared__ float t[32][33];
    const float* in;
    float* out;
    int bx, by, R, C;
    if (bid < 3072) {
        in = Wqkv; out = WqkvT; R = D_; C = 3 * D_;
        bx = (bid % 96) * 32; by = (bid / 96) * 32;
    } else {
        in = Wout; out = WoutT; R = D_; C = D_;
        const int t2 = bid - 3072;
        bx = (t2 % 32) * 32; by = (t2 / 32) * 32;
    }
    const int tx = tid & 31, ty = tid >> 5;
#pragma unroll
    for (int j = 0; j < 32; j += 8)
        t[ty + j][tx] = in[(size_t)(by + ty + j) * C + bx + tx];
    __syncthreads();
#pragma unroll
    for (int j = 0; j < 32; j += 8)
        out[(size_t)(bx + ty + j) * R + by + tx] = rna_tf32(t[tx][ty + j]);
}

// ---------------------------------------------------------------------------
// tf32 GEMM (round-6 exact): C[M,N] = A[M,K] @ Bt[N,K]^T + bias[N]
// CTA 128x128, 128 threads = 4 warps (2Mx2N), warp tile 64x64. BK=16.
// NSTAGE=4, per-chunk issue, cp_wait2, ONE barrier per chunk.
// ---------------------------------------------------------------------------
#define APAD   20
#define ATILE  (128 * APAD)
#define STW    (2 * ATILE)
#define NSTAGE 4
#define GEMM_SMEM (NSTAGE * STW * 4)    // 81920 B

__global__ __launch_bounds__(128, 2)
void gemm_tf32_kernel(const float* __restrict__ A,
                      const float* __restrict__ Bt,
                      const float* __restrict__ bias,
                      float* __restrict__ C,
                      int M, int N, int K)
{
    extern __shared__ uint32_t smw[];
    const uint32_t sbase = smem_u32(smw);
    const int tid  = threadIdx.x;
    const int wid  = tid >> 5;
    const int lane = tid & 31;
    const int grp  = lane >> 2;
    const int tg   = lane & 3;
    const int warp_m = (wid & 1) * 64;
    const int warp_n = (wid >> 1) * 64;
    const int m0 = blockIdx.y * 128;
    const int n0 = blockIdx.x * 128;
    const int nk = K >> 4;

    const float* Abase = A + (size_t)m0 * K;
    const float* Bbase = Bt + (size_t)n0 * K;

    auto issue = [&](int i) {
        if (i < nk) {
            const int k0 = i << 4;
            const uint32_t st = sbase + ((i & (NSTAGE - 1)) * STW) * 4;
#pragma unroll
            for (int j = 0; j < 4; j++) {
                const int idx = tid + j * 128;
                const int r = idx >> 2, kc = (idx & 3) << 2;
                cp_async16(st + (r * APAD + kc) * 4,
                           Abase + (size_t)r * K + k0 + kc);
                cp_async16(st + (ATILE + r * APAD + kc) * 4,
                           Bbase + (size_t)r * K + k0 + kc);
            }
        }
        cp_commit();
    };

    float acc[4][8][4];
#pragma unroll
    for (int i = 0; i < 4; i++)
#pragma unroll
        for (int j = 0; j < 8; j++)
#pragma unroll
            for (int r = 0; r < 4; r++) acc[i][j][r] = 0.f;

    issue(0); issue(1); issue(2);

    uint32_t a[2][4][4], b[2][8][2];

    for (int i = 0; i < nk; i++) {
        cp_wait2();
        __syncthreads();
        issue(i + 3);

        const uint32_t* Au = smw + (i & (NSTAGE - 1)) * STW;
        const uint32_t* Bu = Au + ATILE;

        {
            const int k0 = tg;
#pragma unroll
            for (int ii = 0; ii < 4; ii++) {
                const uint32_t* p0 = Au + (warp_m + 16 * ii + grp) * APAD;
                a[0][ii][0] = p0[k0];
                a[0][ii][2] = p0[k0 + 4];
                const uint32_t* p1 = p0 + 8 * APAD;
                a[0][ii][1] = p1[k0];
                a[0][ii][3] = p1[k0 + 4];
            }
#pragma unroll
            for (int jj = 0; jj < 8; jj++) {
                const uint32_t* pn = Bu + (warp_n + 8 * jj + grp) * APAD;
                b[0][jj][0] = pn[k0];
                b[0][jj][1] = pn[k0 + 4];
            }
        }
#pragma unroll
        for (int ks = 0; ks < 2; ks++) {
            if (ks == 0) {
                const int k0 = 8 + tg;
#pragma unroll
                for (int ii = 0; ii < 4; ii++) {
                    const uint32_t* p0 = Au + (warp_m + 16 * ii + grp) * APAD;
                    a[1][ii][0] = p0[k0];
                    a[1][ii][2] = p0[k0 + 4];
                    const uint32_t* p1 = p0 + 8 * APAD;
                    a[1][ii][1] = p1[k0];
                    a[1][ii][3] = p1[k0 + 4];
                }
#pragma unroll
                for (int jj = 0; jj < 8; jj++) {
                    const uint32_t* pn = Bu + (warp_n + 8 * jj + grp) * APAD;
                    b[1][jj][0] = pn[k0];
                    b[1][jj][1] = pn[k0 + 4];
                }
            }
#pragma unroll
            for (int ii = 0; ii < 4; ii++)
#pragma unroll
                for (int jj = 0; jj < 8; jj++)
                    mma_tf32(acc[ii][jj], a[ks][ii], b[ks][jj]);
        }
    }

#pragma unroll
    for (int ii = 0; ii < 4; ii++) {
        const int m = m0 + warp_m + 16 * ii + grp;
#pragma unroll
        for (int jj = 0; jj < 8; jj++) {
            const int n = n0 + warp_n + 8 * jj + 2 * tg;
            const float bv0 = __ldg(&bias[n]);
            const float bv1 = __ldg(&bias[n + 1]);
            float2 v0 = {acc[ii][jj][0] + bv0, acc[ii][jj][1] + bv1};
            float2 v1 = {acc[ii][jj][2] + bv0, acc[ii][jj][3] + bv1};
            *(float2*)(C + (size_t)m * N + n)       = v0;
            *(float2*)(C + (size_t)(m + 8) * N + n) = v1;
        }
    }
}

// ---------------------------------------------------------------------------
// Merged convert: Q/K split (blocks [0, 8192)) | V transpose+split (rest).
// ---------------------------------------------------------------------------
__global__ __launch_bounds__(256)
void convert_kernel(const float* __restrict__ qkv,
                    __half* __restrict__ qh, __half* __restrict__ ql,
                    __half* __restrict__ kh, __half* __restrict__ kl,
                    __half* __restrict__ vh, __half* __restrict__ vl)
{
    const int bid = blockIdx.x;
    const int tid = threadIdx.x;
    if (bid < 8192) {
        // Q/K split: [bh][t][64] hi/lo
        int i = bid * 256 + tid;
        int c4 = i & 15;
        int t  = (i >> 4) & (T_ - 1);
        int bh = i >> 15;
        int b = bh >> 4, h = bh & 15;
        const float4* src = (const float4*)(qkv + ((size_t)(b * T_ + t)) * 3 * D_);
        float4 q4 = src[h * 16 + c4];
        float4 k4 = src[256 + h * 16 + c4];
        size_t o = ((size_t)bh * T_ + t) * 64 + c4 * 4;
        split_store4(q4, qh, ql, o);
        split_store4(k4, kh, kl, o);
        return;
    }
    // V transpose+split: grid part maps to (t-tile, d-tile, bh)
    __shared__ float tile[32][33];
    const int vb = bid - 8192;              // 0 .. T_/32 * 2 * BH - 1
    const int t0 = (vb % (T_ / 32)) * 32;
    const int d0 = ((vb / (T_ / 32)) & 1) * 32;
    const int bh = vb / (T_ / 32) / 2;
    const int b = bh >> 4, h = bh & 15;
    const int tx = tid & 31, ty = tid >> 5;
#pragma unroll
    for (int j = 0; j < 32; j += 8)
        tile[ty + j][tx] = qkv[((size_t)(b * T_ + t0 + ty + j)) * 3 * D_
                               + 2 * D_ + h * 64 + d0 + tx];
    __syncthreads();
#pragma unroll
    for (int j = 0; j < 32; j += 8) {
        int d = d0 + ty + j;
        float v = tile[tx][ty + j];
        __half hv = __float2half_rn(v);
        __half lv = __float2half_rn(v - __half2float(hv));
        size_t o = ((size_t)bh * DK_ + d) * T_ + t0 + tx;
        vh[o] = hv;
        vl[o] = lv;
    }
}

// ---------------------------------------------------------------------------
// Flash attention on fp16 tensor cores with hi/lo split (round-6 proven).
// ---------------------------------------------------------------------------
#define AW   36
#define KVW  (64 * AW)
#define BUFW (4 * KVW)
#define ATT_SMEM (2 * BUFW * 4)

__global__ __launch_bounds__(256, 2)
void flash_mma_kernel(const __half* __restrict__ qh_g, const __half* __restrict__ ql_g,
                      const __half* __restrict__ kh_g, const __half* __restrict__ kl_g,
                      const __half* __restrict__ vh_g, const __half* __restrict__ vl_g,
                      float* __restrict__ out)
{
    extern __shared__ uint32_t smw[];
    const uint32_t sbase = smem_u32(smw);
    const int tid = threadIdx.x, wid = tid >> 5, lane = tid & 31;
    const int grp = lane >> 2, tg = lane & 3;
    const int bh = blockIdx.y, b = bh >> 4, h = bh & 15;
    const int qt = gridDim.x - 1 - blockIdx.x;
    const int q0 = qt * 128;
    const int wm = wid * 16;
    const int row0 = q0 + wm + grp;
    const int row1 = row0 + 8;

    {
        const uint4* qh4 = (const uint4*)(qh_g + (size_t)bh * T_ * DK_) + q0 * 8;
        const uint4* ql4 = (const uint4*)(ql_g + (size_t)bh * T_ * DK_) + q0 * 8;
#pragma unroll
        for (int j = 0; j < 4; j++) {
            int idx = tid + j * 256;
            int r = idx >> 3, c = idx & 7;
            uint32_t dst = sbase + (r * AW + c * 4) * 4;
            cp_async16(dst, qh4 + r * 8 + c);
            cp_async16(dst + 4608 * 4, ql4 + r * 8 + c);
        }
        cp_commit(); cp_wait0();
        __syncthreads();
    }
    uint32_t qfh[4][4], qfl[4][4];
    {
        const uint32_t* Q = smw;
        const int base = (wm + grp) * AW + tg;
#pragma unroll
        for (int kc = 0; kc < 4; kc++) {
            qfh[kc][0] = Q[base + 8 * kc];
            qfh[kc][1] = Q[base + 8 * AW + 8 * kc];
            qfh[kc][2] = Q[base + 8 * kc + 4];
            qfh[kc][3] = Q[base + 8 * AW + 8 * kc + 4];
            qfl[kc][0] = Q[4608 + base + 8 * kc];
            qfl[kc][1] = Q[4608 + base + 8 * AW + 8 * kc];
            qfl[kc][2] = Q[4608 + base + 8 * kc + 4];
            qfl[kc][3] = Q[4608 + base + 8 * AW + 8 * kc + 4];
        }
    }
    __syncthreads();

    const uint4* kh4 = (const uint4*)(kh_g + (size_t)bh * T_ * DK_);
    const uint4* kl4 = (const uint4*)(kl_g + (size_t)bh * T_ * DK_);
    const uint4* vh4 = (const uint4*)(vh_g + (size_t)bh * DK_ * T_);
    const uint4* vl4 = (const uint4*)(vl_g + (size_t)bh * DK_ * T_);

    auto kv_load = [&](int t, int buf) {
        const int kv0 = t * 64;
#pragma unroll
        for (int j = 0; j < 2; j++) {
            int idx = tid + j * 256;
            int r = idx >> 3, c = idx & 7;
            uint32_t dst = sbase + (buf * BUFW + r * AW + c * 4) * 4;
            cp_async16(dst,               kh4 + (kv0 + r) * 8 + c);
            cp_async16(dst + KVW * 4,     kl4 + (kv0 + r) * 8 + c);
            cp_async16(dst + 2 * KVW * 4, vh4 + (size_t)r * (T_ / 8) + kv0 / 8 + c);
            cp_async16(dst + 3 * KVW * 4, vl4 + (size_t)r * (T_ / 8) + kv0 / 8 + c);
        }
    };

    float o[8][4];
#pragma unroll
    for (int j = 0; j < 8; j++)
#pragma unroll
        for (int e = 0; e < 4; e++) o[j][e] = 0.f;
    float m0 = -1e30f, m1 = -1e30f, l0 = 0.f, l1 = 0.f;

    const int nt = 2 * (qt + 1);
    kv_load(0, 0); cp_commit();

    for (int t = 0; t < nt; t++) {
        if (t + 1 < nt) { kv_load(t + 1, (t + 1) & 1); cp_commit(); cp_wait1(); }
        else           { cp_wait0(); }
        __syncthreads();

        const uint32_t* Kh = smw + (t & 1) * BUFW;
        const uint32_t* Kl = Kh + KVW;
        const uint32_t* Vh = Kh + 2 * KVW;
        const uint32_t* Vl = Kh + 3 * KVW;

        float s[8][4];
#pragma unroll
        for (int j = 0; j < 8; j++)
#pragma unroll
            for (int e = 0; e < 4; e++) s[j][e] = 0.f;
#pragma unroll
        for (int kc = 0; kc < 4; kc++) {
            const int bo = 8 * kc + tg;
#pragma unroll
            for (int j = 0; j < 8; j++) {
                const int nb = (8 * j + grp) * AW + bo;
                uint32_t b0h = Kh[nb], b1h = Kh[nb + 4];
                uint32_t b0l = Kl[nb], b1l = Kl[nb + 4];
                mma16816(s[j], qfh[kc][0], qfh[kc][1], qfh[kc][2], qfh[kc][3], b0h, b1h);
                mma16816(s[j], qfl[kc][0], qfl[kc][1], qfl[kc][2], qfl[kc][3], b0h, b1h);
                mma16816(s[j], qfh[kc][0], qfh[kc][1], qfh[kc][2], qfh[kc][3], b0l, b1l);
            }
        }

        const int kv0 = t * 64;
        const float cs = 0.125f * 1.4426950408889634f;
        const bool maskw = (kv0 + 63 > q0 + wm);
        float mx0 = -1e30f, mx1 = -1e30f;
#pragma unroll
        for (int j = 0; j < 8; j++) {
            const int c0 = kv0 + 8 * j + 2 * tg;
            float x0 = s[j][0] * cs, x1 = s[j][1] * cs;
            float x2 = s[j][2] * cs, x3 = s[j][3] * cs;
            if (maskw) {
                if (c0 > row0)     x0 = -1e30f;
                if (c0 + 1 > row0) x1 = -1e30f;
                if (c0 > row1)     x2 = -1e30f;
                if (c0 + 1 > row1) x3 = -1e30f;
            }
            s[j][0] = x0; s[j][1] = x1; s[j][2] = x2; s[j][3] = x3;
            mx0 = fmaxf(mx0, fmaxf(x0, x1));
            mx1 = fmaxf(mx1, fmaxf(x2, x3));
        }
        mx0 = fmaxf(mx0, __shfl_xor_sync(0xffffffffu, mx0, 1));
        mx0 = fmaxf(mx0, __shfl_xor_sync(0xffffffffu, mx0, 2));
        mx1 = fmaxf(mx1, __shfl_xor_sync(0xffffffffu, mx1, 1));
        mx1 = fmaxf(mx1, __shfl_xor_sync(0xffffffffu, mx1, 2));
        const float mn0 = fmaxf(m0, mx0), mn1 = fmaxf(m1, mx1);
        const float a0 = ex2f(m0 - mn0),  a1 = ex2f(m1 - mn1);
        m0 = mn0; m1 = mn1;

        float sum0 = 0.f, sum1 = 0.f;
#pragma unroll
        for (int j = 0; j < 8; j++) {
            float p0 = ex2f(s[j][0] - m0), p1 = ex2f(s[j][1] - m0);
            float p2 = ex2f(s[j][2] - m1), p3 = ex2f(s[j][3] - m1);
            s[j][0] = p0; s[j][1] = p1; s[j][2] = p2; s[j][3] = p3;
            sum0 += p0 + p1; sum1 += p2 + p3;
        }
        sum0 += __shfl_xor_sync(0xffffffffu, sum0, 1);
        sum0 += __shfl_xor_sync(0xffffffffu, sum0, 2);
        sum1 += __shfl_xor_sync(0xffffffffu, sum1, 1);
        sum1 += __shfl_xor_sync(0xffffffffu, sum1, 2);
        l0 = l0 * a0 + sum0;
        l1 = l1 * a1 + sum1;
#pragma unroll
        for (int j = 0; j < 8; j++) {
            o[j][0] *= a0; o[j][1] *= a0; o[j][2] *= a1; o[j][3] *= a1;
        }

#pragma unroll
        for (int kc = 0; kc < 4; kc++) {
            const int j0 = 2 * kc, j1 = 2 * kc + 1;
            __half2 A0 = __floats2half2_rn(s[j0][0], s[j0][1]);
            __half2 A1 = __floats2half2_rn(s[j0][2], s[j0][3]);
            __half2 A2 = __floats2half2_rn(s[j1][0], s[j1][1]);
            __half2 A3 = __floats2half2_rn(s[j1][2], s[j1][3]);
            float2 f0 = __half22float2(A0), f1 = __half22float2(A1);
            float2 f2 = __half22float2(A2), f3 = __half22float2(A3);
            __half2 L0 = __floats2half2_rn(s[j0][0] - f0.x, s[j0][1] - f0.y);
            __half2 L1 = __floats2half2_rn(s[j0][2] - f1.x, s[j0][3] - f1.y);
            __half2 L2 = __floats2half2_rn(s[j1][0] - f2.x, s[j1][1] - f2.y);
            __half2 L3 = __floats2half2_rn(s[j1][2] - f3.x, s[j1][3] - f3.y);
            const uint32_t ph0 = *(uint32_t*)&A0, ph1 = *(uint32_t*)&A1;
            const uint32_t ph2 = *(uint32_t*)&A2, ph3 = *(uint32_t*)&A3;
            const uint32_t pl0 = *(uint32_t*)&L0, pl1 = *(uint32_t*)&L1;
            const uint32_t pl2 = *(uint32_t*)&L2, pl3 = *(uint32_t*)&L3;
            const int bo = 8 * kc + tg;
#pragma unroll
            for (int jj = 0; jj < 8; jj++) {
                const int nb = (8 * jj + grp) * AW + bo;
                uint32_t v0h = Vh[nb], v1h = Vh[nb + 4];
                uint32_t v0l = Vl[nb], v1l = Vl[nb + 4];
                mma16816(o[jj], ph0, ph1, ph2, ph3, v0h, v1h);
                mma16816(o[jj], pl0, pl1, pl2, pl3, v0h, v1h);
                mma16816(o[jj], ph0, ph1, ph2, ph3, v0l, v1l);
            }
        }
        __syncthreads();
    }

    const float i0 = 1.0f / l0, i1 = 1.0f / l1;
    float* out0 = out + ((size_t)(b * T_ + row0)) * D_ + h * 64 + 2 * tg;
    float* out1 = out + ((size_t)(b * T_ + row1)) * D_ + h * 64 + 2 * tg;
#pragma unroll
    for (int jj = 0; jj < 8; jj++) {
        float2 v0 = {rna_tf32(o[jj][0] * i0), rna_tf32(o[jj][1] * i0)};
        float2 v1 = {rna_tf32(o[jj][2] * i1), rna_tf32(o[jj][3] * i1)};
        *(float2*)(out0 + 8 * jj) = v0;
        *(float2*)(out1 + 8 * jj) = v1;
    }
}

// ---------------------------------------------------------------------------
extern "C" void kernel_launch(void* const* d_in, const int* in_sizes, int n_in,
                              void* d_out, int out_size)
{
    (void)in_sizes; (void)n_in; (void)out_size;
    const float* x     = (const float*)d_in[0];
    const float* W_qkv = (const float*)d_in[1];
    const float* b_qkv = (const float*)d_in[2];
    const float* W_out = (const float*)d_in[3];
    const float* b_out = (const float*)d_in[4];
    float* out = (float*)d_out;

    float *xt_ptr, *qkv_ptr, *att_ptr, *wqkvt_ptr, *woutt_ptr;
    cudaGetSymbolAddress((void**)&xt_ptr,    g_x_t32);
    cudaGetSymbolAddress((void**)&qkv_ptr,   g_qkv);
    cudaGetSymbolAddress((void**)&att_ptr,   g_att);
    cudaGetSymbolAddress((void**)&wqkvt_ptr, g_wqkv_t);
    cudaGetSymbolAddress((void**)&woutt_ptr, g_wout_t);
    __half *qh, *ql, *kh, *kl, *vh, *vl;
    cudaGetSymbolAddress((void**)&qh, g_q_hi);
    cudaGetSymbolAddress((void**)&ql, g_q_lo);
    cudaGetSymbolAddress((void**)&kh, g_k_hi);
    cudaGetSymbolAddress((void**)&kl, g_k_lo);
    cudaGetSymbolAddress((void**)&vh, g_vt_hi);
    cudaGetSymbolAddress((void**)&vl, g_vt_lo);

    cudaFuncSetAttribute(gemm_tf32_kernel,
                         cudaFuncAttributeMaxDynamicSharedMemorySize, GEMM_SMEM);
    cudaFuncSetAttribute(flash_mma_kernel,
                         cudaFuncAttributeMaxDynamicSharedMemorySize, ATT_SMEM);

    // 0) Merged prologue: transpose+round both weights, round x
    prologue_kernel<<<4096 + (M_ * D_ / 4) / 256, 256>>>(
        W_qkv, wqkvt_ptr, W_out, woutt_ptr, (const float4*)x, (float4*)xt_ptr);

    // 1) QKV projection (round-6 GEMM, plain epilogue)
    gemm_tf32_kernel<<<dim3(3 * D_ / 128, M_ / 128), 128, GEMM_SMEM>>>(
        xt_ptr, wqkvt_ptr, b_qkv, qkv_ptr, M_, 3 * D_, D_);

    // 2) Merged convert: Q/K split + V transpose/split
    convert_kernel<<<8192 + (T_ / 32) * 2 * BH_, 256>>>(
        qkv_ptr, qh, ql, kh, kl, vh, vl);

    // 3) Causal attention (fp16 mma, split-3x accuracy)
    flash_mma_kernel<<<dim3(T_ / 128, BH_), 256, ATT_SMEM>>>(
        qh, ql, kh, kl, vh, vl, att_ptr);

    // 4) Output projection (round-6 GEMM)
    gemm_tf32_kernel<<<dim3(D_ / 128, M_ / 128), 128, GEMM_SMEM>>>(
        att_ptr, woutt_ptr, b_out, out, M_, D_, D_);
}

// round 13
// speedup vs baseline: 1.2217x; 1.0557x over previous
#include <cuda_runtime.h>
#include <cuda_fp16.h>
#include <cstdint>

#define B_  4
#define T_  2048
#define D_  1024
#define H_  16
#define DK_ 64
#define M_  (B_*T_)
#define BH_ (B_*H_)

// Scratch (allocation-free rule: module-scope device globals)
__device__ float g_x_t32[(size_t)M_ * D_];       // x pre-rounded to tf32
__device__ float g_qkv[(size_t)M_ * 3 * D_];     // [B,T,3D]
__device__ float g_att[(size_t)M_ * D_];         // [B,T,D] (tf32-rounded values)
__device__ float g_wqkv_t[(size_t)3 * D_ * D_];  // W_qkv^T [3D, D] tf32-rounded
__device__ float g_wout_t[(size_t)D_ * D_];      // W_out^T [D, D] tf32-rounded
// half hi/lo splits for attention
__device__ __half g_q_hi[(size_t)BH_ * T_ * DK_];
__device__ __half g_q_lo[(size_t)BH_ * T_ * DK_];
__device__ __half g_k_hi[(size_t)BH_ * T_ * DK_];
__device__ __half g_k_lo[(size_t)BH_ * T_ * DK_];
__device__ __half g_vt_hi[(size_t)BH_ * DK_ * T_];  // [bh][d][t]
__device__ __half g_vt_lo[(size_t)BH_ * DK_ * T_];

// ---------------------------------------------------------------------------
// PTX helpers
// ---------------------------------------------------------------------------
__device__ __forceinline__ uint32_t smem_u32(const void* p) {
    uint32_t a;
    asm("{ .reg .u64 t; cvta.to.shared.u64 t, %1; cvt.u32.u64 %0, t; }"
        : "=r"(a) : "l"(p));
    return a;
}
__device__ __forceinline__ void cp_async16(uint32_t dst, const void* src) {
    asm volatile("cp.async.ca.shared.global [%0], [%1], 16;"
                 :: "r"(dst), "l"(src) : "memory");
}
__device__ __forceinline__ void cp_commit() {
    asm volatile("cp.async.commit_group;" ::: "memory");
}
__device__ __forceinline__ void cp_wait0() {
    asm volatile("cp.async.wait_group 0;" ::: "memory");
}
__device__ __forceinline__ void cp_wait1() {
    asm volatile("cp.async.wait_group 1;" ::: "memory");
}
__device__ __forceinline__ void cp_wait2() {
    asm volatile("cp.async.wait_group 2;" ::: "memory");
}
__device__ __forceinline__ float ex2f(float x) {
    float y;
    asm("ex2.approx.f32 %0, %1;" : "=f"(y) : "f"(x));
    return y;
}
__device__ __forceinline__ float rna_tf32(float x) {
    uint32_t r;
    asm("cvt.rna.tf32.f32 %0, %1;" : "=r"(r) : "f"(x));
    return __uint_as_float(r);
}
__device__ __forceinline__ void cvt4_rna(uint32_t (&o)[4], float4 v) {
    asm("cvt.rna.tf32.f32 %0, %1;" : "=r"(o[0]) : "f"(v.x));
    asm("cvt.rna.tf32.f32 %0, %1;" : "=r"(o[1]) : "f"(v.y));
    asm("cvt.rna.tf32.f32 %0, %1;" : "=r"(o[2]) : "f"(v.z));
    asm("cvt.rna.tf32.f32 %0, %1;" : "=r"(o[3]) : "f"(v.w));
}
__device__ __forceinline__ void mma16816(float (&c)[4], uint32_t a0, uint32_t a1,
                                         uint32_t a2, uint32_t a3,
                                         uint32_t b0, uint32_t b1) {
    asm volatile(
        "mma.sync.aligned.m16n8k16.row.col.f32.f16.f16.f32 "
        "{%0,%1,%2,%3}, {%4,%5,%6,%7}, {%8,%9}, {%0,%1,%2,%3};"
        : "+f"(c[0]), "+f"(c[1]), "+f"(c[2]), "+f"(c[3])
        : "r"(a0), "r"(a1), "r"(a2), "r"(a3), "r"(b0), "r"(b1));
}
__device__ __forceinline__ void mma_tf32(float (&c)[4], const uint32_t (&a)[4],
                                         const uint32_t (&b)[2]) {
    asm volatile(
        "mma.sync.aligned.m16n8k8.row.col.f32.tf32.tf32.f32 "
        "{%0,%1,%2,%3}, {%4,%5,%6,%7}, {%8,%9}, {%0,%1,%2,%3};"
        : "+f"(c[0]), "+f"(c[1]), "+f"(c[2]), "+f"(c[3])
        : "r"(a[0]), "r"(a[1]), "r"(a[2]), "r"(a[3]), "r"(b[0]), "r"(b[1]));
}

// split one float4 into half hi/lo pairs and store
__device__ __forceinline__ void split_store4(float4 v, __half* hi, __half* lo,
                                             size_t o) {
    __half2 h0 = __floats2half2_rn(v.x, v.y);
    __half2 h1 = __floats2half2_rn(v.z, v.w);
    float2 f0 = __half22float2(h0), f1 = __half22float2(h1);
    __half2 l0 = __floats2half2_rn(v.x - f0.x, v.y - f0.y);
    __half2 l1 = __floats2half2_rn(v.z - f1.x, v.w - f1.y);
    *(__half2*)(hi + o)     = h0;
    *(__half2*)(hi + o + 2) = h1;
    *(__half2*)(lo + o)     = l0;
    *(__half2*)(lo + o + 2) = l1;
}

// ---------------------------------------------------------------------------
// Merged prologue: W_qkv transpose+round | W_out transpose+round | x round.
// ---------------------------------------------------------------------------
__global__ __launch_bounds__(256)
void prologue_kernel(const float* __restrict__ Wqkv, float* __restrict__ WqkvT,
                     const float* __restrict__ Wout, float* __restrict__ WoutT,
                     const float4* __restrict__ x, float4* __restrict__ xT)
{
    const int bid = blockIdx.x;
    const int tid = threadIdx.x;
    if (bid >= 4096) {
        const int i = (bid - 4096) * 256 + tid;
        uint32_t c4[4];
        cvt4_rna(c4, x[i]);
        xT[i] = *(float4*)c4;
        return;
    }
    __shared__ float t[32][33];
    const float* in;
    float* out;
    int bx, by, R, C;
    if (bid < 3072) {
        in = Wqkv; out = WqkvT; R = D_; C = 3 * D_;
        bx = (bid % 96) * 32; by = (bid / 96) * 32;
    } else {
        in = Wout; out = WoutT; R = D_; C = D_;
        const int t2 = bid - 3072;
        bx = (t2 % 32) * 32; by = (t2 / 32) * 32;
    }
    const int tx = tid & 31, ty = tid >> 5;
#pragma unroll
    for (int j = 0; j < 32; j += 8)
        t[ty + j][tx] = in[(size_t)(by + ty + j) * C + bx + tx];
    __syncthreads();
#pragma unroll
    for (int j = 0; j < 32; j += 8)
        out[(size_t)(bx + ty + j) * R + by + tx] = rna_tf32(t[tx][ty + j]);
}

// ---------------------------------------------------------------------------
// tf32 GEMM (round-6 exact): C[M,N] = A[M,K] @ Bt[N,K]^T + bias[N]
// ---------------------------------------------------------------------------
#define APAD   20
#define ATILE  (128 * APAD)
#define STW    (2 * ATILE)
#define NSTAGE 4
#define GEMM_SMEM (NSTAGE * STW * 4)    // 81920 B

__global__ __launch_bounds__(128, 2)
void gemm_tf32_kernel(const float* __restrict__ A,
                      const float* __restrict__ Bt,
                      const float* __restrict__ bias,
                      float* __restrict__ C,
                      int M, int N, int K)
{
    extern __shared__ uint32_t smw[];
    const uint32_t sbase = smem_u32(smw);
    const int tid  = threadIdx.x;
    const int wid  = tid >> 5;
    const int lane = tid & 31;
    const int grp  = lane >> 2;
    const int tg   = lane & 3;
    const int warp_m = (wid & 1) * 64;
    const int warp_n = (wid >> 1) * 64;
    const int m0 = blockIdx.y * 128;
    const int n0 = blockIdx.x * 128;
    const int nk = K >> 4;

    const float* Abase = A + (size_t)m0 * K;
    const float* Bbase = Bt + (size_t)n0 * K;

    auto issue = [&](int i) {
        if (i < nk) {
            const int k0 = i << 4;
            const uint32_t st = sbase + ((i & (NSTAGE - 1)) * STW) * 4;
#pragma unroll
            for (int j = 0; j < 4; j++) {
                const int idx = tid + j * 128;
                const int r = idx >> 2, kc = (idx & 3) << 2;
                cp_async16(st + (r * APAD + kc) * 4,
                           Abase + (size_t)r * K + k0 + kc);
                cp_async16(st + (ATILE + r * APAD + kc) * 4,
                           Bbase + (size_t)r * K + k0 + kc);
            }
        }
        cp_commit();
    };

    float acc[4][8][4];
#pragma unroll
    for (int i = 0; i < 4; i++)
#pragma unroll
        for (int j = 0; j < 8; j++)
#pragma unroll
            for (int r = 0; r < 4; r++) acc[i][j][r] = 0.f;

    issue(0); issue(1); issue(2);

    uint32_t a[2][4][4], b[2][8][2];

    for (int i = 0; i < nk; i++) {
        cp_wait2();
        __syncthreads();
        issue(i + 3);

        const uint32_t* Au = smw + (i & (NSTAGE - 1)) * STW;
        const uint32_t* Bu = Au + ATILE;

        {
            const int k0 = tg;
#pragma unroll
            for (int ii = 0; ii < 4; ii++) {
                const uint32_t* p0 = Au + (warp_m + 16 * ii + grp) * APAD;
                a[0][ii][0] = p0[k0];
                a[0][ii][2] = p0[k0 + 4];
                const uint32_t* p1 = p0 + 8 * APAD;
                a[0][ii][1] = p1[k0];
                a[0][ii][3] = p1[k0 + 4];
            }
#pragma unroll
            for (int jj = 0; jj < 8; jj++) {
                const uint32_t* pn = Bu + (warp_n + 8 * jj + grp) * APAD;
                b[0][jj][0] = pn[k0];
                b[0][jj][1] = pn[k0 + 4];
            }
        }
#pragma unroll
        for (int ks = 0; ks < 2; ks++) {
            if (ks == 0) {
                const int k0 = 8 + tg;
#pragma unroll
                for (int ii = 0; ii < 4; ii++) {
                    const uint32_t* p0 = Au + (warp_m + 16 * ii + grp) * APAD;
                    a[1][ii][0] = p0[k0];
                    a[1][ii][2] = p0[k0 + 4];
                    const uint32_t* p1 = p0 + 8 * APAD;
                    a[1][ii][1] = p1[k0];
                    a[1][ii][3] = p1[k0 + 4];
                }
#pragma unroll
                for (int jj = 0; jj < 8; jj++) {
                    const uint32_t* pn = Bu + (warp_n + 8 * jj + grp) * APAD;
                    b[1][jj][0] = pn[k0];
                    b[1][jj][1] = pn[k0 + 4];
                }
            }
#pragma unroll
            for (int ii = 0; ii < 4; ii++)
#pragma unroll
                for (int jj = 0; jj < 8; jj++)
                    mma_tf32(acc[ii][jj], a[ks][ii], b[ks][jj]);
        }
    }

#pragma unroll
    for (int ii = 0; ii < 4; ii++) {
        const int m = m0 + warp_m + 16 * ii + grp;
#pragma unroll
        for (int jj = 0; jj < 8; jj++) {
            const int n = n0 + warp_n + 8 * jj + 2 * tg;
            const float bv0 = __ldg(&bias[n]);
            const float bv1 = __ldg(&bias[n + 1]);
            float2 v0 = {acc[ii][jj][0] + bv0, acc[ii][jj][1] + bv1};
            float2 v1 = {acc[ii][jj][2] + bv0, acc[ii][jj][3] + bv1};
            *(float2*)(C + (size_t)m * N + n)       = v0;
            *(float2*)(C + (size_t)(m + 8) * N + n) = v1;
        }
    }
}

// ---------------------------------------------------------------------------
// Merged convert: Q/K split (blocks [0, 8192)) | V transpose+split (rest).
// ---------------------------------------------------------------------------
__global__ __launch_bounds__(256)
void convert_kernel(const float* __restrict__ qkv,
                    __half* __restrict__ qh, __half* __restrict__ ql,
                    __half* __restrict__ kh, __half* __restrict__ kl,
                    __half* __restrict__ vh, __half* __restrict__ vl)
{
    const int bid = blockIdx.x;
    const int tid = threadIdx.x;
    if (bid < 8192) {
        int i = bid * 256 + tid;
        int c4 = i & 15;
        int t  = (i >> 4) & (T_ - 1);
        int bh = i >> 15;
        int b = bh >> 4, h = bh & 15;
        const float4* src = (const float4*)(qkv + ((size_t)(b * T_ + t)) * 3 * D_);
        float4 q4 = src[h * 16 + c4];
        float4 k4 = src[256 + h * 16 + c4];
        size_t o = ((size_t)bh * T_ + t) * 64 + c4 * 4;
        split_store4(q4, qh, ql, o);
        split_store4(k4, kh, kl, o);
        return;
    }
    __shared__ float tile[32][33];
    const int vb = bid - 8192;
    const int t0 = (vb % (T_ / 32)) * 32;
    const int d0 = ((vb / (T_ / 32)) & 1) * 32;
    const int bh = vb / (T_ / 32) / 2;
    const int b = bh >> 4, h = bh & 15;
    const int tx = tid & 31, ty = tid >> 5;
#pragma unroll
    for (int j = 0; j < 32; j += 8)
        tile[ty + j][tx] = qkv[((size_t)(b * T_ + t0 + ty + j)) * 3 * D_
                               + 2 * D_ + h * 64 + d0 + tx];
    __syncthreads();
#pragma unroll
    for (int j = 0; j < 32; j += 8) {
        int d = d0 + ty + j;
        float v = tile[tx][ty + j];
        __half hv = __float2half_rn(v);
        __half lv = __float2half_rn(v - __half2float(hv));
        size_t o = ((size_t)bh * DK_ + d) * T_ + t0 + tx;
        vh[o] = hv;
        vl[o] = lv;
    }
}

// ---------------------------------------------------------------------------
// Flash attention, fp16 mma. QK: 3-term hi/lo split (full accuracy).
// PV: 2-term (ph*vh + ph*vl) — drops the pl*vh correction (~2.4e-4 rms).
// KV ring: 3 buffers, prefetch distance 2, ONE barrier per kv tile.
// ---------------------------------------------------------------------------
#define AW   36
#define KVW  (64 * AW)
#define BUFW (4 * KVW)
#define ATT_SMEM (3 * BUFW * 4)          // 110592 B

__global__ __launch_bounds__(256, 2)
void flash_mma_kernel(const __half* __restrict__ qh_g, const __half* __restrict__ ql_g,
                      const __half* __restrict__ kh_g, const __half* __restrict__ kl_g,
                      const __half* __restrict__ vh_g, const __half* __restrict__ vl_g,
                      float* __restrict__ out)
{
    extern __shared__ uint32_t smw[];
    const uint32_t sbase = smem_u32(smw);
    const int tid = threadIdx.x, wid = tid >> 5, lane = tid & 31;
    const int grp = lane >> 2, tg = lane & 3;
    const int bh = blockIdx.y, b = bh >> 4, h = bh & 15;
    const int qt = gridDim.x - 1 - blockIdx.x;
    const int q0 = qt * 128;
    const int wm = wid * 16;
    const int row0 = q0 + wm + grp;
    const int row1 = row0 + 8;

    // stage Q (hi|lo) in buffer-0 region, lift fragments, then release
    {
        const uint4* qh4 = (const uint4*)(qh_g + (size_t)bh * T_ * DK_) + q0 * 8;
        const uint4* ql4 = (const uint4*)(ql_g + (size_t)bh * T_ * DK_) + q0 * 8;
#pragma unroll
        for (int j = 0; j < 4; j++) {
            int idx = tid + j * 256;
            int r = idx >> 3, c = idx & 7;
            uint32_t dst = sbase + (r * AW + c * 4) * 4;
            cp_async16(dst, qh4 + r * 8 + c);
            cp_async16(dst + 4608 * 4, ql4 + r * 8 + c);
        }
        cp_commit(); cp_wait0();
        __syncthreads();
    }
    uint32_t qfh[4][4], qfl[4][4];
    {
        const uint32_t* Q = smw;
        const int base = (wm + grp) * AW + tg;
#pragma unroll
        for (int kc = 0; kc < 4; kc++) {
            qfh[kc][0] = Q[base + 8 * kc];
            qfh[kc][1] = Q[base + 8 * AW + 8 * kc];
            qfh[kc][2] = Q[base + 8 * kc + 4];
            qfh[kc][3] = Q[base + 8 * AW + 8 * kc + 4];
            qfl[kc][0] = Q[4608 + base + 8 * kc];
            qfl[kc][1] = Q[4608 + base + 8 * AW + 8 * kc];
            qfl[kc][2] = Q[4608 + base + 8 * kc + 4];
            qfl[kc][3] = Q[4608 + base + 8 * AW + 8 * kc + 4];
        }
    }
    __syncthreads();    // Q staging region becomes KV buffer 0

    const uint4* kh4 = (const uint4*)(kh_g + (size_t)bh * T_ * DK_);
    const uint4* kl4 = (const uint4*)(kl_g + (size_t)bh * T_ * DK_);
    const uint4* vh4 = (const uint4*)(vh_g + (size_t)bh * DK_ * T_);
    const uint4* vl4 = (const uint4*)(vl_g + (size_t)bh * DK_ * T_);

    auto kv_load = [&](int t, int buf) {
        const int kv0 = t * 64;
#pragma unroll
        for (int j = 0; j < 2; j++) {
            int idx = tid + j * 256;
            int r = idx >> 3, c = idx & 7;
            uint32_t dst = sbase + (buf * BUFW + r * AW + c * 4) * 4;
            cp_async16(dst,               kh4 + (kv0 + r) * 8 + c);
            cp_async16(dst + KVW * 4,     kl4 + (kv0 + r) * 8 + c);
            cp_async16(dst + 2 * KVW * 4, vh4 + (size_t)r * (T_ / 8) + kv0 / 8 + c);
            cp_async16(dst + 3 * KVW * 4, vl4 + (size_t)r * (T_ / 8) + kv0 / 8 + c);
        }
    };

    float o[8][4];
#pragma unroll
    for (int j = 0; j < 8; j++)
#pragma unroll
        for (int e = 0; e < 4; e++) o[j][e] = 0.f;
    float m0 = -1e30f, m1 = -1e30f, l0 = 0.f, l1 = 0.f;

    const int nt = 2 * (qt + 1);
    kv_load(0, 0); cp_commit();
    kv_load(1, 1); cp_commit();

    int bc = 0, bn = 2;     // current buffer (tile t), next-load buffer (t+2)
    for (int t = 0; t < nt; t++) {
        cp_wait1();          // own copies of tile t complete (t+1 may pend)
        __syncthreads();     // publish copies; proves tile t-1 compute done
        if (t + 2 < nt) kv_load(t + 2, bn);   // overwrites tile t-1's buffer
        cp_commit();

        const uint32_t* Kh = smw + bc * BUFW;
        const uint32_t* Kl = Kh + KVW;
        const uint32_t* Vh = Kh + 2 * KVW;
        const uint32_t* Vl = Kh + 3 * KVW;

        // ---- S = Q K^T (3-term split, full accuracy)
        float s[8][4];
#pragma unroll
        for (int j = 0; j < 8; j++)
#pragma unroll
            for (int e = 0; e < 4; e++) s[j][e] = 0.f;
#pragma unroll
        for (int kc = 0; kc < 4; kc++) {
            const int bo = 8 * kc + tg;
#pragma unroll
            for (int j = 0; j < 8; j++) {
                const int nb = (8 * j + grp) * AW + bo;
                uint32_t b0h = Kh[nb], b1h = Kh[nb + 4];
                uint32_t b0l = Kl[nb], b1l = Kl[nb + 4];
                mma16816(s[j], qfh[kc][0], qfh[kc][1], qfh[kc][2], qfh[kc][3], b0h, b1h);
                mma16816(s[j], qfl[kc][0], qfl[kc][1], qfl[kc][2], qfl[kc][3], b0h, b1h);
                mma16816(s[j], qfh[kc][0], qfh[kc][1], qfh[kc][2], qfh[kc][3], b0l, b1l);
            }
        }

        // ---- online softmax (base-2)
        const int kv0 = t * 64;
        const float cs = 0.125f * 1.4426950408889634f;
        const bool maskw = (kv0 + 63 > q0 + wm);
        float mx0 = -1e30f, mx1 = -1e30f;
#pragma unroll
        for (int j = 0; j < 8; j++) {
            const int c0 = kv0 + 8 * j + 2 * tg;
            float x0 = s[j][0] * cs, x1 = s[j][1] * cs;
            float x2 = s[j][2] * cs, x3 = s[j][3] * cs;
            if (maskw) {
                if (c0 > row0)     x0 = -1e30f;
                if (c0 + 1 > row0) x1 = -1e30f;
                if (c0 > row1)     x2 = -1e30f;
                if (c0 + 1 > row1) x3 = -1e30f;
            }
            s[j][0] = x0; s[j][1] = x1; s[j][2] = x2; s[j][3] = x3;
            mx0 = fmaxf(mx0, fmaxf(x0, x1));
            mx1 = fmaxf(mx1, fmaxf(x2, x3));
        }
        mx0 = fmaxf(mx0, __shfl_xor_sync(0xffffffffu, mx0, 1));
        mx0 = fmaxf(mx0, __shfl_xor_sync(0xffffffffu, mx0, 2));
        mx1 = fmaxf(mx1, __shfl_xor_sync(0xffffffffu, mx1, 1));
        mx1 = fmaxf(mx1, __shfl_xor_sync(0xffffffffu, mx1, 2));
        const float mn0 = fmaxf(m0, mx0), mn1 = fmaxf(m1, mx1);
        const float a0 = ex2f(m0 - mn0),  a1 = ex2f(m1 - mn1);
        m0 = mn0; m1 = mn1;

        float sum0 = 0.f, sum1 = 0.f;
#pragma unroll
        for (int j = 0; j < 8; j++) {
            float p0 = ex2f(s[j][0] - m0), p1 = ex2f(s[j][1] - m0);
            float p2 = ex2f(s[j][2] - m1), p3 = ex2f(s[j][3] - m1);
            s[j][0] = p0; s[j][1] = p1; s[j][2] = p2; s[j][3] = p3;
            sum0 += p0 + p1; sum1 += p2 + p3;
        }
        sum0 += __shfl_xor_sync(0xffffffffu, sum0, 1);
        sum0 += __shfl_xor_sync(0xffffffffu, sum0, 2);
        sum1 += __shfl_xor_sync(0xffffffffu, sum1, 1);
        sum1 += __shfl_xor_sync(0xffffffffu, sum1, 2);
        l0 = l0 * a0 + sum0;
        l1 = l1 * a1 + sum1;
#pragma unroll
        for (int j = 0; j < 8; j++) {
            o[j][0] *= a0; o[j][1] *= a0; o[j][2] *= a1; o[j][3] *= a1;
        }

        // ---- O += P V (2-term: ph*vh + ph*vl; pl*vh dropped)
#pragma unroll
        for (int kc = 0; kc < 4; kc++) {
            const int j0 = 2 * kc, j1 = 2 * kc + 1;
            __half2 A0 = __floats2half2_rn(s[j0][0], s[j0][1]);
            __half2 A1 = __floats2half2_rn(s[j0][2], s[j0][3]);
            __half2 A2 = __floats2half2_rn(s[j1][0], s[j1][1]);
            __half2 A3 = __floats2half2_rn(s[j1][2], s[j1][3]);
            const uint32_t ph0 = *(uint32_t*)&A0, ph1 = *(uint32_t*)&A1;
            const uint32_t ph2 = *(uint32_t*)&A2, ph3 = *(uint32_t*)&A3;
            const int bo = 8 * kc + tg;
#pragma unroll
            for (int jj = 0; jj < 8; jj++) {
                const int nb = (8 * jj + grp) * AW + bo;
                uint32_t v0h = Vh[nb], v1h = Vh[nb + 4];
                uint32_t v0l = Vl[nb], v1l = Vl[nb + 4];
                mma16816(o[jj], ph0, ph1, ph2, ph3, v0h, v1h);
                mma16816(o[jj], ph0, ph1, ph2, ph3, v0l, v1l);
            }
        }

        bc = (bc == 2) ? 0 : bc + 1;
        bn = (bn == 2) ? 0 : bn + 1;
    }

    const float i0 = 1.0f / l0, i1 = 1.0f / l1;
    float* out0 = out + ((size_t)(b * T_ + row0)) * D_ + h * 64 + 2 * tg;
    float* out1 = out + ((size_t)(b * T_ + row1)) * D_ + h * 64 + 2 * tg;
#pragma unroll
    for (int jj = 0; jj < 8; jj++) {
        float2 v0 = {rna_tf32(o[jj][0] * i0), rna_tf32(o[jj][1] * i0)};
        float2 v1 = {rna_tf32(o[jj][2] * i1), rna_tf32(o[jj][3] * i1)};
        *(float2*)(out0 + 8 * jj) = v0;
        *(float2*)(out1 + 8 * jj) = v1;
    }
}

// ---------------------------------------------------------------------------
extern "C" void kernel_launch(void* const* d_in, const int* in_sizes, int n_in,
                              void* d_out, int out_size)
{
    (void)in_sizes; (void)n_in; (void)out_size;
    const float* x     = (const float*)d_in[0];
    const float* W_qkv = (const float*)d_in[1];
    const float* b_qkv = (const float*)d_in[2];
    const float* W_out = (const float*)d_in[3];
    const float* b_out = (const float*)d_in[4];
    float* out = (float*)d_out;

    float *xt_ptr, *qkv_ptr, *att_ptr, *wqkvt_ptr, *woutt_ptr;
    cudaGetSymbolAddress((void**)&xt_ptr,    g_x_t32);
    cudaGetSymbolAddress((void**)&qkv_ptr,   g_qkv);
    cudaGetSymbolAddress((void**)&att_ptr,   g_att);
    cudaGetSymbolAddress((void**)&wqkvt_ptr, g_wqkv_t);
    cudaGetSymbolAddress((void**)&woutt_ptr, g_wout_t);
    __half *qh, *ql, *kh, *kl, *vh, *vl;
    cudaGetSymbolAddress((void**)&qh, g_q_hi);
    cudaGetSymbolAddress((void**)&ql, g_q_lo);
    cudaGetSymbolAddress((void**)&kh, g_k_hi);
    cudaGetSymbolAddress((void**)&kl, g_k_lo);
    cudaGetSymbolAddress((void**)&vh, g_vt_hi);
    cudaGetSymbolAddress((void**)&vl, g_vt_lo);

    cudaFuncSetAttribute(gemm_tf32_kernel,
                         cudaFuncAttributeMaxDynamicSharedMemorySize, GEMM_SMEM);
    cudaFuncSetAttribute(flash_mma_kernel,
                         cudaFuncAttributeMaxDynamicSharedMemorySize, ATT_SMEM);

    // 0) Merged prologue
    prologue_kernel<<<4096 + (M_ * D_ / 4) / 256, 256>>>(
        W_qkv, wqkvt_ptr, W_out, woutt_ptr, (const float4*)x, (float4*)xt_ptr);

    // 1) QKV projection
    gemm_tf32_kernel<<<dim3(3 * D_ / 128, M_ / 128), 128, GEMM_SMEM>>>(
        xt_ptr, wqkvt_ptr, b_qkv, qkv_ptr, M_, 3 * D_, D_);

    // 2) Merged convert
    convert_kernel<<<8192 + (T_ / 32) * 2 * BH_, 256>>>(
        qkv_ptr, qh, ql, kh, kl, vh, vl);

    // 3) Causal attention (fp16 mma; QK 3-term, PV 2-term; 3-buffer ring)
    flash_mma_kernel<<<dim3(T_ / 128, BH_), 256, ATT_SMEM>>>(
        qh, ql, kh, kl, vh, vl, att_ptr);

    // 4) Output projection
    gemm_tf32_kernel<<<dim3(D_ / 128, M_ / 128), 128, GEMM_SMEM>>>(
        att_ptr, woutt_ptr, b_out, out, M_, D_, D_);
}

// round 14
// speedup vs baseline: 1.3464x; 1.1020x over previous
#include <cuda_runtime.h>
#include <cuda_fp16.h>
#include <cstdint>

#define B_  4
#define T_  2048
#define D_  1024
#define H_  16
#define DK_ 64
#define M_  (B_*T_)
#define BH_ (B_*H_)

// Scratch (allocation-free rule: module-scope device globals)
__device__ float g_x_t32[(size_t)M_ * D_];       // x pre-rounded to tf32
__device__ float g_qkv[(size_t)M_ * 3 * D_];     // [B,T,3D]
__device__ float g_att[(size_t)M_ * D_];         // [B,T,D] (tf32-rounded values)
__device__ float g_wqkv_t[(size_t)3 * D_ * D_];  // W_qkv^T [3D, D] tf32-rounded
__device__ float g_wout_t[(size_t)D_ * D_];      // W_out^T [D, D] tf32-rounded
// half hi/lo splits for attention (V: hi only)
__device__ __half g_q_hi[(size_t)BH_ * T_ * DK_];
__device__ __half g_q_lo[(size_t)BH_ * T_ * DK_];
__device__ __half g_k_hi[(size_t)BH_ * T_ * DK_];
__device__ __half g_k_lo[(size_t)BH_ * T_ * DK_];
__device__ __half g_vt_hi[(size_t)BH_ * DK_ * T_];  // [bh][d][t]

// ---------------------------------------------------------------------------
// PTX helpers
// ---------------------------------------------------------------------------
__device__ __forceinline__ uint32_t smem_u32(const void* p) {
    uint32_t a;
    asm("{ .reg .u64 t; cvta.to.shared.u64 t, %1; cvt.u32.u64 %0, t; }"
        : "=r"(a) : "l"(p));
    return a;
}
__device__ __forceinline__ void cp_async16(uint32_t dst, const void* src) {
    asm volatile("cp.async.ca.shared.global [%0], [%1], 16;"
                 :: "r"(dst), "l"(src) : "memory");
}
__device__ __forceinline__ void cp_commit() {
    asm volatile("cp.async.commit_group;" ::: "memory");
}
__device__ __forceinline__ void cp_wait0() {
    asm volatile("cp.async.wait_group 0;" ::: "memory");
}
__device__ __forceinline__ void cp_wait1() {
    asm volatile("cp.async.wait_group 1;" ::: "memory");
}
__device__ __forceinline__ void cp_wait2() {
    asm volatile("cp.async.wait_group 2;" ::: "memory");
}
__device__ __forceinline__ float ex2f(float x) {
    float y;
    asm("ex2.approx.f32 %0, %1;" : "=f"(y) : "f"(x));
    return y;
}
__device__ __forceinline__ float rna_tf32(float x) {
    uint32_t r;
    asm("cvt.rna.tf32.f32 %0, %1;" : "=r"(r) : "f"(x));
    return __uint_as_float(r);
}
__device__ __forceinline__ void cvt4_rna(uint32_t (&o)[4], float4 v) {
    asm("cvt.rna.tf32.f32 %0, %1;" : "=r"(o[0]) : "f"(v.x));
    asm("cvt.rna.tf32.f32 %0, %1;" : "=r"(o[1]) : "f"(v.y));
    asm("cvt.rna.tf32.f32 %0, %1;" : "=r"(o[2]) : "f"(v.z));
    asm("cvt.rna.tf32.f32 %0, %1;" : "=r"(o[3]) : "f"(v.w));
}
__device__ __forceinline__ void mma16816(float (&c)[4], uint32_t a0, uint32_t a1,
                                         uint32_t a2, uint32_t a3,
                                         uint32_t b0, uint32_t b1) {
    asm volatile(
        "mma.sync.aligned.m16n8k16.row.col.f32.f16.f16.f32 "
        "{%0,%1,%2,%3}, {%4,%5,%6,%7}, {%8,%9}, {%0,%1,%2,%3};"
        : "+f"(c[0]), "+f"(c[1]), "+f"(c[2]), "+f"(c[3])
        : "r"(a0), "r"(a1), "r"(a2), "r"(a3), "r"(b0), "r"(b1));
}
__device__ __forceinline__ void mma_tf32(float (&c)[4], const uint32_t (&a)[4],
                                         const uint32_t (&b)[2]) {
    asm volatile(
        "mma.sync.aligned.m16n8k8.row.col.f32.tf32.tf32.f32 "
        "{%0,%1,%2,%3}, {%4,%5,%6,%7}, {%8,%9}, {%0,%1,%2,%3};"
        : "+f"(c[0]), "+f"(c[1]), "+f"(c[2]), "+f"(c[3])
        : "r"(a[0]), "r"(a[1]), "r"(a[2]), "r"(a[3]), "r"(b[0]), "r"(b[1]));
}

// split one float4 into half hi/lo pairs and store
__device__ __forceinline__ void split_store4(float4 v, __half* hi, __half* lo,
                                             size_t o) {
    __half2 h0 = __floats2half2_rn(v.x, v.y);
    __half2 h1 = __floats2half2_rn(v.z, v.w);
    float2 f0 = __half22float2(h0), f1 = __half22float2(h1);
    __half2 l0 = __floats2half2_rn(v.x - f0.x, v.y - f0.y);
    __half2 l1 = __floats2half2_rn(v.z - f1.x, v.w - f1.y);
    *(__half2*)(hi + o)     = h0;
    *(__half2*)(hi + o + 2) = h1;
    *(__half2*)(lo + o)     = l0;
    *(__half2*)(lo + o + 2) = l1;
}

// ---------------------------------------------------------------------------
// Merged prologue: W_qkv transpose+round | W_out transpose+round | x round.
// ---------------------------------------------------------------------------
__global__ __launch_bounds__(256)
void prologue_kernel(const float* __restrict__ Wqkv, float* __restrict__ WqkvT,
                     const float* __restrict__ Wout, float* __restrict__ WoutT,
                     const float4* __restrict__ x, float4* __restrict__ xT)
{
    const int bid = blockIdx.x;
    const int tid = threadIdx.x;
    if (bid >= 4096) {
        const int i = (bid - 4096) * 256 + tid;
        uint32_t c4[4];
        cvt4_rna(c4, x[i]);
        xT[i] = *(float4*)c4;
        return;
    }
    __shared__ float t[32][33];
    const float* in;
    float* out;
    int bx, by, R, C;
    if (bid < 3072) {
        in = Wqkv; out = WqkvT; R = D_; C = 3 * D_;
        bx = (bid % 96) * 32; by = (bid / 96) * 32;
    } else {
        in = Wout; out = WoutT; R = D_; C = D_;
        const int t2 = bid - 3072;
        bx = (t2 % 32) * 32; by = (t2 / 32) * 32;
    }
    const int tx = tid & 31, ty = tid >> 5;
#pragma unroll
    for (int j = 0; j < 32; j += 8)
        t[ty + j][tx] = in[(size_t)(by + ty + j) * C + bx + tx];
    __syncthreads();
#pragma unroll
    for (int j = 0; j < 32; j += 8)
        out[(size_t)(bx + ty + j) * R + by + tx] = rna_tf32(t[tx][ty + j]);
}

// ---------------------------------------------------------------------------
// tf32 GEMM (round-6 exact): C[M,N] = A[M,K] @ Bt[N,K]^T + bias[N]
// ---------------------------------------------------------------------------
#define APAD   20
#define ATILE  (128 * APAD)
#define STW    (2 * ATILE)
#define NSTAGE 4
#define GEMM_SMEM (NSTAGE * STW * 4)    // 81920 B

__global__ __launch_bounds__(128, 2)
void gemm_tf32_kernel(const float* __restrict__ A,
                      const float* __restrict__ Bt,
                      const float* __restrict__ bias,
                      float* __restrict__ C,
                      int M, int N, int K)
{
    extern __shared__ uint32_t smw[];
    const uint32_t sbase = smem_u32(smw);
    const int tid  = threadIdx.x;
    const int wid  = tid >> 5;
    const int lane = tid & 31;
    const int grp  = lane >> 2;
    const int tg   = lane & 3;
    const int warp_m = (wid & 1) * 64;
    const int warp_n = (wid >> 1) * 64;
    const int m0 = blockIdx.y * 128;
    const int n0 = blockIdx.x * 128;
    const int nk = K >> 4;

    const float* Abase = A + (size_t)m0 * K;
    const float* Bbase = Bt + (size_t)n0 * K;

    auto issue = [&](int i) {
        if (i < nk) {
            const int k0 = i << 4;
            const uint32_t st = sbase + ((i & (NSTAGE - 1)) * STW) * 4;
#pragma unroll
            for (int j = 0; j < 4; j++) {
                const int idx = tid + j * 128;
                const int r = idx >> 2, kc = (idx & 3) << 2;
                cp_async16(st + (r * APAD + kc) * 4,
                           Abase + (size_t)r * K + k0 + kc);
                cp_async16(st + (ATILE + r * APAD + kc) * 4,
                           Bbase + (size_t)r * K + k0 + kc);
            }
        }
        cp_commit();
    };

    float acc[4][8][4];
#pragma unroll
    for (int i = 0; i < 4; i++)
#pragma unroll
        for (int j = 0; j < 8; j++)
#pragma unroll
            for (int r = 0; r < 4; r++) acc[i][j][r] = 0.f;

    issue(0); issue(1); issue(2);

    uint32_t a[2][4][4], b[2][8][2];

    for (int i = 0; i < nk; i++) {
        cp_wait2();
        __syncthreads();
        issue(i + 3);

        const uint32_t* Au = smw + (i & (NSTAGE - 1)) * STW;
        const uint32_t* Bu = Au + ATILE;

        {
            const int k0 = tg;
#pragma unroll
            for (int ii = 0; ii < 4; ii++) {
                const uint32_t* p0 = Au + (warp_m + 16 * ii + grp) * APAD;
                a[0][ii][0] = p0[k0];
                a[0][ii][2] = p0[k0 + 4];
                const uint32_t* p1 = p0 + 8 * APAD;
                a[0][ii][1] = p1[k0];
                a[0][ii][3] = p1[k0 + 4];
            }
#pragma unroll
            for (int jj = 0; jj < 8; jj++) {
                const uint32_t* pn = Bu + (warp_n + 8 * jj + grp) * APAD;
                b[0][jj][0] = pn[k0];
                b[0][jj][1] = pn[k0 + 4];
            }
        }
#pragma unroll
        for (int ks = 0; ks < 2; ks++) {
            if (ks == 0) {
                const int k0 = 8 + tg;
#pragma unroll
                for (int ii = 0; ii < 4; ii++) {
                    const uint32_t* p0 = Au + (warp_m + 16 * ii + grp) * APAD;
                    a[1][ii][0] = p0[k0];
                    a[1][ii][2] = p0[k0 + 4];
                    const uint32_t* p1 = p0 + 8 * APAD;
                    a[1][ii][1] = p1[k0];
                    a[1][ii][3] = p1[k0 + 4];
                }
#pragma unroll
                for (int jj = 0; jj < 8; jj++) {
                    const uint32_t* pn = Bu + (warp_n + 8 * jj + grp) * APAD;
                    b[1][jj][0] = pn[k0];
                    b[1][jj][1] = pn[k0 + 4];
                }
            }
#pragma unroll
            for (int ii = 0; ii < 4; ii++)
#pragma unroll
                for (int jj = 0; jj < 8; jj++)
                    mma_tf32(acc[ii][jj], a[ks][ii], b[ks][jj]);
        }
    }

#pragma unroll
    for (int ii = 0; ii < 4; ii++) {
        const int m = m0 + warp_m + 16 * ii + grp;
#pragma unroll
        for (int jj = 0; jj < 8; jj++) {
            const int n = n0 + warp_n + 8 * jj + 2 * tg;
            const float bv0 = __ldg(&bias[n]);
            const float bv1 = __ldg(&bias[n + 1]);
            float2 v0 = {acc[ii][jj][0] + bv0, acc[ii][jj][1] + bv1};
            float2 v1 = {acc[ii][jj][2] + bv0, acc[ii][jj][3] + bv1};
            *(float2*)(C + (size_t)m * N + n)       = v0;
            *(float2*)(C + (size_t)(m + 8) * N + n) = v1;
        }
    }
}

// ---------------------------------------------------------------------------
// Merged convert: Q/K split (blocks [0, 8192)) | V transpose (hi only, rest).
// ---------------------------------------------------------------------------
__global__ __launch_bounds__(256)
void convert_kernel(const float* __restrict__ qkv,
                    __half* __restrict__ qh, __half* __restrict__ ql,
                    __half* __restrict__ kh, __half* __restrict__ kl,
                    __half* __restrict__ vh)
{
    const int bid = blockIdx.x;
    const int tid = threadIdx.x;
    if (bid < 8192) {
        int i = bid * 256 + tid;
        int c4 = i & 15;
        int t  = (i >> 4) & (T_ - 1);
        int bh = i >> 15;
        int b = bh >> 4, h = bh & 15;
        const float4* src = (const float4*)(qkv + ((size_t)(b * T_ + t)) * 3 * D_);
        float4 q4 = src[h * 16 + c4];
        float4 k4 = src[256 + h * 16 + c4];
        size_t o = ((size_t)bh * T_ + t) * 64 + c4 * 4;
        split_store4(q4, qh, ql, o);
        split_store4(k4, kh, kl, o);
        return;
    }
    __shared__ float tile[32][33];
    const int vb = bid - 8192;
    const int t0 = (vb % (T_ / 32)) * 32;
    const int d0 = ((vb / (T_ / 32)) & 1) * 32;
    const int bh = vb / (T_ / 32) / 2;
    const int b = bh >> 4, h = bh & 15;
    const int tx = tid & 31, ty = tid >> 5;
#pragma unroll
    for (int j = 0; j < 32; j += 8)
        tile[ty + j][tx] = qkv[((size_t)(b * T_ + t0 + ty + j)) * 3 * D_
                               + 2 * D_ + h * 64 + d0 + tx];
    __syncthreads();
#pragma unroll
    for (int j = 0; j < 32; j += 8) {
        int d = d0 + ty + j;
        size_t o = ((size_t)bh * DK_ + d) * T_ + t0 + tx;
        vh[o] = __float2half_rn(tile[tx][ty + j]);
    }
}

// ---------------------------------------------------------------------------
// Flash attention, fp16 mma. QK: 3-term hi/lo split. PV: 1-term (ph*vh).
// KV buffer = Kh|Kl|Vh (3 arrays). Ring of 3, ONE barrier per kv tile.
// ---------------------------------------------------------------------------
#define AW   36
#define KVW  (64 * AW)
#define BUFW (3 * KVW)
#define ATT_SMEM (3 * BUFW * 4)          // 82944 B

__global__ __launch_bounds__(256, 2)
void flash_mma_kernel(const __half* __restrict__ qh_g, const __half* __restrict__ ql_g,
                      const __half* __restrict__ kh_g, const __half* __restrict__ kl_g,
                      const __half* __restrict__ vh_g,
                      float* __restrict__ out)
{
    extern __shared__ uint32_t smw[];
    const uint32_t sbase = smem_u32(smw);
    const int tid = threadIdx.x, wid = tid >> 5, lane = tid & 31;
    const int grp = lane >> 2, tg = lane & 3;
    const int bh = blockIdx.y, b = bh >> 4, h = bh & 15;
    const int qt = gridDim.x - 1 - blockIdx.x;
    const int q0 = qt * 128;
    const int wm = wid * 16;
    const int row0 = q0 + wm + grp;
    const int row1 = row0 + 8;

    // stage Q (hi|lo) at smem base, lift fragments, then release
    {
        const uint4* qh4 = (const uint4*)(qh_g + (size_t)bh * T_ * DK_) + q0 * 8;
        const uint4* ql4 = (const uint4*)(ql_g + (size_t)bh * T_ * DK_) + q0 * 8;
#pragma unroll
        for (int j = 0; j < 4; j++) {
            int idx = tid + j * 256;
            int r = idx >> 3, c = idx & 7;
            uint32_t dst = sbase + (r * AW + c * 4) * 4;
            cp_async16(dst, qh4 + r * 8 + c);
            cp_async16(dst + 4608 * 4, ql4 + r * 8 + c);
        }
        cp_commit(); cp_wait0();
        __syncthreads();
    }
    uint32_t qfh[4][4], qfl[4][4];
    {
        const uint32_t* Q = smw;
        const int base = (wm + grp) * AW + tg;
#pragma unroll
        for (int kc = 0; kc < 4; kc++) {
            qfh[kc][0] = Q[base + 8 * kc];
            qfh[kc][1] = Q[base + 8 * AW + 8 * kc];
            qfh[kc][2] = Q[base + 8 * kc + 4];
            qfh[kc][3] = Q[base + 8 * AW + 8 * kc + 4];
            qfl[kc][0] = Q[4608 + base + 8 * kc];
            qfl[kc][1] = Q[4608 + base + 8 * AW + 8 * kc];
            qfl[kc][2] = Q[4608 + base + 8 * kc + 4];
            qfl[kc][3] = Q[4608 + base + 8 * AW + 8 * kc + 4];
        }
    }
    __syncthreads();    // Q staging region becomes KV buffers

    const uint4* kh4 = (const uint4*)(kh_g + (size_t)bh * T_ * DK_);
    const uint4* kl4 = (const uint4*)(kl_g + (size_t)bh * T_ * DK_);
    const uint4* vh4 = (const uint4*)(vh_g + (size_t)bh * DK_ * T_);

    auto kv_load = [&](int t, int buf) {
        const int kv0 = t * 64;
#pragma unroll
        for (int j = 0; j < 2; j++) {
            int idx = tid + j * 256;
            int r = idx >> 3, c = idx & 7;
            uint32_t dst = sbase + (buf * BUFW + r * AW + c * 4) * 4;
            cp_async16(dst,               kh4 + (kv0 + r) * 8 + c);
            cp_async16(dst + KVW * 4,     kl4 + (kv0 + r) * 8 + c);
            cp_async16(dst + 2 * KVW * 4, vh4 + (size_t)r * (T_ / 8) + kv0 / 8 + c);
        }
    };

    float o[8][4];
#pragma unroll
    for (int j = 0; j < 8; j++)
#pragma unroll
        for (int e = 0; e < 4; e++) o[j][e] = 0.f;
    float m0 = -1e30f, m1 = -1e30f, l0 = 0.f, l1 = 0.f;

    const int nt = 2 * (qt + 1);
    kv_load(0, 0); cp_commit();
    kv_load(1, 1); cp_commit();

    int bc = 0, bn = 2;
    for (int t = 0; t < nt; t++) {
        cp_wait1();
        __syncthreads();
        if (t + 2 < nt) kv_load(t + 2, bn);
        cp_commit();

        const uint32_t* Kh = smw + bc * BUFW;
        const uint32_t* Kl = Kh + KVW;
        const uint32_t* Vh = Kh + 2 * KVW;

        // ---- S = Q K^T (3-term split)
        float s[8][4];
#pragma unroll
        for (int j = 0; j < 8; j++)
#pragma unroll
            for (int e = 0; e < 4; e++) s[j][e] = 0.f;
#pragma unroll
        for (int kc = 0; kc < 4; kc++) {
            const int bo = 8 * kc + tg;
#pragma unroll
            for (int j = 0; j < 8; j++) {
                const int nb = (8 * j + grp) * AW + bo;
                uint32_t b0h = Kh[nb], b1h = Kh[nb + 4];
                uint32_t b0l = Kl[nb], b1l = Kl[nb + 4];
                mma16816(s[j], qfh[kc][0], qfh[kc][1], qfh[kc][2], qfh[kc][3], b0h, b1h);
                mma16816(s[j], qfl[kc][0], qfl[kc][1], qfl[kc][2], qfl[kc][3], b0h, b1h);
                mma16816(s[j], qfh[kc][0], qfh[kc][1], qfh[kc][2], qfh[kc][3], b0l, b1l);
            }
        }

        // ---- online softmax (base-2)
        const int kv0 = t * 64;
        const float cs = 0.125f * 1.4426950408889634f;
        const bool maskw = (kv0 + 63 > q0 + wm);
        float mx0 = -1e30f, mx1 = -1e30f;
#pragma unroll
        for (int j = 0; j < 8; j++) {
            const int c0 = kv0 + 8 * j + 2 * tg;
            float x0 = s[j][0] * cs, x1 = s[j][1] * cs;
            float x2 = s[j][2] * cs, x3 = s[j][3] * cs;
            if (maskw) {
                if (c0 > row0)     x0 = -1e30f;
                if (c0 + 1 > row0) x1 = -1e30f;
                if (c0 > row1)     x2 = -1e30f;
                if (c0 + 1 > row1) x3 = -1e30f;
            }
            s[j][0] = x0; s[j][1] = x1; s[j][2] = x2; s[j][3] = x3;
            mx0 = fmaxf(mx0, fmaxf(x0, x1));
            mx1 = fmaxf(mx1, fmaxf(x2, x3));
        }
        mx0 = fmaxf(mx0, __shfl_xor_sync(0xffffffffu, mx0, 1));
        mx0 = fmaxf(mx0, __shfl_xor_sync(0xffffffffu, mx0, 2));
        mx1 = fmaxf(mx1, __shfl_xor_sync(0xffffffffu, mx1, 1));
        mx1 = fmaxf(mx1, __shfl_xor_sync(0xffffffffu, mx1, 2));
        const float mn0 = fmaxf(m0, mx0), mn1 = fmaxf(m1, mx1);
        const float a0 = ex2f(m0 - mn0),  a1 = ex2f(m1 - mn1);
        m0 = mn0; m1 = mn1;

        float sum0 = 0.f, sum1 = 0.f;
#pragma unroll
        for (int j = 0; j < 8; j++) {
            float p0 = ex2f(s[j][0] - m0), p1 = ex2f(s[j][1] - m0);
            float p2 = ex2f(s[j][2] - m1), p3 = ex2f(s[j][3] - m1);
            s[j][0] = p0; s[j][1] = p1; s[j][2] = p2; s[j][3] = p3;
            sum0 += p0 + p1; sum1 += p2 + p3;
        }
        sum0 += __shfl_xor_sync(0xffffffffu, sum0, 1);
        sum0 += __shfl_xor_sync(0xffffffffu, sum0, 2);
        sum1 += __shfl_xor_sync(0xffffffffu, sum1, 1);
        sum1 += __shfl_xor_sync(0xffffffffu, sum1, 2);
        l0 = l0 * a0 + sum0;
        l1 = l1 * a1 + sum1;
#pragma unroll
        for (int j = 0; j < 8; j++) {
            o[j][0] *= a0; o[j][1] *= a0; o[j][2] *= a1; o[j][3] *= a1;
        }

        // ---- O += P V (1-term: ph*vh)
#pragma unroll
        for (int kc = 0; kc < 4; kc++) {
            const int j0 = 2 * kc, j1 = 2 * kc + 1;
            __half2 A0 = __floats2half2_rn(s[j0][0], s[j0][1]);
            __half2 A1 = __floats2half2_rn(s[j0][2], s[j0][3]);
            __half2 A2 = __floats2half2_rn(s[j1][0], s[j1][1]);
            __half2 A3 = __floats2half2_rn(s[j1][2], s[j1][3]);
            const uint32_t ph0 = *(uint32_t*)&A0, ph1 = *(uint32_t*)&A1;
            const uint32_t ph2 = *(uint32_t*)&A2, ph3 = *(uint32_t*)&A3;
            const int bo = 8 * kc + tg;
#pragma unroll
            for (int jj = 0; jj < 8; jj++) {
                const int nb = (8 * jj + grp) * AW + bo;
                mma16816(o[jj], ph0, ph1, ph2, ph3, Vh[nb], Vh[nb + 4]);
            }
        }

        bc = (bc == 2) ? 0 : bc + 1;
        bn = (bn == 2) ? 0 : bn + 1;
    }

    const float i0 = 1.0f / l0, i1 = 1.0f / l1;
    float* out0 = out + ((size_t)(b * T_ + row0)) * D_ + h * 64 + 2 * tg;
    float* out1 = out + ((size_t)(b * T_ + row1)) * D_ + h * 64 + 2 * tg;
#pragma unroll
    for (int jj = 0; jj < 8; jj++) {
        float2 v0 = {rna_tf32(o[jj][0] * i0), rna_tf32(o[jj][1] * i0)};
        float2 v1 = {rna_tf32(o[jj][2] * i1), rna_tf32(o[jj][3] * i1)};
        *(float2*)(out0 + 8 * jj) = v0;
        *(float2*)(out1 + 8 * jj) = v1;
    }
}

// ---------------------------------------------------------------------------
extern "C" void kernel_launch(void* const* d_in, const int* in_sizes, int n_in,
                              void* d_out, int out_size)
{
    (void)in_sizes; (void)n_in; (void)out_size;
    const float* x     = (const float*)d_in[0];
    const float* W_qkv = (const float*)d_in[1];
    const float* b_qkv = (const float*)d_in[2];
    const float* W_out = (const float*)d_in[3];
    const float* b_out = (const float*)d_in[4];
    float* out = (float*)d_out;

    float *xt_ptr, *qkv_ptr, *att_ptr, *wqkvt_ptr, *woutt_ptr;
    cudaGetSymbolAddress((void**)&xt_ptr,    g_x_t32);
    cudaGetSymbolAddress((void**)&qkv_ptr,   g_qkv);
    cudaGetSymbolAddress((void**)&att_ptr,   g_att);
    cudaGetSymbolAddress((void**)&wqkvt_ptr, g_wqkv_t);
    cudaGetSymbolAddress((void**)&woutt_ptr, g_wout_t);
    __half *qh, *ql, *kh, *kl, *vh;
    cudaGetSymbolAddress((void**)&qh, g_q_hi);
    cudaGetSymbolAddress((void**)&ql, g_q_lo);
    cudaGetSymbolAddress((void**)&kh, g_k_hi);
    cudaGetSymbolAddress((void**)&kl, g_k_lo);
    cudaGetSymbolAddress((void**)&vh, g_vt_hi);

    cudaFuncSetAttribute(gemm_tf32_kernel,
                         cudaFuncAttributeMaxDynamicSharedMemorySize, GEMM_SMEM);
    cudaFuncSetAttribute(flash_mma_kernel,
                         cudaFuncAttributeMaxDynamicSharedMemorySize, ATT_SMEM);

    // 0) Merged prologue
    prologue_kernel<<<4096 + (M_ * D_ / 4) / 256, 256>>>(
        W_qkv, wqkvt_ptr, W_out, woutt_ptr, (const float4*)x, (float4*)xt_ptr);

    // 1) QKV projection
    gemm_tf32_kernel<<<dim3(3 * D_ / 128, M_ / 128), 128, GEMM_SMEM>>>(
        xt_ptr, wqkvt_ptr, b_qkv, qkv_ptr, M_, 3 * D_, D_);

    // 2) Merged convert (V: hi only)
    convert_kernel<<<8192 + (T_ / 32) * 2 * BH_, 256>>>(
        qkv_ptr, qh, ql, kh, kl, vh);

    // 3) Causal attention (QK 3-term, PV 1-term, 3-buffer ring)
    flash_mma_kernel<<<dim3(T_ / 128, BH_), 256, ATT_SMEM>>>(
        qh, ql, kh, kl, vh, att_ptr);

    // 4) Output projection
    gemm_tf32_kernel<<<dim3(D_ / 128, M_ / 128), 128, GEMM_SMEM>>>(
        att_ptr, woutt_ptr, b_out, out, M_, D_, D_);
}

// round 15
// speedup vs baseline: 1.4579x; 1.0828x over previous
#include <cuda_runtime.h>
#include <cuda_fp16.h>
#include <cstdint>

#define B_  4
#define T_  2048
#define D_  1024
#define H_  16
#define DK_ 64
#define M_  (B_*T_)
#define BH_ (B_*H_)

// Scratch (allocation-free rule: module-scope device globals)
__device__ float g_x_t32[(size_t)M_ * D_];       // x pre-rounded to tf32
__device__ float g_qkv[(size_t)M_ * 3 * D_];     // [B,T,3D]
__device__ float g_att[(size_t)M_ * D_];         // [B,T,D] (tf32-rounded values)
__device__ float g_wqkv_t[(size_t)3 * D_ * D_];  // W_qkv^T [3D, D] tf32-rounded
__device__ float g_wout_t[(size_t)D_ * D_];      // W_out^T [D, D] tf32-rounded
// half splits for attention: Q hi/lo, K hi only, V hi only
__device__ __half g_q_hi[(size_t)BH_ * T_ * DK_];
__device__ __half g_q_lo[(size_t)BH_ * T_ * DK_];
__device__ __half g_k_hi[(size_t)BH_ * T_ * DK_];
__device__ __half g_vt_hi[(size_t)BH_ * DK_ * T_];  // [bh][d][t]

// ---------------------------------------------------------------------------
// PTX helpers
// ---------------------------------------------------------------------------
__device__ __forceinline__ uint32_t smem_u32(const void* p) {
    uint32_t a;
    asm("{ .reg .u64 t; cvta.to.shared.u64 t, %1; cvt.u32.u64 %0, t; }"
        : "=r"(a) : "l"(p));
    return a;
}
__device__ __forceinline__ void cp_async16(uint32_t dst, const void* src) {
    asm volatile("cp.async.ca.shared.global [%0], [%1], 16;"
                 :: "r"(dst), "l"(src) : "memory");
}
__device__ __forceinline__ void cp_commit() {
    asm volatile("cp.async.commit_group;" ::: "memory");
}
__device__ __forceinline__ void cp_wait0() {
    asm volatile("cp.async.wait_group 0;" ::: "memory");
}
__device__ __forceinline__ void cp_wait1() {
    asm volatile("cp.async.wait_group 1;" ::: "memory");
}
__device__ __forceinline__ void cp_wait2() {
    asm volatile("cp.async.wait_group 2;" ::: "memory");
}
__device__ __forceinline__ float ex2f(float x) {
    float y;
    asm("ex2.approx.f32 %0, %1;" : "=f"(y) : "f"(x));
    return y;
}
__device__ __forceinline__ float rna_tf32(float x) {
    uint32_t r;
    asm("cvt.rna.tf32.f32 %0, %1;" : "=r"(r) : "f"(x));
    return __uint_as_float(r);
}
__device__ __forceinline__ void cvt4_rna(uint32_t (&o)[4], float4 v) {
    asm("cvt.rna.tf32.f32 %0, %1;" : "=r"(o[0]) : "f"(v.x));
    asm("cvt.rna.tf32.f32 %0, %1;" : "=r"(o[1]) : "f"(v.y));
    asm("cvt.rna.tf32.f32 %0, %1;" : "=r"(o[2]) : "f"(v.z));
    asm("cvt.rna.tf32.f32 %0, %1;" : "=r"(o[3]) : "f"(v.w));
}
__device__ __forceinline__ void mma16816(float (&c)[4], uint32_t a0, uint32_t a1,
                                         uint32_t a2, uint32_t a3,
                                         uint32_t b0, uint32_t b1) {
    asm volatile(
        "mma.sync.aligned.m16n8k16.row.col.f32.f16.f16.f32 "
        "{%0,%1,%2,%3}, {%4,%5,%6,%7}, {%8,%9}, {%0,%1,%2,%3};"
        : "+f"(c[0]), "+f"(c[1]), "+f"(c[2]), "+f"(c[3])
        : "r"(a0), "r"(a1), "r"(a2), "r"(a3), "r"(b0), "r"(b1));
}
__device__ __forceinline__ void mma_tf32(float (&c)[4], const uint32_t (&a)[4],
                                         const uint32_t (&b)[2]) {
    asm volatile(
        "mma.sync.aligned.m16n8k8.row.col.f32.tf32.tf32.f32 "
        "{%0,%1,%2,%3}, {%4,%5,%6,%7}, {%8,%9}, {%0,%1,%2,%3};"
        : "+f"(c[0]), "+f"(c[1]), "+f"(c[2]), "+f"(c[3])
        : "r"(a[0]), "r"(a[1]), "r"(a[2]), "r"(a[3]), "r"(b[0]), "r"(b[1]));
}

// split one float4 into half hi/lo pairs and store
__device__ __forceinline__ void split_store4(float4 v, __half* hi, __half* lo,
                                             size_t o) {
    __half2 h0 = __floats2half2_rn(v.x, v.y);
    __half2 h1 = __floats2half2_rn(v.z, v.w);
    float2 f0 = __half22float2(h0), f1 = __half22float2(h1);
    __half2 l0 = __floats2half2_rn(v.x - f0.x, v.y - f0.y);
    __half2 l1 = __floats2half2_rn(v.z - f1.x, v.w - f1.y);
    *(__half2*)(hi + o)     = h0;
    *(__half2*)(hi + o + 2) = h1;
    *(__half2*)(lo + o)     = l0;
    *(__half2*)(lo + o + 2) = l1;
}

// ---------------------------------------------------------------------------
// Merged prologue: W_qkv transpose+round | W_out transpose+round | x round.
// ---------------------------------------------------------------------------
__global__ __launch_bounds__(256)
void prologue_kernel(const float* __restrict__ Wqkv, float* __restrict__ WqkvT,
                     const float* __restrict__ Wout, float* __restrict__ WoutT,
                     const float4* __restrict__ x, float4* __restrict__ xT)
{
    const int bid = blockIdx.x;
    const int tid = threadIdx.x;
    if (bid >= 4096) {
        const int i = (bid - 4096) * 256 + tid;
        uint32_t c4[4];
        cvt4_rna(c4, x[i]);
        xT[i] = *(float4*)c4;
        return;
    }
    __shared__ float t[32][33];
    const float* in;
    float* out;
    int bx, by, R, C;
    if (bid < 3072) {
        in = Wqkv; out = WqkvT; R = D_; C = 3 * D_;
        bx = (bid % 96) * 32; by = (bid / 96) * 32;
    } else {
        in = Wout; out = WoutT; R = D_; C = D_;
        const int t2 = bid - 3072;
        bx = (t2 % 32) * 32; by = (t2 / 32) * 32;
    }
    const int tx = tid & 31, ty = tid >> 5;
#pragma unroll
    for (int j = 0; j < 32; j += 8)
        t[ty + j][tx] = in[(size_t)(by + ty + j) * C + bx + tx];
    __syncthreads();
#pragma unroll
    for (int j = 0; j < 32; j += 8)
        out[(size_t)(bx + ty + j) * R + by + tx] = rna_tf32(t[tx][ty + j]);
}

// ---------------------------------------------------------------------------
// tf32 GEMM (round-6 exact): C[M,N] = A[M,K] @ Bt[N,K]^T + bias[N]
// ---------------------------------------------------------------------------
#define APAD   20
#define ATILE  (128 * APAD)
#define STW    (2 * ATILE)
#define NSTAGE 4
#define GEMM_SMEM (NSTAGE * STW * 4)    // 81920 B

__global__ __launch_bounds__(128, 2)
void gemm_tf32_kernel(const float* __restrict__ A,
                      const float* __restrict__ Bt,
                      const float* __restrict__ bias,
                      float* __restrict__ C,
                      int M, int N, int K)
{
    extern __shared__ uint32_t smw[];
    const uint32_t sbase = smem_u32(smw);
    const int tid  = threadIdx.x;
    const int wid  = tid >> 5;
    const int lane = tid & 31;
    const int grp  = lane >> 2;
    const int tg   = lane & 3;
    const int warp_m = (wid & 1) * 64;
    const int warp_n = (wid >> 1) * 64;
    const int m0 = blockIdx.y * 128;
    const int n0 = blockIdx.x * 128;
    const int nk = K >> 4;

    const float* Abase = A + (size_t)m0 * K;
    const float* Bbase = Bt + (size_t)n0 * K;

    auto issue = [&](int i) {
        if (i < nk) {
            const int k0 = i << 4;
            const uint32_t st = sbase + ((i & (NSTAGE - 1)) * STW) * 4;
#pragma unroll
            for (int j = 0; j < 4; j++) {
                const int idx = tid + j * 128;
                const int r = idx >> 2, kc = (idx & 3) << 2;
                cp_async16(st + (r * APAD + kc) * 4,
                           Abase + (size_t)r * K + k0 + kc);
                cp_async16(st + (ATILE + r * APAD + kc) * 4,
                           Bbase + (size_t)r * K + k0 + kc);
            }
        }
        cp_commit();
    };

    float acc[4][8][4];
#pragma unroll
    for (int i = 0; i < 4; i++)
#pragma unroll
        for (int j = 0; j < 8; j++)
#pragma unroll
            for (int r = 0; r < 4; r++) acc[i][j][r] = 0.f;

    issue(0); issue(1); issue(2);

    uint32_t a[2][4][4], b[2][8][2];

    for (int i = 0; i < nk; i++) {
        cp_wait2();
        __syncthreads();
        issue(i + 3);

        const uint32_t* Au = smw + (i & (NSTAGE - 1)) * STW;
        const uint32_t* Bu = Au + ATILE;

        {
            const int k0 = tg;
#pragma unroll
            for (int ii = 0; ii < 4; ii++) {
                const uint32_t* p0 = Au + (warp_m + 16 * ii + grp) * APAD;
                a[0][ii][0] = p0[k0];
                a[0][ii][2] = p0[k0 + 4];
                const uint32_t* p1 = p0 + 8 * APAD;
                a[0][ii][1] = p1[k0];
                a[0][ii][3] = p1[k0 + 4];
            }
#pragma unroll
            for (int jj = 0; jj < 8; jj++) {
                const uint32_t* pn = Bu + (warp_n + 8 * jj + grp) * APAD;
                b[0][jj][0] = pn[k0];
                b[0][jj][1] = pn[k0 + 4];
            }
        }
#pragma unroll
        for (int ks = 0; ks < 2; ks++) {
            if (ks == 0) {
                const int k0 = 8 + tg;
#pragma unroll
                for (int ii = 0; ii < 4; ii++) {
                    const uint32_t* p0 = Au + (warp_m + 16 * ii + grp) * APAD;
                    a[1][ii][0] = p0[k0];
                    a[1][ii][2] = p0[k0 + 4];
                    const uint32_t* p1 = p0 + 8 * APAD;
                    a[1][ii][1] = p1[k0];
                    a[1][ii][3] = p1[k0 + 4];
                }
#pragma unroll
                for (int jj = 0; jj < 8; jj++) {
                    const uint32_t* pn = Bu + (warp_n + 8 * jj + grp) * APAD;
                    b[1][jj][0] = pn[k0];
                    b[1][jj][1] = pn[k0 + 4];
                }
            }
#pragma unroll
            for (int ii = 0; ii < 4; ii++)
#pragma unroll
                for (int jj = 0; jj < 8; jj++)
                    mma_tf32(acc[ii][jj], a[ks][ii], b[ks][jj]);
        }
    }

#pragma unroll
    for (int ii = 0; ii < 4; ii++) {
        const int m = m0 + warp_m + 16 * ii + grp;
#pragma unroll
        for (int jj = 0; jj < 8; jj++) {
            const int n = n0 + warp_n + 8 * jj + 2 * tg;
            const float bv0 = __ldg(&bias[n]);
            const float bv1 = __ldg(&bias[n + 1]);
            float2 v0 = {acc[ii][jj][0] + bv0, acc[ii][jj][1] + bv1};
            float2 v1 = {acc[ii][jj][2] + bv0, acc[ii][jj][3] + bv1};
            *(float2*)(C + (size_t)m * N + n)       = v0;
            *(float2*)(C + (size_t)(m + 8) * N + n) = v1;
        }
    }
}

// ---------------------------------------------------------------------------
// Merged convert: Q split hi/lo, K hi only (blocks [0,8192)) | V hi (rest).
// ---------------------------------------------------------------------------
__global__ __launch_bounds__(256)
void convert_kernel(const float* __restrict__ qkv,
                    __half* __restrict__ qh, __half* __restrict__ ql,
                    __half* __restrict__ kh, __half* __restrict__ vh)
{
    const int bid = blockIdx.x;
    const int tid = threadIdx.x;
    if (bid < 8192) {
        int i = bid * 256 + tid;
        int c4 = i & 15;
        int t  = (i >> 4) & (T_ - 1);
        int bh = i >> 15;
        int b = bh >> 4, h = bh & 15;
        const float4* src = (const float4*)(qkv + ((size_t)(b * T_ + t)) * 3 * D_);
        float4 q4 = src[h * 16 + c4];
        float4 k4 = src[256 + h * 16 + c4];
        size_t o = ((size_t)bh * T_ + t) * 64 + c4 * 4;
        split_store4(q4, qh, ql, o);
        __half2 kh0 = __floats2half2_rn(k4.x, k4.y);
        __half2 kh1 = __floats2half2_rn(k4.z, k4.w);
        *(__half2*)(kh + o)     = kh0;
        *(__half2*)(kh + o + 2) = kh1;
        return;
    }
    __shared__ float tile[32][33];
    const int vb = bid - 8192;
    const int t0 = (vb % (T_ / 32)) * 32;
    const int d0 = ((vb / (T_ / 32)) & 1) * 32;
    const int bh = vb / (T_ / 32) / 2;
    const int b = bh >> 4, h = bh & 15;
    const int tx = tid & 31, ty = tid >> 5;
#pragma unroll
    for (int j = 0; j < 32; j += 8)
        tile[ty + j][tx] = qkv[((size_t)(b * T_ + t0 + ty + j)) * 3 * D_
                               + 2 * D_ + h * 64 + d0 + tx];
    __syncthreads();
#pragma unroll
    for (int j = 0; j < 32; j += 8) {
        int d = d0 + ty + j;
        size_t o = ((size_t)bh * DK_ + d) * T_ + t0 + tx;
        vh[o] = __float2half_rn(tile[tx][ty + j]);
    }
}

// ---------------------------------------------------------------------------
// Flash attention, fp16 mma.
// QK: 2-term (qh + ql)·kh  (K unsplit; qh·kl dropped, ~2.8e-4 logit rms).
// PV: 1-term ph·vh.
// KV buffer = Kh|Vh (2 arrays). Ring of 3, ONE barrier per kv tile.
// ---------------------------------------------------------------------------
#define AW   36
#define KVW  (64 * AW)
#define BUFW (2 * KVW)
#define ATT_SMEM (3 * BUFW * 4)          // 55296 B

__global__ __launch_bounds__(256, 2)
void flash_mma_kernel(const __half* __restrict__ qh_g, const __half* __restrict__ ql_g,
                      const __half* __restrict__ kh_g,
                      const __half* __restrict__ vh_g,
                      float* __restrict__ out)
{
    extern __shared__ uint32_t smw[];
    const uint32_t sbase = smem_u32(smw);
    const int tid = threadIdx.x, wid = tid >> 5, lane = tid & 31;
    const int grp = lane >> 2, tg = lane & 3;
    const int bh = blockIdx.y, b = bh >> 4, h = bh & 15;
    const int qt = gridDim.x - 1 - blockIdx.x;
    const int q0 = qt * 128;
    const int wm = wid * 16;
    const int row0 = q0 + wm + grp;
    const int row1 = row0 + 8;

    // stage Q (hi|lo) at smem base, lift fragments, then release
    {
        const uint4* qh4 = (const uint4*)(qh_g + (size_t)bh * T_ * DK_) + q0 * 8;
        const uint4* ql4 = (const uint4*)(ql_g + (size_t)bh * T_ * DK_) + q0 * 8;
#pragma unroll
        for (int j = 0; j < 4; j++) {
            int idx = tid + j * 256;
            int r = idx >> 3, c = idx & 7;
            uint32_t dst = sbase + (r * AW + c * 4) * 4;
            cp_async16(dst, qh4 + r * 8 + c);
            cp_async16(dst + 4608 * 4, ql4 + r * 8 + c);
        }
        cp_commit(); cp_wait0();
        __syncthreads();
    }
    uint32_t qfh[4][4], qfl[4][4];
    {
        const uint32_t* Q = smw;
        const int base = (wm + grp) * AW + tg;
#pragma unroll
        for (int kc = 0; kc < 4; kc++) {
            qfh[kc][0] = Q[base + 8 * kc];
            qfh[kc][1] = Q[base + 8 * AW + 8 * kc];
            qfh[kc][2] = Q[base + 8 * kc + 4];
            qfh[kc][3] = Q[base + 8 * AW + 8 * kc + 4];
            qfl[kc][0] = Q[4608 + base + 8 * kc];
            qfl[kc][1] = Q[4608 + base + 8 * AW + 8 * kc];
            qfl[kc][2] = Q[4608 + base + 8 * kc + 4];
            qfl[kc][3] = Q[4608 + base + 8 * AW + 8 * kc + 4];
        }
    }
    __syncthreads();    // Q staging region becomes KV buffers

    const uint4* kh4 = (const uint4*)(kh_g + (size_t)bh * T_ * DK_);
    const uint4* vh4 = (const uint4*)(vh_g + (size_t)bh * DK_ * T_);

    auto kv_load = [&](int t, int buf) {
        const int kv0 = t * 64;
#pragma unroll
        for (int j = 0; j < 2; j++) {
            int idx = tid + j * 256;
            int r = idx >> 3, c = idx & 7;
            uint32_t dst = sbase + (buf * BUFW + r * AW + c * 4) * 4;
            cp_async16(dst,           kh4 + (kv0 + r) * 8 + c);
            cp_async16(dst + KVW * 4, vh4 + (size_t)r * (T_ / 8) + kv0 / 8 + c);
        }
    };

    float o[8][4];
#pragma unroll
    for (int j = 0; j < 8; j++)
#pragma unroll
        for (int e = 0; e < 4; e++) o[j][e] = 0.f;
    float m0 = -1e30f, m1 = -1e30f, l0 = 0.f, l1 = 0.f;

    const int nt = 2 * (qt + 1);
    kv_load(0, 0); cp_commit();
    kv_load(1, 1); cp_commit();

    int bc = 0, bn = 2;
    for (int t = 0; t < nt; t++) {
        cp_wait1();
        __syncthreads();
        if (t + 2 < nt) kv_load(t + 2, bn);
        cp_commit();

        const uint32_t* Kh = smw + bc * BUFW;
        const uint32_t* Vh = Kh + KVW;

        // ---- S = (Qh + Ql) K^T (2-term)
        float s[8][4];
#pragma unroll
        for (int j = 0; j < 8; j++)
#pragma unroll
            for (int e = 0; e < 4; e++) s[j][e] = 0.f;
#pragma unroll
        for (int kc = 0; kc < 4; kc++) {
            const int bo = 8 * kc + tg;
#pragma unroll
            for (int j = 0; j < 8; j++) {
                const int nb = (8 * j + grp) * AW + bo;
                uint32_t b0h = Kh[nb], b1h = Kh[nb + 4];
                mma16816(s[j], qfh[kc][0], qfh[kc][1], qfh[kc][2], qfh[kc][3], b0h, b1h);
                mma16816(s[j], qfl[kc][0], qfl[kc][1], qfl[kc][2], qfl[kc][3], b0h, b1h);
            }
        }

        // ---- online softmax (base-2)
        const int kv0 = t * 64;
        const float cs = 0.125f * 1.4426950408889634f;
        const bool maskw = (kv0 + 63 > q0 + wm);
        float mx0 = -1e30f, mx1 = -1e30f;
#pragma unroll
        for (int j = 0; j < 8; j++) {
            const int c0 = kv0 + 8 * j + 2 * tg;
            float x0 = s[j][0] * cs, x1 = s[j][1] * cs;
            float x2 = s[j][2] * cs, x3 = s[j][3] * cs;
            if (maskw) {
                if (c0 > row0)     x0 = -1e30f;
                if (c0 + 1 > row0) x1 = -1e30f;
                if (c0 > row1)     x2 = -1e30f;
                if (c0 + 1 > row1) x3 = -1e30f;
            }
            s[j][0] = x0; s[j][1] = x1; s[j][2] = x2; s[j][3] = x3;
            mx0 = fmaxf(mx0, fmaxf(x0, x1));
            mx1 = fmaxf(mx1, fmaxf(x2, x3));
        }
        mx0 = fmaxf(mx0, __shfl_xor_sync(0xffffffffu, mx0, 1));
        mx0 = fmaxf(mx0, __shfl_xor_sync(0xffffffffu, mx0, 2));
        mx1 = fmaxf(mx1, __shfl_xor_sync(0xffffffffu, mx1, 1));
        mx1 = fmaxf(mx1, __shfl_xor_sync(0xffffffffu, mx1, 2));
        const float mn0 = fmaxf(m0, mx0), mn1 = fmaxf(m1, mx1);
        const float a0 = ex2f(m0 - mn0),  a1 = ex2f(m1 - mn1);
        m0 = mn0; m1 = mn1;

        float sum0 = 0.f, sum1 = 0.f;
#pragma unroll
        for (int j = 0; j < 8; j++) {
            float p0 = ex2f(s[j][0] - m0), p1 = ex2f(s[j][1] - m0);
            float p2 = ex2f(s[j][2] - m1), p3 = ex2f(s[j][3] - m1);
            s[j][0] = p0; s[j][1] = p1; s[j][2] = p2; s[j][3] = p3;
            sum0 += p0 + p1; sum1 += p2 + p3;
        }
        sum0 += __shfl_xor_sync(0xffffffffu, sum0, 1);
        sum0 += __shfl_xor_sync(0xffffffffu, sum0, 2);
        sum1 += __shfl_xor_sync(0xffffffffu, sum1, 1);
        sum1 += __shfl_xor_sync(0xffffffffu, sum1, 2);
        l0 = l0 * a0 + sum0;
        l1 = l1 * a1 + sum1;
#pragma unroll
        for (int j = 0; j < 8; j++) {
            o[j][0] *= a0; o[j][1] *= a0; o[j][2] *= a1; o[j][3] *= a1;
        }

        // ---- O += P V (1-term)
#pragma unroll
        for (int kc = 0; kc < 4; kc++) {
            const int j0 = 2 * kc, j1 = 2 * kc + 1;
            __half2 A0 = __floats2half2_rn(s[j0][0], s[j0][1]);
            __half2 A1 = __floats2half2_rn(s[j0][2], s[j0][3]);
            __half2 A2 = __floats2half2_rn(s[j1][0], s[j1][1]);
            __half2 A3 = __floats2half2_rn(s[j1][2], s[j1][3]);
            const uint32_t ph0 = *(uint32_t*)&A0, ph1 = *(uint32_t*)&A1;
            const uint32_t ph2 = *(uint32_t*)&A2, ph3 = *(uint32_t*)&A3;
            const int bo = 8 * kc + tg;
#pragma unroll
            for (int jj = 0; jj < 8; jj++) {
                const int nb = (8 * jj + grp) * AW + bo;
                mma16816(o[jj], ph0, ph1, ph2, ph3, Vh[nb], Vh[nb + 4]);
            }
        }

        bc = (bc == 2) ? 0 : bc + 1;
        bn = (bn == 2) ? 0 : bn + 1;
    }

    const float i0 = 1.0f / l0, i1 = 1.0f / l1;
    float* out0 = out + ((size_t)(b * T_ + row0)) * D_ + h * 64 + 2 * tg;
    float* out1 = out + ((size_t)(b * T_ + row1)) * D_ + h * 64 + 2 * tg;
#pragma unroll
    for (int jj = 0; jj < 8; jj++) {
        float2 v0 = {rna_tf32(o[jj][0] * i0), rna_tf32(o[jj][1] * i0)};
        float2 v1 = {rna_tf32(o[jj][2] * i1), rna_tf32(o[jj][3] * i1)};
        *(float2*)(out0 + 8 * jj) = v0;
        *(float2*)(out1 + 8 * jj) = v1;
    }
}

// ---------------------------------------------------------------------------
extern "C" void kernel_launch(void* const* d_in, const int* in_sizes, int n_in,
                              void* d_out, int out_size)
{
    (void)in_sizes; (void)n_in; (void)out_size;
    const float* x     = (const float*)d_in[0];
    const float* W_qkv = (const float*)d_in[1];
    const float* b_qkv = (const float*)d_in[2];
    const float* W_out = (const float*)d_in[3];
    const float* b_out = (const float*)d_in[4];
    float* out = (float*)d_out;

    float *xt_ptr, *qkv_ptr, *att_ptr, *wqkvt_ptr, *woutt_ptr;
    cudaGetSymbolAddress((void**)&xt_ptr,    g_x_t32);
    cudaGetSymbolAddress((void**)&qkv_ptr,   g_qkv);
    cudaGetSymbolAddress((void**)&att_ptr,   g_att);
    cudaGetSymbolAddress((void**)&wqkvt_ptr, g_wqkv_t);
    cudaGetSymbolAddress((void**)&woutt_ptr, g_wout_t);
    __half *qh, *ql, *kh, *vh;
    cudaGetSymbolAddress((void**)&qh, g_q_hi);
    cudaGetSymbolAddress((void**)&ql, g_q_lo);
    cudaGetSymbolAddress((void**)&kh, g_k_hi);
    cudaGetSymbolAddress((void**)&vh, g_vt_hi);

    cudaFuncSetAttribute(gemm_tf32_kernel,
                         cudaFuncAttributeMaxDynamicSharedMemorySize, GEMM_SMEM);
    cudaFuncSetAttribute(flash_mma_kernel,
                         cudaFuncAttributeMaxDynamicSharedMemorySize, ATT_SMEM);

    // 0) Merged prologue
    prologue_kernel<<<4096 + (M_ * D_ / 4) / 256, 256>>>(
        W_qkv, wqkvt_ptr, W_out, woutt_ptr, (const float4*)x, (float4*)xt_ptr);

    // 1) QKV projection
    gemm_tf32_kernel<<<dim3(3 * D_ / 128, M_ / 128), 128, GEMM_SMEM>>>(
        xt_ptr, wqkvt_ptr, b_qkv, qkv_ptr, M_, 3 * D_, D_);

    // 2) Merged convert (Q: hi/lo; K, V: hi only)
    convert_kernel<<<8192 + (T_ / 32) * 2 * BH_, 256>>>(
        qkv_ptr, qh, ql, kh, vh);

    // 3) Causal attention (QK 2-term, PV 1-term, 2-array KV ring of 3)
    flash_mma_kernel<<<dim3(T_ / 128, BH_), 256, ATT_SMEM>>>(
        qh, ql, kh, vh, att_ptr);

    // 4) Output projection
    gemm_tf32_kernel<<<dim3(D_ / 128, M_ / 128), 128, GEMM_SMEM>>>(
        att_ptr, woutt_ptr, b_out, out, M_, D_, D_);
}

// round 16
// speedup vs baseline: 2.0262x; 1.3898x over previous
#include <cuda_runtime.h>
#include <cuda_fp16.h>
#include <cstdint>

#define B_  4
#define T_  2048
#define D_  1024
#define H_  16
#define DK_ 64
#define M_  (B_*T_)
#define BH_ (B_*H_)

// Scratch (allocation-free rule: module-scope device globals)
__device__ __half g_x_h[(size_t)M_ * D_];        // x in fp16
__device__ float  g_qkv[(size_t)M_ * 3 * D_];    // [B,T,3D] fp32 GEMM output
__device__ __half g_att[(size_t)M_ * D_];        // attention output, fp16
__device__ __half g_wqkv_h[(size_t)3 * D_ * D_]; // W_qkv^T [3D, D] fp16
__device__ __half g_wout_h[(size_t)D_ * D_];     // W_out^T [D, D] fp16
// half splits for attention: Q hi/lo, K hi only, V hi only
__device__ __half g_q_hi[(size_t)BH_ * T_ * DK_];
__device__ __half g_q_lo[(size_t)BH_ * T_ * DK_];
__device__ __half g_k_hi[(size_t)BH_ * T_ * DK_];
__device__ __half g_vt_hi[(size_t)BH_ * DK_ * T_];  // [bh][d][t]

// ---------------------------------------------------------------------------
// PTX helpers
// ---------------------------------------------------------------------------
__device__ __forceinline__ uint32_t smem_u32(const void* p) {
    uint32_t a;
    asm("{ .reg .u64 t; cvta.to.shared.u64 t, %1; cvt.u32.u64 %0, t; }"
        : "=r"(a) : "l"(p));
    return a;
}
__device__ __forceinline__ void cp_async16(uint32_t dst, const void* src) {
    asm volatile("cp.async.ca.shared.global [%0], [%1], 16;"
                 :: "r"(dst), "l"(src) : "memory");
}
__device__ __forceinline__ void cp_commit() {
    asm volatile("cp.async.commit_group;" ::: "memory");
}
__device__ __forceinline__ void cp_wait0() {
    asm volatile("cp.async.wait_group 0;" ::: "memory");
}
__device__ __forceinline__ void cp_wait1() {
    asm volatile("cp.async.wait_group 1;" ::: "memory");
}
__device__ __forceinline__ void cp_wait2() {
    asm volatile("cp.async.wait_group 2;" ::: "memory");
}
__device__ __forceinline__ float ex2f(float x) {
    float y;
    asm("ex2.approx.f32 %0, %1;" : "=f"(y) : "f"(x));
    return y;
}
__device__ __forceinline__ void mma16816(float (&c)[4], uint32_t a0, uint32_t a1,
                                         uint32_t a2, uint32_t a3,
                                         uint32_t b0, uint32_t b1) {
    asm volatile(
        "mma.sync.aligned.m16n8k16.row.col.f32.f16.f16.f32 "
        "{%0,%1,%2,%3}, {%4,%5,%6,%7}, {%8,%9}, {%0,%1,%2,%3};"
        : "+f"(c[0]), "+f"(c[1]), "+f"(c[2]), "+f"(c[3])
        : "r"(a0), "r"(a1), "r"(a2), "r"(a3), "r"(b0), "r"(b1));
}

// split one float4 into half hi/lo pairs and store
__device__ __forceinline__ void split_store4(float4 v, __half* hi, __half* lo,
                                             size_t o) {
    __half2 h0 = __floats2half2_rn(v.x, v.y);
    __half2 h1 = __floats2half2_rn(v.z, v.w);
    float2 f0 = __half22float2(h0), f1 = __half22float2(h1);
    __half2 l0 = __floats2half2_rn(v.x - f0.x, v.y - f0.y);
    __half2 l1 = __floats2half2_rn(v.z - f1.x, v.w - f1.y);
    *(__half2*)(hi + o)     = h0;
    *(__half2*)(hi + o + 2) = h1;
    *(__half2*)(lo + o)     = l0;
    *(__half2*)(lo + o + 2) = l1;
}

// ---------------------------------------------------------------------------
// Merged prologue: W_qkv transpose->fp16 | W_out transpose->fp16 | x->fp16.
//   [0, 3072)     : W_qkv^T tiles (96 x 32 of 32x32)
//   [3072, 4096)  : W_out^T tiles (32 x 32)
//   [4096, 12288) : x cvt (8192 blocks x 256 float4)
// ---------------------------------------------------------------------------
__global__ __launch_bounds__(256)
void prologue_kernel(const float* __restrict__ Wqkv, __half* __restrict__ WqkvH,
                     const float* __restrict__ Wout, __half* __restrict__ WoutH,
                     const float4* __restrict__ x, __half* __restrict__ xH)
{
    const int bid = blockIdx.x;
    const int tid = threadIdx.x;
    if (bid >= 4096) {
        const int i = (bid - 4096) * 256 + tid;
        float4 v = x[i];
        __half2 h0 = __floats2half2_rn(v.x, v.y);
        __half2 h1 = __floats2half2_rn(v.z, v.w);
        *(__half2*)(xH + (size_t)i * 4)     = h0;
        *(__half2*)(xH + (size_t)i * 4 + 2) = h1;
        return;
    }
    __shared__ float t[32][33];
    const float* in;
    __half* out;
    int bx, by, R, C;
    if (bid < 3072) {
        in = Wqkv; out = WqkvH; R = D_; C = 3 * D_;
        bx = (bid % 96) * 32; by = (bid / 96) * 32;
    } else {
        in = Wout; out = WoutH; R = D_; C = D_;
        const int t2 = bid - 3072;
        bx = (t2 % 32) * 32; by = (t2 / 32) * 32;
    }
    const int tx = tid & 31, ty = tid >> 5;
#pragma unroll
    for (int j = 0; j < 32; j += 8)
        t[ty + j][tx] = in[(size_t)(by + ty + j) * C + bx + tx];
    __syncthreads();
#pragma unroll
    for (int j = 0; j < 32; j += 8)
        out[(size_t)(bx + ty + j) * R + by + tx] = __float2half_rn(t[tx][ty + j]);
}

// ---------------------------------------------------------------------------
// fp16 GEMM: C[M,N] = A[M,K] @ Bt[N,K]^T + bias[N]  (A, Bt fp16; C fp32)
// CTA 128x128, 128 thr = 4 warps (2Mx2N), warp tile 64x64, BK=32.
// Round-6 schedule: NSTAGE=4, per-chunk issue, cp_wait2, 1 barrier/chunk.
// Optional fp16 output (for QKV->none; used for nothing here, C fp32 always).
// ---------------------------------------------------------------------------
#define HPAD   20                        // u32 per row (16 data + 4 pad)
#define HTILE  (128 * HPAD)              // u32 per operand per stage
#define HSTW   (2 * HTILE)
#define NSTAGE 4
#define GEMM_SMEM (NSTAGE * HSTW * 4)    // 81920 B

__global__ __launch_bounds__(128, 2)
void gemm_f16_kernel(const __half* __restrict__ A,
                     const __half* __restrict__ Bt,
                     const float* __restrict__ bias,
                     float* __restrict__ C,
                     int M, int N, int K)
{
    extern __shared__ uint32_t smw[];
    const uint32_t sbase = smem_u32(smw);
    const int tid  = threadIdx.x;
    const int wid  = tid >> 5;
    const int lane = tid & 31;
    const int grp  = lane >> 2;
    const int tg   = lane & 3;
    const int warp_m = (wid & 1) * 64;
    const int warp_n = (wid >> 1) * 64;
    const int m0 = blockIdx.y * 128;
    const int n0 = blockIdx.x * 128;
    const int nk = K >> 5;               // chunks of BK=32

    const __half* Abase = A + (size_t)m0 * K;
    const __half* Bbase = Bt + (size_t)n0 * K;

    auto issue = [&](int i) {
        if (i < nk) {
            const int k0 = i << 5;       // halves
            const uint32_t st = sbase + ((i & (NSTAGE - 1)) * HSTW) * 4;
#pragma unroll
            for (int j = 0; j < 4; j++) {
                const int idx = tid + j * 128;           // 0..511
                const int r = idx >> 2, g = idx & 3;     // row, 8-half group
                cp_async16(st + (r * HPAD + g * 4) * 4,
                           Abase + (size_t)r * K + k0 + g * 8);
                cp_async16(st + (HTILE + r * HPAD + g * 4) * 4,
                           Bbase + (size_t)r * K + k0 + g * 8);
            }
        }
        cp_commit();
    };

    float acc[4][8][4];
#pragma unroll
    for (int i = 0; i < 4; i++)
#pragma unroll
        for (int j = 0; j < 8; j++)
#pragma unroll
            for (int r = 0; r < 4; r++) acc[i][j][r] = 0.f;

    issue(0); issue(1); issue(2);

    uint32_t a[2][4][4], b[2][8][2];

    for (int i = 0; i < nk; i++) {
        cp_wait2();
        __syncthreads();
        issue(i + 3);

        const uint32_t* Au = smw + (i & (NSTAGE - 1)) * HSTW;
        const uint32_t* Bu = Au + HTILE;

        // load ks=0 fragments (u32 cols tg, tg+4)
        {
            const int k0 = tg;
#pragma unroll
            for (int ii = 0; ii < 4; ii++) {
                const uint32_t* p0 = Au + (warp_m + 16 * ii + grp) * HPAD;
                const uint32_t* p1 = p0 + 8 * HPAD;
                a[0][ii][0] = p0[k0];
                a[0][ii][1] = p1[k0];
                a[0][ii][2] = p0[k0 + 4];
                a[0][ii][3] = p1[k0 + 4];
            }
#pragma unroll
            for (int jj = 0; jj < 8; jj++) {
                const uint32_t* pn = Bu + (warp_n + 8 * jj + grp) * HPAD;
                b[0][jj][0] = pn[k0];
                b[0][jj][1] = pn[k0 + 4];
            }
        }
#pragma unroll
        for (int ks = 0; ks < 2; ks++) {
            if (ks == 0) {      // prefetch ks=1 fragments (cols 8+tg, 8+tg+4)
                const int k0 = 8 + tg;
#pragma unroll
                for (int ii = 0; ii < 4; ii++) {
                    const uint32_t* p0 = Au + (warp_m + 16 * ii + grp) * HPAD;
                    const uint32_t* p1 = p0 + 8 * HPAD;
                    a[1][ii][0] = p0[k0];
                    a[1][ii][1] = p1[k0];
                    a[1][ii][2] = p0[k0 + 4];
                    a[1][ii][3] = p1[k0 + 4];
                }
#pragma unroll
                for (int jj = 0; jj < 8; jj++) {
                    const uint32_t* pn = Bu + (warp_n + 8 * jj + grp) * HPAD;
                    b[1][jj][0] = pn[k0];
                    b[1][jj][1] = pn[k0 + 4];
                }
            }
#pragma unroll
            for (int ii = 0; ii < 4; ii++)
#pragma unroll
                for (int jj = 0; jj < 8; jj++)
                    mma16816(acc[ii][jj], a[ks][ii][0], a[ks][ii][1],
                             a[ks][ii][2], a[ks][ii][3],
                             b[ks][jj][0], b[ks][jj][1]);
        }
    }

#pragma unroll
    for (int ii = 0; ii < 4; ii++) {
        const int m = m0 + warp_m + 16 * ii + grp;
#pragma unroll
        for (int jj = 0; jj < 8; jj++) {
            const int n = n0 + warp_n + 8 * jj + 2 * tg;
            const float bv0 = __ldg(&bias[n]);
            const float bv1 = __ldg(&bias[n + 1]);
            float2 v0 = {acc[ii][jj][0] + bv0, acc[ii][jj][1] + bv1};
            float2 v1 = {acc[ii][jj][2] + bv0, acc[ii][jj][3] + bv1};
            *(float2*)(C + (size_t)m * N + n)       = v0;
            *(float2*)(C + (size_t)(m + 8) * N + n) = v1;
        }
    }
}

// ---------------------------------------------------------------------------
// Merged convert: Q split hi/lo, K hi only (blocks [0,8192)) | V hi (rest).
// ---------------------------------------------------------------------------
__global__ __launch_bounds__(256)
void convert_kernel(const float* __restrict__ qkv,
                    __half* __restrict__ qh, __half* __restrict__ ql,
                    __half* __restrict__ kh, __half* __restrict__ vh)
{
    const int bid = blockIdx.x;
    const int tid = threadIdx.x;
    if (bid < 8192) {
        int i = bid * 256 + tid;
        int c4 = i & 15;
        int t  = (i >> 4) & (T_ - 1);
        int bh = i >> 15;
        int b = bh >> 4, h = bh & 15;
        const float4* src = (const float4*)(qkv + ((size_t)(b * T_ + t)) * 3 * D_);
        float4 q4 = src[h * 16 + c4];
        float4 k4 = src[256 + h * 16 + c4];
        size_t o = ((size_t)bh * T_ + t) * 64 + c4 * 4;
        split_store4(q4, qh, ql, o);
        __half2 kh0 = __floats2half2_rn(k4.x, k4.y);
        __half2 kh1 = __floats2half2_rn(k4.z, k4.w);
        *(__half2*)(kh + o)     = kh0;
        *(__half2*)(kh + o + 2) = kh1;
        return;
    }
    __shared__ float tile[32][33];
    const int vb = bid - 8192;
    const int t0 = (vb % (T_ / 32)) * 32;
    const int d0 = ((vb / (T_ / 32)) & 1) * 32;
    const int bh = vb / (T_ / 32) / 2;
    const int b = bh >> 4, h = bh & 15;
    const int tx = tid & 31, ty = tid >> 5;
#pragma unroll
    for (int j = 0; j < 32; j += 8)
        tile[ty + j][tx] = qkv[((size_t)(b * T_ + t0 + ty + j)) * 3 * D_
                               + 2 * D_ + h * 64 + d0 + tx];
    __syncthreads();
#pragma unroll
    for (int j = 0; j < 32; j += 8) {
        int d = d0 + ty + j;
        size_t o = ((size_t)bh * DK_ + d) * T_ + t0 + tx;
        vh[o] = __float2half_rn(tile[tx][ty + j]);
    }
}

// ---------------------------------------------------------------------------
// Flash attention (round-15 proven): QK 2-term (qh+ql)*kh, PV 1-term.
// Epilogue now stores fp16 (att feeds the fp16 out-proj).
// ---------------------------------------------------------------------------
#define AW   36
#define KVW  (64 * AW)
#define BUFW (2 * KVW)
#define ATT_SMEM (3 * BUFW * 4)          // 55296 B

__global__ __launch_bounds__(256, 2)
void flash_mma_kernel(const __half* __restrict__ qh_g, const __half* __restrict__ ql_g,
                      const __half* __restrict__ kh_g,
                      const __half* __restrict__ vh_g,
                      __half* __restrict__ out)
{
    extern __shared__ uint32_t smw[];
    const uint32_t sbase = smem_u32(smw);
    const int tid = threadIdx.x, wid = tid >> 5, lane = tid & 31;
    const int grp = lane >> 2, tg = lane & 3;
    const int bh = blockIdx.y, b = bh >> 4, h = bh & 15;
    const int qt = gridDim.x - 1 - blockIdx.x;
    const int q0 = qt * 128;
    const int wm = wid * 16;
    const int row0 = q0 + wm + grp;
    const int row1 = row0 + 8;

    {
        const uint4* qh4 = (const uint4*)(qh_g + (size_t)bh * T_ * DK_) + q0 * 8;
        const uint4* ql4 = (const uint4*)(ql_g + (size_t)bh * T_ * DK_) + q0 * 8;
#pragma unroll
        for (int j = 0; j < 4; j++) {
            int idx = tid + j * 256;
            int r = idx >> 3, c = idx & 7;
            uint32_t dst = sbase + (r * AW + c * 4) * 4;
            cp_async16(dst, qh4 + r * 8 + c);
            cp_async16(dst + 4608 * 4, ql4 + r * 8 + c);
        }
        cp_commit(); cp_wait0();
        __syncthreads();
    }
    uint32_t qfh[4][4], qfl[4][4];
    {
        const uint32_t* Q = smw;
        const int base = (wm + grp) * AW + tg;
#pragma unroll
        for (int kc = 0; kc < 4; kc++) {
            qfh[kc][0] = Q[base + 8 * kc];
            qfh[kc][1] = Q[base + 8 * AW + 8 * kc];
            qfh[kc][2] = Q[base + 8 * kc + 4];
            qfh[kc][3] = Q[base + 8 * AW + 8 * kc + 4];
            qfl[kc][0] = Q[4608 + base + 8 * kc];
            qfl[kc][1] = Q[4608 + base + 8 * AW + 8 * kc];
            qfl[kc][2] = Q[4608 + base + 8 * kc + 4];
            qfl[kc][3] = Q[4608 + base + 8 * AW + 8 * kc + 4];
        }
    }
    __syncthreads();

    const uint4* kh4 = (const uint4*)(kh_g + (size_t)bh * T_ * DK_);
    const uint4* vh4 = (const uint4*)(vh_g + (size_t)bh * DK_ * T_);

    auto kv_load = [&](int t, int buf) {
        const int kv0 = t * 64;
#pragma unroll
        for (int j = 0; j < 2; j++) {
            int idx = tid + j * 256;
            int r = idx >> 3, c = idx & 7;
            uint32_t dst = sbase + (buf * BUFW + r * AW + c * 4) * 4;
            cp_async16(dst,           kh4 + (kv0 + r) * 8 + c);
            cp_async16(dst + KVW * 4, vh4 + (size_t)r * (T_ / 8) + kv0 / 8 + c);
        }
    };

    float o[8][4];
#pragma unroll
    for (int j = 0; j < 8; j++)
#pragma unroll
        for (int e = 0; e < 4; e++) o[j][e] = 0.f;
    float m0 = -1e30f, m1 = -1e30f, l0 = 0.f, l1 = 0.f;

    const int nt = 2 * (qt + 1);
    kv_load(0, 0); cp_commit();
    kv_load(1, 1); cp_commit();

    int bc = 0, bn = 2;
    for (int t = 0; t < nt; t++) {
        cp_wait1();
        __syncthreads();
        if (t + 2 < nt) kv_load(t + 2, bn);
        cp_commit();

        const uint32_t* Kh = smw + bc * BUFW;
        const uint32_t* Vh = Kh + KVW;

        float s[8][4];
#pragma unroll
        for (int j = 0; j < 8; j++)
#pragma unroll
            for (int e = 0; e < 4; e++) s[j][e] = 0.f;
#pragma unroll
        for (int kc = 0; kc < 4; kc++) {
            const int bo = 8 * kc + tg;
#pragma unroll
            for (int j = 0; j < 8; j++) {
                const int nb = (8 * j + grp) * AW + bo;
                uint32_t b0h = Kh[nb], b1h = Kh[nb + 4];
                mma16816(s[j], qfh[kc][0], qfh[kc][1], qfh[kc][2], qfh[kc][3], b0h, b1h);
                mma16816(s[j], qfl[kc][0], qfl[kc][1], qfl[kc][2], qfl[kc][3], b0h, b1h);
            }
        }

        const int kv0 = t * 64;
        const float cs = 0.125f * 1.4426950408889634f;
        const bool maskw = (kv0 + 63 > q0 + wm);
        float mx0 = -1e30f, mx1 = -1e30f;
#pragma unroll
        for (int j = 0; j < 8; j++) {
            const int c0 = kv0 + 8 * j + 2 * tg;
            float x0 = s[j][0] * cs, x1 = s[j][1] * cs;
            float x2 = s[j][2] * cs, x3 = s[j][3] * cs;
            if (maskw) {
                if (c0 > row0)     x0 = -1e30f;
                if (c0 + 1 > row0) x1 = -1e30f;
                if (c0 > row1)     x2 = -1e30f;
                if (c0 + 1 > row1) x3 = -1e30f;
            }
            s[j][0] = x0; s[j][1] = x1; s[j][2] = x2; s[j][3] = x3;
            mx0 = fmaxf(mx0, fmaxf(x0, x1));
            mx1 = fmaxf(mx1, fmaxf(x2, x3));
        }
        mx0 = fmaxf(mx0, __shfl_xor_sync(0xffffffffu, mx0, 1));
        mx0 = fmaxf(mx0, __shfl_xor_sync(0xffffffffu, mx0, 2));
        mx1 = fmaxf(mx1, __shfl_xor_sync(0xffffffffu, mx1, 1));
        mx1 = fmaxf(mx1, __shfl_xor_sync(0xffffffffu, mx1, 2));
        const float mn0 = fmaxf(m0, mx0), mn1 = fmaxf(m1, mx1);
        const float a0 = ex2f(m0 - mn0),  a1 = ex2f(m1 - mn1);
        m0 = mn0; m1 = mn1;

        float sum0 = 0.f, sum1 = 0.f;
#pragma unroll
        for (int j = 0; j < 8; j++) {
            float p0 = ex2f(s[j][0] - m0), p1 = ex2f(s[j][1] - m0);
            float p2 = ex2f(s[j][2] - m1), p3 = ex2f(s[j][3] - m1);
            s[j][0] = p0; s[j][1] = p1; s[j][2] = p2; s[j][3] = p3;
            sum0 += p0 + p1; sum1 += p2 + p3;
        }
        sum0 += __shfl_xor_sync(0xffffffffu, sum0, 1);
        sum0 += __shfl_xor_sync(0xffffffffu, sum0, 2);
        sum1 += __shfl_xor_sync(0xffffffffu, sum1, 1);
        sum1 += __shfl_xor_sync(0xffffffffu, sum1, 2);
        l0 = l0 * a0 + sum0;
        l1 = l1 * a1 + sum1;
#pragma unroll
        for (int j = 0; j < 8; j++) {
            o[j][0] *= a0; o[j][1] *= a0; o[j][2] *= a1; o[j][3] *= a1;
        }

#pragma unroll
        for (int kc = 0; kc < 4; kc++) {
            const int j0 = 2 * kc, j1 = 2 * kc + 1;
            __half2 A0 = __floats2half2_rn(s[j0][0], s[j0][1]);
            __half2 A1 = __floats2half2_rn(s[j0][2], s[j0][3]);
            __half2 A2 = __floats2half2_rn(s[j1][0], s[j1][1]);
            __half2 A3 = __floats2half2_rn(s[j1][2], s[j1][3]);
            const uint32_t ph0 = *(uint32_t*)&A0, ph1 = *(uint32_t*)&A1;
            const uint32_t ph2 = *(uint32_t*)&A2, ph3 = *(uint32_t*)&A3;
            const int bo = 8 * kc + tg;
#pragma unroll
            for (int jj = 0; jj < 8; jj++) {
                const int nb = (8 * jj + grp) * AW + bo;
                mma16816(o[jj], ph0, ph1, ph2, ph3, Vh[nb], Vh[nb + 4]);
            }
        }

        bc = (bc == 2) ? 0 : bc + 1;
        bn = (bn == 2) ? 0 : bn + 1;
    }

    // epilogue: fp16 store (out-proj consumes fp16 A directly)
    const float i0 = 1.0f / l0, i1 = 1.0f / l1;
    __half* out0 = out + ((size_t)(b * T_ + row0)) * D_ + h * 64 + 2 * tg;
    __half* out1 = out + ((size_t)(b * T_ + row1)) * D_ + h * 64 + 2 * tg;
#pragma unroll
    for (int jj = 0; jj < 8; jj++) {
        *(__half2*)(out0 + 8 * jj) = __floats2half2_rn(o[jj][0] * i0, o[jj][1] * i0);
        *(__half2*)(out1 + 8 * jj) = __floats2half2_rn(o[jj][2] * i1, o[jj][3] * i1);
    }
}

// ---------------------------------------------------------------------------
extern "C" void kernel_launch(void* const* d_in, const int* in_sizes, int n_in,
                              void* d_out, int out_size)
{
    (void)in_sizes; (void)n_in; (void)out_size;
    const float* x     = (const float*)d_in[0];
    const float* W_qkv = (const float*)d_in[1];
    const float* b_qkv = (const float*)d_in[2];
    const float* W_out = (const float*)d_in[3];
    const float* b_out = (const float*)d_in[4];
    float* out = (float*)d_out;

    float* qkv_ptr;
    __half *xh_ptr, *att_ptr, *wqkvh_ptr, *wouth_ptr;
    cudaGetSymbolAddress((void**)&xh_ptr,    g_x_h);
    cudaGetSymbolAddress((void**)&qkv_ptr,   g_qkv);
    cudaGetSymbolAddress((void**)&att_ptr,   g_att);
    cudaGetSymbolAddress((void**)&wqkvh_ptr, g_wqkv_h);
    cudaGetSymbolAddress((void**)&wouth_ptr, g_wout_h);
    __half *qh, *ql, *kh, *vh;
    cudaGetSymbolAddress((void**)&qh, g_q_hi);
    cudaGetSymbolAddress((void**)&ql, g_q_lo);
    cudaGetSymbolAddress((void**)&kh, g_k_hi);
    cudaGetSymbolAddress((void**)&vh, g_vt_hi);

    cudaFuncSetAttribute(gemm_f16_kernel,
                         cudaFuncAttributeMaxDynamicSharedMemorySize, GEMM_SMEM);
    cudaFuncSetAttribute(flash_mma_kernel,
                         cudaFuncAttributeMaxDynamicSharedMemorySize, ATT_SMEM);

    // 0) Merged prologue: weights transpose->fp16, x->fp16
    prologue_kernel<<<4096 + (M_ * D_ / 4) / 256, 256>>>(
        W_qkv, wqkvh_ptr, W_out, wouth_ptr, (const float4*)x, xh_ptr);

    // 1) QKV projection (fp16 mma, BK=32)
    gemm_f16_kernel<<<dim3(3 * D_ / 128, M_ / 128), 128, GEMM_SMEM>>>(
        xh_ptr, wqkvh_ptr, b_qkv, qkv_ptr, M_, 3 * D_, D_);

    // 2) Merged convert (Q: hi/lo; K, V: hi only)
    convert_kernel<<<8192 + (T_ / 32) * 2 * BH_, 256>>>(
        qkv_ptr, qh, ql, kh, vh);

    // 3) Causal attention (QK 2-term, PV 1-term; fp16 output)
    flash_mma_kernel<<<dim3(T_ / 128, BH_), 256, ATT_SMEM>>>(
        qh, ql, kh, vh, att_ptr);

    // 4) Output projection (fp16 mma)
    gemm_f16_kernel<<<dim3(D_ / 128, M_ / 128), 128, GEMM_SMEM>>>(
        att_ptr, wouth_ptr, b_out, out, M_, D_, D_);
}

// round 17
// speedup vs baseline: 2.2062x; 1.0888x over previous
#include <cuda_runtime.h>
#include <cuda_fp16.h>
#include <cstdint>

#define B_  4
#define T_  2048
#define D_  1024
#define H_  16
#define DK_ 64
#define M_  (B_*T_)
#define BH_ (B_*H_)

// Scratch (allocation-free rule: module-scope device globals)
__device__ __half g_x_h[(size_t)M_ * D_];        // x in fp16
__device__ float  g_qkv[(size_t)M_ * 3 * D_];    // [B,T,3D] fp32 GEMM output
__device__ __half g_att[(size_t)M_ * D_];        // attention output, fp16
__device__ __half g_wqkv_h[(size_t)3 * D_ * D_]; // W_qkv^T [3D, D] fp16
__device__ __half g_wout_h[(size_t)D_ * D_];     // W_out^T [D, D] fp16
// fp16 attention operands (no splits remaining)
__device__ __half g_q_hi[(size_t)BH_ * T_ * DK_];
__device__ __half g_k_hi[(size_t)BH_ * T_ * DK_];
__device__ __half g_vt_hi[(size_t)BH_ * DK_ * T_];  // [bh][d][t]

// ---------------------------------------------------------------------------
// PTX helpers
// ---------------------------------------------------------------------------
__device__ __forceinline__ uint32_t smem_u32(const void* p) {
    uint32_t a;
    asm("{ .reg .u64 t; cvta.to.shared.u64 t, %1; cvt.u32.u64 %0, t; }"
        : "=r"(a) : "l"(p));
    return a;
}
__device__ __forceinline__ void cp_async16(uint32_t dst, const void* src) {
    asm volatile("cp.async.ca.shared.global [%0], [%1], 16;"
                 :: "r"(dst), "l"(src) : "memory");
}
__device__ __forceinline__ void cp_commit() {
    asm volatile("cp.async.commit_group;" ::: "memory");
}
__device__ __forceinline__ void cp_wait0() {
    asm volatile("cp.async.wait_group 0;" ::: "memory");
}
__device__ __forceinline__ void cp_wait1() {
    asm volatile("cp.async.wait_group 1;" ::: "memory");
}
__device__ __forceinline__ void cp_wait2() {
    asm volatile("cp.async.wait_group 2;" ::: "memory");
}
__device__ __forceinline__ float ex2f(float x) {
    float y;
    asm("ex2.approx.f32 %0, %1;" : "=f"(y) : "f"(x));
    return y;
}
__device__ __forceinline__ void mma16816(float (&c)[4], uint32_t a0, uint32_t a1,
                                         uint32_t a2, uint32_t a3,
                                         uint32_t b0, uint32_t b1) {
    asm volatile(
        "mma.sync.aligned.m16n8k16.row.col.f32.f16.f16.f32 "
        "{%0,%1,%2,%3}, {%4,%5,%6,%7}, {%8,%9}, {%0,%1,%2,%3};"
        : "+f"(c[0]), "+f"(c[1]), "+f"(c[2]), "+f"(c[3])
        : "r"(a0), "r"(a1), "r"(a2), "r"(a3), "r"(b0), "r"(b1));
}

// ---------------------------------------------------------------------------
// Merged prologue: W_qkv transpose->fp16 | W_out transpose->fp16 | x->fp16.
// ---------------------------------------------------------------------------
__global__ __launch_bounds__(256)
void prologue_kernel(const float* __restrict__ Wqkv, __half* __restrict__ WqkvH,
                     const float* __restrict__ Wout, __half* __restrict__ WoutH,
                     const float4* __restrict__ x, __half* __restrict__ xH)
{
    const int bid = blockIdx.x;
    const int tid = threadIdx.x;
    if (bid >= 4096) {
        const int i = (bid - 4096) * 256 + tid;
        float4 v = x[i];
        __half2 h0 = __floats2half2_rn(v.x, v.y);
        __half2 h1 = __floats2half2_rn(v.z, v.w);
        *(__half2*)(xH + (size_t)i * 4)     = h0;
        *(__half2*)(xH + (size_t)i * 4 + 2) = h1;
        return;
    }
    __shared__ float t[32][33];
    const float* in;
    __half* out;
    int bx, by, R, C;
    if (bid < 3072) {
        in = Wqkv; out = WqkvH; R = D_; C = 3 * D_;
        bx = (bid % 96) * 32; by = (bid / 96) * 32;
    } else {
        in = Wout; out = WoutH; R = D_; C = D_;
        const int t2 = bid - 3072;
        bx = (t2 % 32) * 32; by = (t2 / 32) * 32;
    }
    const int tx = tid & 31, ty = tid >> 5;
#pragma unroll
    for (int j = 0; j < 32; j += 8)
        t[ty + j][tx] = in[(size_t)(by + ty + j) * C + bx + tx];
    __syncthreads();
#pragma unroll
    for (int j = 0; j < 32; j += 8)
        out[(size_t)(bx + ty + j) * R + by + tx] = __float2half_rn(t[tx][ty + j]);
}

// ---------------------------------------------------------------------------
// fp16 GEMM (round-16 proven): C[M,N] = A[M,K] @ Bt[N,K]^T + bias[N]
// ---------------------------------------------------------------------------
#define HPAD   20
#define HTILE  (128 * HPAD)
#define HSTW   (2 * HTILE)
#define NSTAGE 4
#define GEMM_SMEM (NSTAGE * HSTW * 4)    // 81920 B

__global__ __launch_bounds__(128, 2)
void gemm_f16_kernel(const __half* __restrict__ A,
                     const __half* __restrict__ Bt,
                     const float* __restrict__ bias,
                     float* __restrict__ C,
                     int M, int N, int K)
{
    extern __shared__ uint32_t smw[];
    const uint32_t sbase = smem_u32(smw);
    const int tid  = threadIdx.x;
    const int wid  = tid >> 5;
    const int lane = tid & 31;
    const int grp  = lane >> 2;
    const int tg   = lane & 3;
    const int warp_m = (wid & 1) * 64;
    const int warp_n = (wid >> 1) * 64;
    const int m0 = blockIdx.y * 128;
    const int n0 = blockIdx.x * 128;
    const int nk = K >> 5;

    const __half* Abase = A + (size_t)m0 * K;
    const __half* Bbase = Bt + (size_t)n0 * K;

    auto issue = [&](int i) {
        if (i < nk) {
            const int k0 = i << 5;
            const uint32_t st = sbase + ((i & (NSTAGE - 1)) * HSTW) * 4;
#pragma unroll
            for (int j = 0; j < 4; j++) {
                const int idx = tid + j * 128;
                const int r = idx >> 2, g = idx & 3;
                cp_async16(st + (r * HPAD + g * 4) * 4,
                           Abase + (size_t)r * K + k0 + g * 8);
                cp_async16(st + (HTILE + r * HPAD + g * 4) * 4,
                           Bbase + (size_t)r * K + k0 + g * 8);
            }
        }
        cp_commit();
    };

    float acc[4][8][4];
#pragma unroll
    for (int i = 0; i < 4; i++)
#pragma unroll
        for (int j = 0; j < 8; j++)
#pragma unroll
            for (int r = 0; r < 4; r++) acc[i][j][r] = 0.f;

    issue(0); issue(1); issue(2);

    uint32_t a[2][4][4], b[2][8][2];

    for (int i = 0; i < nk; i++) {
        cp_wait2();
        __syncthreads();
        issue(i + 3);

        const uint32_t* Au = smw + (i & (NSTAGE - 1)) * HSTW;
        const uint32_t* Bu = Au + HTILE;

        {
            const int k0 = tg;
#pragma unroll
            for (int ii = 0; ii < 4; ii++) {
                const uint32_t* p0 = Au + (warp_m + 16 * ii + grp) * HPAD;
                const uint32_t* p1 = p0 + 8 * HPAD;
                a[0][ii][0] = p0[k0];
                a[0][ii][1] = p1[k0];
                a[0][ii][2] = p0[k0 + 4];
                a[0][ii][3] = p1[k0 + 4];
            }
#pragma unroll
            for (int jj = 0; jj < 8; jj++) {
                const uint32_t* pn = Bu + (warp_n + 8 * jj + grp) * HPAD;
                b[0][jj][0] = pn[k0];
                b[0][jj][1] = pn[k0 + 4];
            }
        }
#pragma unroll
        for (int ks = 0; ks < 2; ks++) {
            if (ks == 0) {
                const int k0 = 8 + tg;
#pragma unroll
                for (int ii = 0; ii < 4; ii++) {
                    const uint32_t* p0 = Au + (warp_m + 16 * ii + grp) * HPAD;
                    const uint32_t* p1 = p0 + 8 * HPAD;
                    a[1][ii][0] = p0[k0];
                    a[1][ii][1] = p1[k0];
                    a[1][ii][2] = p0[k0 + 4];
                    a[1][ii][3] = p1[k0 + 4];
                }
#pragma unroll
                for (int jj = 0; jj < 8; jj++) {
                    const uint32_t* pn = Bu + (warp_n + 8 * jj + grp) * HPAD;
                    b[1][jj][0] = pn[k0];
                    b[1][jj][1] = pn[k0 + 4];
                }
            }
#pragma unroll
            for (int ii = 0; ii < 4; ii++)
#pragma unroll
                for (int jj = 0; jj < 8; jj++)
                    mma16816(acc[ii][jj], a[ks][ii][0], a[ks][ii][1],
                             a[ks][ii][2], a[ks][ii][3],
                             b[ks][jj][0], b[ks][jj][1]);
        }
    }

#pragma unroll
    for (int ii = 0; ii < 4; ii++) {
        const int m = m0 + warp_m + 16 * ii + grp;
#pragma unroll
        for (int jj = 0; jj < 8; jj++) {
            const int n = n0 + warp_n + 8 * jj + 2 * tg;
            const float bv0 = __ldg(&bias[n]);
            const float bv1 = __ldg(&bias[n + 1]);
            float2 v0 = {acc[ii][jj][0] + bv0, acc[ii][jj][1] + bv1};
            float2 v1 = {acc[ii][jj][2] + bv0, acc[ii][jj][3] + bv1};
            *(float2*)(C + (size_t)m * N + n)       = v0;
            *(float2*)(C + (size_t)(m + 8) * N + n) = v1;
        }
    }
}

// ---------------------------------------------------------------------------
// Merged convert: Q, K fp16 (blocks [0, 8192)) | V transpose fp16 (rest).
// ---------------------------------------------------------------------------
__global__ __launch_bounds__(256)
void convert_kernel(const float* __restrict__ qkv,
                    __half* __restrict__ qh,
                    __half* __restrict__ kh, __half* __restrict__ vh)
{
    const int bid = blockIdx.x;
    const int tid = threadIdx.x;
    if (bid < 8192) {
        int i = bid * 256 + tid;
        int c4 = i & 15;
        int t  = (i >> 4) & (T_ - 1);
        int bh = i >> 15;
        int b = bh >> 4, h = bh & 15;
        const float4* src = (const float4*)(qkv + ((size_t)(b * T_ + t)) * 3 * D_);
        float4 q4 = src[h * 16 + c4];
        float4 k4 = src[256 + h * 16 + c4];
        size_t o = ((size_t)bh * T_ + t) * 64 + c4 * 4;
        *(__half2*)(qh + o)     = __floats2half2_rn(q4.x, q4.y);
        *(__half2*)(qh + o + 2) = __floats2half2_rn(q4.z, q4.w);
        *(__half2*)(kh + o)     = __floats2half2_rn(k4.x, k4.y);
        *(__half2*)(kh + o + 2) = __floats2half2_rn(k4.z, k4.w);
        return;
    }
    __shared__ float tile[32][33];
    const int vb = bid - 8192;
    const int t0 = (vb % (T_ / 32)) * 32;
    const int d0 = ((vb / (T_ / 32)) & 1) * 32;
    const int bh = vb / (T_ / 32) / 2;
    const int b = bh >> 4, h = bh & 15;
    const int tx = tid & 31, ty = tid >> 5;
#pragma unroll
    for (int j = 0; j < 32; j += 8)
        tile[ty + j][tx] = qkv[((size_t)(b * T_ + t0 + ty + j)) * 3 * D_
                               + 2 * D_ + h * 64 + d0 + tx];
    __syncthreads();
#pragma unroll
    for (int j = 0; j < 32; j += 8) {
        int d = d0 + ty + j;
        size_t o = ((size_t)bh * DK_ + d) * T_ + t0 + tx;
        vh[o] = __float2half_rn(tile[tx][ty + j]);
    }
}

// ---------------------------------------------------------------------------
// Flash attention, plain fp16 mma: QK 1-term, PV 1-term.
// KV buffer = Kh|Vh (2 arrays). Ring of 3, ONE barrier per kv tile.
// ---------------------------------------------------------------------------
#define AW   36
#define KVW  (64 * AW)
#define BUFW (2 * KVW)
#define ATT_SMEM (3 * BUFW * 4)          // 55296 B

__global__ __launch_bounds__(256, 2)
void flash_mma_kernel(const __half* __restrict__ qh_g,
                      const __half* __restrict__ kh_g,
                      const __half* __restrict__ vh_g,
                      __half* __restrict__ out)
{
    extern __shared__ uint32_t smw[];
    const uint32_t sbase = smem_u32(smw);
    const int tid = threadIdx.x, wid = tid >> 5, lane = tid & 31;
    const int grp = lane >> 2, tg = lane & 3;
    const int bh = blockIdx.y, b = bh >> 4, h = bh & 15;
    const int qt = gridDim.x - 1 - blockIdx.x;
    const int q0 = qt * 128;
    const int wm = wid * 16;
    const int row0 = q0 + wm + grp;
    const int row1 = row0 + 8;

    // stage Q at smem base, lift fragments, then release
    {
        const uint4* qh4 = (const uint4*)(qh_g + (size_t)bh * T_ * DK_) + q0 * 8;
#pragma unroll
        for (int j = 0; j < 4; j++) {
            int idx = tid + j * 256;
            int r = idx >> 3, c = idx & 7;
            cp_async16(sbase + (r * AW + c * 4) * 4, qh4 + r * 8 + c);
        }
        cp_commit(); cp_wait0();
        __syncthreads();
    }
    uint32_t qf[4][4];
    {
        const uint32_t* Q = smw;
        const int base = (wm + grp) * AW + tg;
#pragma unroll
        for (int kc = 0; kc < 4; kc++) {
            qf[kc][0] = Q[base + 8 * kc];
            qf[kc][1] = Q[base + 8 * AW + 8 * kc];
            qf[kc][2] = Q[base + 8 * kc + 4];
            qf[kc][3] = Q[base + 8 * AW + 8 * kc + 4];
        }
    }
    __syncthreads();    // Q staging region becomes KV buffers

    const uint4* kh4 = (const uint4*)(kh_g + (size_t)bh * T_ * DK_);
    const uint4* vh4 = (const uint4*)(vh_g + (size_t)bh * DK_ * T_);

    auto kv_load = [&](int t, int buf) {
        const int kv0 = t * 64;
#pragma unroll
        for (int j = 0; j < 2; j++) {
            int idx = tid + j * 256;
            int r = idx >> 3, c = idx & 7;
            uint32_t dst = sbase + (buf * BUFW + r * AW + c * 4) * 4;
            cp_async16(dst,           kh4 + (kv0 + r) * 8 + c);
            cp_async16(dst + KVW * 4, vh4 + (size_t)r * (T_ / 8) + kv0 / 8 + c);
        }
    };

    float o[8][4];
#pragma unroll
    for (int j = 0; j < 8; j++)
#pragma unroll
        for (int e = 0; e < 4; e++) o[j][e] = 0.f;
    float m0 = -1e30f, m1 = -1e30f, l0 = 0.f, l1 = 0.f;

    const int nt = 2 * (qt + 1);
    kv_load(0, 0); cp_commit();
    kv_load(1, 1); cp_commit();

    int bc = 0, bn = 2;
    for (int t = 0; t < nt; t++) {
        cp_wait1();
        __syncthreads();
        if (t + 2 < nt) kv_load(t + 2, bn);
        cp_commit();

        const uint32_t* Kh = smw + bc * BUFW;
        const uint32_t* Vh = Kh + KVW;

        // ---- S = Q K^T (1-term)
        float s[8][4];
#pragma unroll
        for (int j = 0; j < 8; j++)
#pragma unroll
            for (int e = 0; e < 4; e++) s[j][e] = 0.f;
#pragma unroll
        for (int kc = 0; kc < 4; kc++) {
            const int bo = 8 * kc + tg;
#pragma unroll
            for (int j = 0; j < 8; j++) {
                const int nb = (8 * j + grp) * AW + bo;
                mma16816(s[j], qf[kc][0], qf[kc][1], qf[kc][2], qf[kc][3],
                         Kh[nb], Kh[nb + 4]);
            }
        }

        // ---- online softmax (base-2)
        const int kv0 = t * 64;
        const float cs = 0.125f * 1.4426950408889634f;
        const bool maskw = (kv0 + 63 > q0 + wm);
        float mx0 = -1e30f, mx1 = -1e30f;
#pragma unroll
        for (int j = 0; j < 8; j++) {
            const int c0 = kv0 + 8 * j + 2 * tg;
            float x0 = s[j][0] * cs, x1 = s[j][1] * cs;
            float x2 = s[j][2] * cs, x3 = s[j][3] * cs;
            if (maskw) {
                if (c0 > row0)     x0 = -1e30f;
                if (c0 + 1 > row0) x1 = -1e30f;
                if (c0 > row1)     x2 = -1e30f;
                if (c0 + 1 > row1) x3 = -1e30f;
            }
            s[j][0] = x0; s[j][1] = x1; s[j][2] = x2; s[j][3] = x3;
            mx0 = fmaxf(mx0, fmaxf(x0, x1));
            mx1 = fmaxf(mx1, fmaxf(x2, x3));
        }
        mx0 = fmaxf(mx0, __shfl_xor_sync(0xffffffffu, mx0, 1));
        mx0 = fmaxf(mx0, __shfl_xor_sync(0xffffffffu, mx0, 2));
        mx1 = fmaxf(mx1, __shfl_xor_sync(0xffffffffu, mx1, 1));
        mx1 = fmaxf(mx1, __shfl_xor_sync(0xffffffffu, mx1, 2));
        const float mn0 = fmaxf(m0, mx0), mn1 = fmaxf(m1, mx1);
        const float a0 = ex2f(m0 - mn0),  a1 = ex2f(m1 - mn1);
        m0 = mn0; m1 = mn1;

        float sum0 = 0.f, sum1 = 0.f;
#pragma unroll
        for (int j = 0; j < 8; j++) {
            float p0 = ex2f(s[j][0] - m0), p1 = ex2f(s[j][1] - m0);
            float p2 = ex2f(s[j][2] - m1), p3 = ex2f(s[j][3] - m1);
            s[j][0] = p0; s[j][1] = p1; s[j][2] = p2; s[j][3] = p3;
            sum0 += p0 + p1; sum1 += p2 + p3;
        }
        sum0 += __shfl_xor_sync(0xffffffffu, sum0, 1);
        sum0 += __shfl_xor_sync(0xffffffffu, sum0, 2);
        sum1 += __shfl_xor_sync(0xffffffffu, sum1, 1);
        sum1 += __shfl_xor_sync(0xffffffffu, sum1, 2);
        l0 = l0 * a0 + sum0;
        l1 = l1 * a1 + sum1;
#pragma unroll
        for (int j = 0; j < 8; j++) {
            o[j][0] *= a0; o[j][1] *= a0; o[j][2] *= a1; o[j][3] *= a1;
        }

        // ---- O += P V (1-term)
#pragma unroll
        for (int kc = 0; kc < 4; kc++) {
            const int j0 = 2 * kc, j1 = 2 * kc + 1;
            __half2 A0 = __floats2half2_rn(s[j0][0], s[j0][1]);
            __half2 A1 = __floats2half2_rn(s[j0][2], s[j0][3]);
            __half2 A2 = __floats2half2_rn(s[j1][0], s[j1][1]);
            __half2 A3 = __floats2half2_rn(s[j1][2], s[j1][3]);
            const uint32_t ph0 = *(uint32_t*)&A0, ph1 = *(uint32_t*)&A1;
            const uint32_t ph2 = *(uint32_t*)&A2, ph3 = *(uint32_t*)&A3;
            const int bo = 8 * kc + tg;
#pragma unroll
            for (int jj = 0; jj < 8; jj++) {
                const int nb = (8 * jj + grp) * AW + bo;
                mma16816(o[jj], ph0, ph1, ph2, ph3, Vh[nb], Vh[nb + 4]);
            }
        }

        bc = (bc == 2) ? 0 : bc + 1;
        bn = (bn == 2) ? 0 : bn + 1;
    }

    // epilogue: fp16 store (out-proj consumes fp16 A directly)
    const float i0 = 1.0f / l0, i1 = 1.0f / l1;
    __half* out0 = out + ((size_t)(b * T_ + row0)) * D_ + h * 64 + 2 * tg;
    __half* out1 = out + ((size_t)(b * T_ + row1)) * D_ + h * 64 + 2 * tg;
#pragma unroll
    for (int jj = 0; jj < 8; jj++) {
        *(__half2*)(out0 + 8 * jj) = __floats2half2_rn(o[jj][0] * i0, o[jj][1] * i0);
        *(__half2*)(out1 + 8 * jj) = __floats2half2_rn(o[jj][2] * i1, o[jj][3] * i1);
    }
}

// ---------------------------------------------------------------------------
extern "C" void kernel_launch(void* const* d_in, const int* in_sizes, int n_in,
                              void* d_out, int out_size)
{
    (void)in_sizes; (void)n_in; (void)out_size;
    const float* x     = (const float*)d_in[0];
    const float* W_qkv = (const float*)d_in[1];
    const float* b_qkv = (const float*)d_in[2];
    const float* W_out = (const float*)d_in[3];
    const float* b_out = (const float*)d_in[4];
    float* out = (float*)d_out;

    float* qkv_ptr;
    __half *xh_ptr, *att_ptr, *wqkvh_ptr, *wouth_ptr;
    cudaGetSymbolAddress((void**)&xh_ptr,    g_x_h);
    cudaGetSymbolAddress((void**)&qkv_ptr,   g_qkv);
    cudaGetSymbolAddress((void**)&att_ptr,   g_att);
    cudaGetSymbolAddress((void**)&wqkvh_ptr, g_wqkv_h);
    cudaGetSymbolAddress((void**)&wouth_ptr, g_wout_h);
    __half *qh, *kh, *vh;
    cudaGetSymbolAddress((void**)&qh, g_q_hi);
    cudaGetSymbolAddress((void**)&kh, g_k_hi);
    cudaGetSymbolAddress((void**)&vh, g_vt_hi);

    cudaFuncSetAttribute(gemm_f16_kernel,
                         cudaFuncAttributeMaxDynamicSharedMemorySize, GEMM_SMEM);
    cudaFuncSetAttribute(flash_mma_kernel,
                         cudaFuncAttributeMaxDynamicSharedMemorySize, ATT_SMEM);

    // 0) Merged prologue: weights transpose->fp16, x->fp16
    prologue_kernel<<<4096 + (M_ * D_ / 4) / 256, 256>>>(
        W_qkv, wqkvh_ptr, W_out, wouth_ptr, (const float4*)x, xh_ptr);

    // 1) QKV projection (fp16 mma, BK=32)
    gemm_f16_kernel<<<dim3(3 * D_ / 128, M_ / 128), 128, GEMM_SMEM>>>(
        xh_ptr, wqkvh_ptr, b_qkv, qkv_ptr, M_, 3 * D_, D_);

    // 2) Merged convert (Q, K, V: fp16)
    convert_kernel<<<8192 + (T_ / 32) * 2 * BH_, 256>>>(
        qkv_ptr, qh, kh, vh);

    // 3) Causal attention (plain fp16 QK + PV)
    flash_mma_kernel<<<dim3(T_ / 128, BH_), 256, ATT_SMEM>>>(
        qh, kh, vh, att_ptr);

    // 4) Output projection (fp16 mma)
    gemm_f16_kernel<<<dim3(D_ / 128, M_ / 128), 128, GEMM_SMEM>>>(
        att_ptr, wouth_ptr, b_out, out, M_, D_, D_);
}